// round 5
// baseline (speedup 1.0000x reference)
#include <cuda_runtime.h>
#include <cuda_bf16.h>
#include <cstdint>
#include <math.h>

#define BB 2
#define CC 128
#define NH 4
#define DH 32
#define NT 4096
#define SCALE_F 10.0f

// ---------------- scratch (static device memory; no allocations) -------------
static __device__ float g_q[BB * CC * NT];            // fp32 q (pre-norm)
static __device__ float g_k[BB * CC * NT];            // fp32 k (pre-norm)
static __device__ __nv_bfloat16 g_qb[BB * CC * NT];   // bf16 normalized*SCALE q
static __device__ __nv_bfloat16 g_kb[BB * CC * NT];   // bf16 normalized k
static __device__ __nv_bfloat16 g_vb[BB * CC * NT];   // bf16 v
static __device__ float g_att[BB * CC * NT];
static __device__ float g_colsum[BB * CC];
static __device__ float g_sumv[BB * CC];

// =============================================================================
// helpers
// =============================================================================
__device__ __forceinline__ uint32_t smem_u32(const void* p) {
    uint32_t a;
    asm("{ .reg .u64 t; cvta.to.shared.u64 t, %1; cvt.u32.u64 %0, t; }"
        : "=r"(a) : "l"(p));
    return a;
}

__device__ __forceinline__ uint32_t packbf(float a, float b) {
    uint32_t r;
    asm("cvt.rn.bf16x2.f32 %0, %2, %1;" : "=r"(r) : "f"(a), "f"(b));
    return r;  // lo = a, hi = b
}

__device__ __forceinline__ void ldsm4(uint32_t& r0, uint32_t& r1, uint32_t& r2,
                                      uint32_t& r3, uint32_t addr) {
    asm volatile("ldmatrix.sync.aligned.m8n8.x4.shared.b16 {%0,%1,%2,%3}, [%4];"
                 : "=r"(r0), "=r"(r1), "=r"(r2), "=r"(r3) : "r"(addr));
}

__device__ __forceinline__ void ldsm4t(uint32_t& r0, uint32_t& r1, uint32_t& r2,
                                       uint32_t& r3, uint32_t addr) {
    asm volatile("ldmatrix.sync.aligned.m8n8.x4.trans.shared.b16 {%0,%1,%2,%3}, [%4];"
                 : "=r"(r0), "=r"(r1), "=r"(r2), "=r"(r3) : "r"(addr));
}

__device__ __forceinline__ void mma16816(float* c, uint32_t a0, uint32_t a1,
                                         uint32_t a2, uint32_t a3,
                                         uint32_t b0, uint32_t b1) {
    asm volatile(
        "mma.sync.aligned.m16n8k16.row.col.f32.bf16.bf16.f32 "
        "{%0,%1,%2,%3}, {%4,%5,%6,%7}, {%8,%9}, {%0,%1,%2,%3};"
        : "+f"(c[0]), "+f"(c[1]), "+f"(c[2]), "+f"(c[3])
        : "r"(a0), "r"(a1), "r"(a2), "r"(a3), "r"(b0), "r"(b1));
}

__device__ __forceinline__ void cp16(uint32_t dst, const void* src) {
    asm volatile("cp.async.cg.shared.global [%0], [%1], 16;"
                 :: "r"(dst), "l"(src) : "memory");
}

// exp(x)-1, |x| < ~0.15 : deg-3 Taylor (x^4/24 < 4e-9, below bf16 rounding)
__device__ __forceinline__ float expm1_poly(float x) {
    float p = fmaf(x, 1.0f / 6.0f, 0.5f);
    p = fmaf(x, p, 1.0f);
    return x * p;
}

// =============================================================================
// Projection GEMM, 128 rows x 64 cols per CTA (unchanged from R4)
// =============================================================================
template <bool BF16OUT>
__device__ __forceinline__ void gemm_tile64(const float* __restrict__ W,
                                            const float* __restrict__ bias,
                                            const float* __restrict__ inb,
                                            void* __restrict__ outb,
                                            int n0, float* WsT, float* Bs)
{
    const int tid = threadIdx.x;
    {
        const int m  = tid & 127;
        const int ch = (tid >> 7) * 64;
#pragma unroll
        for (int cc = 0; cc < 64; cc += 4) {
            float4 w = *(const float4*)(W + m * 128 + ch + cc);
            WsT[(ch + cc + 0) * 128 + m] = w.x;
            WsT[(ch + cc + 1) * 128 + m] = w.y;
            WsT[(ch + cc + 2) * 128 + m] = w.z;
            WsT[(ch + cc + 3) * 128 + m] = w.w;
        }
    }
    {
#pragma unroll
        for (int it = 0; it < 8; ++it) {
            int idx = tid + it * 256;
            int row = idx >> 4;
            int col = idx & 15;
            ((float4*)Bs)[idx] = *(const float4*)(inb + (size_t)row * NT + n0 + col * 4);
        }
    }
    __syncthreads();

    const int ty = tid >> 4, tx = tid & 15;
    float acc[8][4];
#pragma unroll
    for (int i = 0; i < 8; ++i)
#pragma unroll
        for (int j = 0; j < 4; ++j) acc[i][j] = 0.f;

#pragma unroll 8
    for (int c = 0; c < 128; ++c) {
        float4 a0 = *(const float4*)(WsT + c * 128 + ty * 8);
        float4 a1 = *(const float4*)(WsT + c * 128 + ty * 8 + 4);
        float4 b0 = *(const float4*)(Bs + c * 64 + tx * 4);
        float av[8] = {a0.x, a0.y, a0.z, a0.w, a1.x, a1.y, a1.z, a1.w};
        float bv[4] = {b0.x, b0.y, b0.z, b0.w};
#pragma unroll
        for (int i = 0; i < 8; ++i)
#pragma unroll
            for (int j = 0; j < 4; ++j) acc[i][j] += av[i] * bv[j];
    }

#pragma unroll
    for (int i = 0; i < 8; ++i) {
        const int m = ty * 8 + i;
        const float bb = bias[m];
        float r0 = acc[i][0] + bb, r1 = acc[i][1] + bb;
        float r2 = acc[i][2] + bb, r3 = acc[i][3] + bb;
        if (BF16OUT) {
            __nv_bfloat16* dst = (__nv_bfloat16*)outb + (size_t)m * NT + n0 + tx * 4;
            *(uint2*)dst = make_uint2(packbf(r0, r1), packbf(r2, r3));
        } else {
            float* dst = (float*)outb + (size_t)m * NT + n0 + tx * 4;
            *(float4*)dst = make_float4(r0, r1, r2, r3);
        }
    }
}

__global__ void __launch_bounds__(256, 2)
proj_qkv_kernel(const float* __restrict__ x, const float* __restrict__ cx,
                const float* __restrict__ Wq, const float* __restrict__ bq,
                const float* __restrict__ Wk, const float* __restrict__ bk,
                const float* __restrict__ Wv, const float* __restrict__ bv)
{
    extern __shared__ float smp[];
    float* WsT = smp;
    float* Bs  = smp + 128 * 128;
    const int n0 = blockIdx.x * 64;
    const int b  = blockIdx.y;
    const int wh = blockIdx.z;
    const size_t boff = (size_t)b * CC * NT;
    if (wh == 0)
        gemm_tile64<false>(Wq, bq, x + boff, g_q + boff, n0, WsT, Bs);
    else if (wh == 1)
        gemm_tile64<false>(Wk, bk, cx + boff, g_k + boff, n0, WsT, Bs);
    else
        gemm_tile64<true>(Wv, bv, cx + boff, g_vb + boff, n0, WsT, Bs);
}

__global__ void __launch_bounds__(256, 2)
proj_out_kernel(const float* __restrict__ Wo, const float* __restrict__ bo,
                float* __restrict__ out)
{
    extern __shared__ float smp[];
    float* WsT = smp;
    float* Bs  = smp + 128 * 128;
    const int n0 = blockIdx.x * 64;
    const int b  = blockIdx.y;
    const size_t boff = (size_t)b * CC * NT;
    gemm_tile64<false>(Wo, bo, g_att + boff, out + boff, n0, WsT, Bs);
}

// =============================================================================
// L2 normalize q,k rows over the spatial axis; write bf16 (SCALE folded into q)
// =============================================================================
__global__ void __launch_bounds__(256, 1) norm_kernel()
{
    const int row = blockIdx.x;
    const float* p = (blockIdx.y == 0 ? g_q : g_k) + (size_t)row * NT;
    __nv_bfloat16* ob = (blockIdx.y == 0 ? g_qb : g_kb) + (size_t)row * NT;
    const int tid = threadIdx.x;

    float s = 0.f;
#pragma unroll
    for (int it = 0; it < 4; ++it) {
        float4 v = ((const float4*)p)[tid + it * 256];
        s += v.x * v.x + v.y * v.y + v.z * v.z + v.w * v.w;
    }
#pragma unroll
    for (int o = 16; o > 0; o >>= 1) s += __shfl_xor_sync(0xffffffffu, s, o);

    __shared__ float red[8];
    if ((tid & 31) == 0) red[tid >> 5] = s;
    __syncthreads();
    if (tid < 32) {
        float v = (tid < 8) ? red[tid] : 0.f;
#pragma unroll
        for (int o = 4; o > 0; o >>= 1) v += __shfl_xor_sync(0xffffffffu, v, o);
        if (tid == 0) red[0] = v;
    }
    __syncthreads();
    const float tot = red[0];
    const float scl = (blockIdx.y == 0 ? SCALE_F : 1.0f) / fmaxf(sqrtf(tot), 1e-12f);

#pragma unroll
    for (int it = 0; it < 4; ++it) {
        float4 v = ((const float4*)p)[tid + it * 256];
        ((uint2*)ob)[tid + it * 256] =
            make_uint2(packbf(v.x * scl, v.y * scl), packbf(v.z * scl, v.w * scl));
    }
}

// colsum[b][c] = sum_n cond_x[b][c][n]
__global__ void __launch_bounds__(256, 1) colsum_kernel(const float* __restrict__ cx)
{
    const int row = blockIdx.x;
    const float* p = cx + (size_t)row * NT;
    const int tid = threadIdx.x;
    float s = 0.f;
#pragma unroll
    for (int it = 0; it < 4; ++it) {
        float4 v = ((const float4*)p)[tid + it * 256];
        s += v.x + v.y + v.z + v.w;
    }
#pragma unroll
    for (int o = 16; o > 0; o >>= 1) s += __shfl_xor_sync(0xffffffffu, s, o);
    __shared__ float red[8];
    if ((tid & 31) == 0) red[tid >> 5] = s;
    __syncthreads();
    if (tid == 0)
        g_colsum[row] = red[0] + red[1] + red[2] + red[3] +
                        red[4] + red[5] + red[6] + red[7];
}

// g_sumv[b][m] = Wv[m,:] . colsum[b,:] + NT * bv[m]
__global__ void __launch_bounds__(128, 1)
sumv_mat_kernel(const float* __restrict__ Wv, const float* __restrict__ bv)
{
    const int o = blockIdx.x;
    const int b = o >> 7, m = o & 127;
    const int tid = threadIdx.x;
    float s = Wv[m * 128 + tid] * g_colsum[b * 128 + tid];
#pragma unroll
    for (int off = 16; off > 0; off >>= 1) s += __shfl_xor_sync(0xffffffffu, s, off);
    __shared__ float red[4];
    if ((tid & 31) == 0) red[tid >> 5] = s;
    __syncthreads();
    if (tid == 0)
        g_sumv[o] = red[0] + red[1] + red[2] + red[3] + (float)NT * bv[m];
}

// =============================================================================
// mma.sync flash attention, j-split warp layout.
// CTA = 128 queries x (b,h); warp (wi in 0..3, wj in 0..1) owns 32 i-rows
// (two 16-row A groups) x 64 j-cols -> K/V ldsm amortized over 2 row groups.
// Cross-wj O/rowsum reduction once at the end via smem (overlaid on K buffer).
// =============================================================================
#define QS_STRIDE 80    // bytes per Q row (32 bf16 = 64B data + pad)
#define KS_STRIDE 272   // bytes per K/V row (128 bf16 = 256B + 16B pad)

__global__ void __launch_bounds__(256, 2) attn_mma_kernel()
{
    __shared__ __align__(16) unsigned char Qs[128 * QS_STRIDE];    // [i][d]
    __shared__ __align__(16) unsigned char Kb[2][32 * KS_STRIDE];  // [d][j]
    __shared__ __align__(16) unsigned char Vb[2][32 * KS_STRIDE];  // [d][j]

    const int tid  = threadIdx.x;
    const int w    = tid >> 5;
    const int lane = tid & 31;
    const int wi = w & 3;        // i-group: rows [wi*32, wi*32+32)
    const int wj = w >> 2;       // j-half:  cols [wj*64, wj*64+64)
    const int i0 = blockIdx.x * 128;
    const int hh = blockIdx.y;
    const int b  = blockIdx.z;
    const int cb = b * CC + hh * DH;
    const __nv_bfloat16* qg = g_qb + (size_t)cb * NT;
    const __nv_bfloat16* kg = g_kb + (size_t)cb * NT;
    const __nv_bfloat16* vg = g_vb + (size_t)cb * NT;

    const uint32_t uQs = smem_u32(Qs);
    const uint32_t uK0 = smem_u32(Kb[0]), uK1 = smem_u32(Kb[1]);
    const uint32_t uV0 = smem_u32(Vb[0]), uV1 = smem_u32(Vb[1]);

    // ---- stage Q tile [128 i][32 d] bf16 (once) ----
    {
        const int i  = tid & 127;
        const int dh = (tid >> 7) * 16;
#pragma unroll
        for (int v = 0; v < 8; ++v) {
            uint32_t lo = *(const uint16_t*)(qg + (size_t)(dh + 2 * v) * NT + i0 + i);
            uint32_t hi = *(const uint16_t*)(qg + (size_t)(dh + 2 * v + 1) * NT + i0 + i);
            *(uint32_t*)(Qs + i * QS_STRIDE + (dh + 2 * v) * 2) = lo | (hi << 16);
        }
    }

    // ---- prefetch K/V tile 0 ----
    {
#pragma unroll
        for (int r = 0; r < 2; ++r) {
            const int idx = tid + r * 256;
            const int d = idx >> 4, ch = idx & 15;
            cp16(uK0 + d * KS_STRIDE + ch * 16, kg + (size_t)d * NT + ch * 8);
            cp16(uV0 + d * KS_STRIDE + ch * 16, vg + (size_t)d * NT + ch * 8);
        }
        asm volatile("cp.async.commit_group;" ::: "memory");
    }
    __syncthreads();   // Q visible

    // ---- Q A-fragments: 2 row-groups x 2 ksteps over d ----
    uint32_t qa[2][2][4];
    {
        const int q = lane >> 3, r = lane & 7;
#pragma unroll
        for (int rg = 0; rg < 2; ++rg)
#pragma unroll
            for (int ks = 0; ks < 2; ++ks) {
                uint32_t addr = uQs + (wi * 32 + rg * 16 + (q & 1) * 8 + r) * QS_STRIDE
                                    + (ks * 16 + (q >> 1) * 8) * 2;
                ldsm4(qa[rg][ks][0], qa[rg][ks][1], qa[rg][ks][2], qa[rg][ks][3], addr);
            }
    }

    float oc[2][4][4];
#pragma unroll
    for (int rg = 0; rg < 2; ++rg)
#pragma unroll
        for (int dn = 0; dn < 4; ++dn)
#pragma unroll
            for (int u = 0; u < 4; ++u) oc[rg][dn][u] = 0.f;
    float dlo[2] = {0.f, 0.f}, dhi[2] = {0.f, 0.f};

    const int lq = lane >> 3, lr = lane & 7;

    for (int t = 0; t < 32; ++t) {
        asm volatile("cp.async.wait_group 0;" ::: "memory");
        __syncthreads();   // tile t resident; buffer t-2 free to refill

        if (t < 31) {
            const uint32_t uKn = ((t + 1) & 1) ? uK1 : uK0;
            const uint32_t uVn = ((t + 1) & 1) ? uV1 : uV0;
            const int j0n = (t + 1) * 128;
#pragma unroll
            for (int r = 0; r < 2; ++r) {
                const int idx = tid + r * 256;
                const int d = idx >> 4, ch = idx & 15;
                cp16(uKn + d * KS_STRIDE + ch * 16, kg + (size_t)d * NT + j0n + ch * 8);
                cp16(uVn + d * KS_STRIDE + ch * 16, vg + (size_t)d * NT + j0n + ch * 8);
            }
            asm volatile("cp.async.commit_group;" ::: "memory");
        }

        const uint32_t uKs = (t & 1) ? uK1 : uK0;
        const uint32_t uVs = (t & 1) ? uV1 : uV0;
        const uint32_t kAddrBase = uKs + lane * KS_STRIDE + wj * 128;  // j offset 64*2B

        // ---- S + expm1 + pack: 4 nt-pairs (each = 16 local j) ----
        uint32_t plA[2][8], phA[2][8];
#pragma unroll
        for (int ntp = 0; ntp < 4; ++ntp) {
            const int ntA = 2 * ntp, ntB = 2 * ntp + 1;
            float scA[2][4], scB[2][4];
            uint32_t b0, b1, b2, b3;
            ldsm4t(b0, b1, b2, b3, kAddrBase + ntA * 16);
#pragma unroll
            for (int rg = 0; rg < 2; ++rg) {
                scA[rg][0] = scA[rg][1] = scA[rg][2] = scA[rg][3] = 0.f;
                mma16816(scA[rg], qa[rg][0][0], qa[rg][0][1], qa[rg][0][2], qa[rg][0][3], b0, b1);
                mma16816(scA[rg], qa[rg][1][0], qa[rg][1][1], qa[rg][1][2], qa[rg][1][3], b2, b3);
            }
            ldsm4t(b0, b1, b2, b3, kAddrBase + ntB * 16);
#pragma unroll
            for (int rg = 0; rg < 2; ++rg) {
                scB[rg][0] = scB[rg][1] = scB[rg][2] = scB[rg][3] = 0.f;
                mma16816(scB[rg], qa[rg][0][0], qa[rg][0][1], qa[rg][0][2], qa[rg][0][3], b0, b1);
                mma16816(scB[rg], qa[rg][1][0], qa[rg][1][1], qa[rg][1][2], qa[rg][1][3], b2, b3);
            }
#pragma unroll
            for (int rg = 0; rg < 2; ++rg) {
                float a0 = expm1_poly(scA[rg][0]), a1 = expm1_poly(scA[rg][1]);
                float a2 = expm1_poly(scA[rg][2]), a3 = expm1_poly(scA[rg][3]);
                float e0 = expm1_poly(scB[rg][0]), e1 = expm1_poly(scB[rg][1]);
                float e2 = expm1_poly(scB[rg][2]), e3 = expm1_poly(scB[rg][3]);
                dlo[rg] += (a0 + a1) + (e0 + e1);
                dhi[rg] += (a2 + a3) + (e2 + e3);
                plA[rg][ntA] = packbf(a0, a1);
                phA[rg][ntA] = packbf(a2, a3);
                plA[rg][ntB] = packbf(e0, e1);
                phA[rg][ntB] = packbf(e2, e3);
            }
        }

        // ---- O += dev @ V : 2 local kstep-pairs x 4 d-tiles x 2 row groups ----
#pragma unroll
        for (int u = 0; u < 2; ++u) {
            const int ug = wj * 2 + u;   // global 32-j block
#pragma unroll
            for (int dn = 0; dn < 4; ++dn) {
                uint32_t b0, b1, b2, b3;
                ldsm4(b0, b1, b2, b3,
                      uVs + (dn * 8 + lr) * KS_STRIDE + (4 * ug + lq) * 16);
#pragma unroll
                for (int rg = 0; rg < 2; ++rg) {
                    mma16816(oc[rg][dn], plA[rg][4 * u],     phA[rg][4 * u],
                                          plA[rg][4 * u + 1], phA[rg][4 * u + 1], b0, b1);
                    mma16816(oc[rg][dn], plA[rg][4 * u + 2], phA[rg][4 * u + 2],
                                          plA[rg][4 * u + 3], phA[rg][4 * u + 3], b2, b3);
                }
            }
        }
    }

    // ---- cross-wj reduction + epilogue ----
    __syncthreads();   // K/V buffers dead; safe to overlay
    float* RedO = (float*)Kb;   // [128][33]
    float* RedD = (float*)Vb;   // [128]

#pragma unroll
    for (int rg = 0; rg < 2; ++rg) {
        dlo[rg] += __shfl_xor_sync(0xffffffffu, dlo[rg], 1);
        dlo[rg] += __shfl_xor_sync(0xffffffffu, dlo[rg], 2);
        dhi[rg] += __shfl_xor_sync(0xffffffffu, dhi[rg], 1);
        dhi[rg] += __shfl_xor_sync(0xffffffffu, dhi[rg], 2);
    }

    const int tq = lane & 3, g = lane >> 2;

    if (wj == 0) {
#pragma unroll
        for (int rg = 0; rg < 2; ++rg) {
            const int r0 = wi * 32 + rg * 16 + g;
            const int r1 = r0 + 8;
#pragma unroll
            for (int dn = 0; dn < 4; ++dn) {
                const int c0 = dn * 8 + 2 * tq;
                RedO[r0 * 33 + c0]     = oc[rg][dn][0];
                RedO[r0 * 33 + c0 + 1] = oc[rg][dn][1];
                RedO[r1 * 33 + c0]     = oc[rg][dn][2];
                RedO[r1 * 33 + c0 + 1] = oc[rg][dn][3];
            }
            if (tq == 0) { RedD[r0] = dlo[rg]; RedD[r1] = dhi[rg]; }
        }
    }
    __syncthreads();
    if (wj == 1) {
        float* att = g_att + (size_t)cb * NT;
        const float* sv = g_sumv + cb;
#pragma unroll
        for (int rg = 0; rg < 2; ++rg) {
            const int r0 = wi * 32 + rg * 16 + g;
            const int r1 = r0 + 8;
            const float inv_lo = 1.0f / (4096.0f + dlo[rg] + RedD[r0]);
            const float inv_hi = 1.0f / (4096.0f + dhi[rg] + RedD[r1]);
#pragma unroll
            for (int dn = 0; dn < 4; ++dn) {
                const int c0 = dn * 8 + 2 * tq;
                const float s0 = sv[c0], s1 = sv[c0 + 1];
                att[(size_t)c0 * NT + i0 + r0] =
                    (oc[rg][dn][0] + RedO[r0 * 33 + c0] + s0) * inv_lo;
                att[(size_t)(c0 + 1) * NT + i0 + r0] =
                    (oc[rg][dn][1] + RedO[r0 * 33 + c0 + 1] + s1) * inv_lo;
                att[(size_t)c0 * NT + i0 + r1] =
                    (oc[rg][dn][2] + RedO[r1 * 33 + c0] + s0) * inv_hi;
                att[(size_t)(c0 + 1) * NT + i0 + r1] =
                    (oc[rg][dn][3] + RedO[r1 * 33 + c0 + 1] + s1) * inv_hi;
            }
        }
    }
}

// =============================================================================
// Launch
// =============================================================================
extern "C" void kernel_launch(void* const* d_in, const int* in_sizes, int n_in,
                              void* d_out, int out_size)
{
    (void)in_sizes; (void)n_in; (void)out_size;
    const float* x  = (const float*)d_in[0];
    const float* cx = (const float*)d_in[1];
    const float* Wq = (const float*)d_in[2];
    const float* bq = (const float*)d_in[3];
    const float* Wk = (const float*)d_in[4];
    const float* bk = (const float*)d_in[5];
    const float* Wv = (const float*)d_in[6];
    const float* bv = (const float*)d_in[7];
    const float* Wo = (const float*)d_in[8];
    const float* bo = (const float*)d_in[9];
    float* out = (float*)d_out;

    const int PROJ_SMEM = (128 * 128 + 128 * 64) * (int)sizeof(float);  // 96 KB

    cudaFuncSetAttribute(proj_qkv_kernel, cudaFuncAttributeMaxDynamicSharedMemorySize, PROJ_SMEM);
    cudaFuncSetAttribute(proj_out_kernel, cudaFuncAttributeMaxDynamicSharedMemorySize, PROJ_SMEM);

    proj_qkv_kernel<<<dim3(NT / 64, BB, 3), 256, PROJ_SMEM>>>(x, cx, Wq, bq, Wk, bk, Wv, bv);
    colsum_kernel<<<dim3(BB * CC), 256>>>(cx);
    sumv_mat_kernel<<<dim3(BB * CC), 128>>>(Wv, bv);
    norm_kernel<<<dim3(BB * CC, 2), 256>>>();
    attn_mma_kernel<<<dim3(NT / 128, NH, BB), 256>>>();
    proj_out_kernel<<<dim3(NT / 64, BB), 256, PROJ_SMEM>>>(Wo, bo, out);
}

// round 7
// speedup vs baseline: 1.0122x; 1.0122x over previous
#include <cuda_runtime.h>
#include <cuda_bf16.h>
#include <cstdint>
#include <math.h>

#define BB 2
#define CC 128
#define NH 4
#define DH 32
#define NT 4096
#define SCALE_F 10.0f

// ---------------- scratch (static device memory; no allocations) -------------
static __device__ float g_q[BB * CC * NT];            // fp32 q (pre-norm)
static __device__ float g_k[BB * CC * NT];            // fp32 k (pre-norm)
static __device__ __nv_bfloat16 g_qb[BB * CC * NT];   // bf16 normalized*SCALE q
static __device__ __nv_bfloat16 g_kb[BB * CC * NT];   // bf16 normalized k
static __device__ __nv_bfloat16 g_vb[BB * CC * NT];   // bf16 v
static __device__ float g_att[BB * CC * NT];
static __device__ float g_colsum[BB * CC];
static __device__ float g_sumv[BB * CC];

// =============================================================================
// helpers
// =============================================================================
__device__ __forceinline__ uint32_t smem_u32(const void* p) {
    uint32_t a;
    asm("{ .reg .u64 t; cvta.to.shared.u64 t, %1; cvt.u32.u64 %0, t; }"
        : "=r"(a) : "l"(p));
    return a;
}

__device__ __forceinline__ uint32_t packbf(float a, float b) {
    uint32_t r;
    asm("cvt.rn.bf16x2.f32 %0, %2, %1;" : "=r"(r) : "f"(a), "f"(b));
    return r;  // lo = a, hi = b
}

__device__ __forceinline__ void ldsm4(uint32_t& r0, uint32_t& r1, uint32_t& r2,
                                      uint32_t& r3, uint32_t addr) {
    asm volatile("ldmatrix.sync.aligned.m8n8.x4.shared.b16 {%0,%1,%2,%3}, [%4];"
                 : "=r"(r0), "=r"(r1), "=r"(r2), "=r"(r3) : "r"(addr));
}

__device__ __forceinline__ void ldsm4t(uint32_t& r0, uint32_t& r1, uint32_t& r2,
                                       uint32_t& r3, uint32_t addr) {
    asm volatile("ldmatrix.sync.aligned.m8n8.x4.trans.shared.b16 {%0,%1,%2,%3}, [%4];"
                 : "=r"(r0), "=r"(r1), "=r"(r2), "=r"(r3) : "r"(addr));
}

__device__ __forceinline__ void mma16816(float* c, uint32_t a0, uint32_t a1,
                                         uint32_t a2, uint32_t a3,
                                         uint32_t b0, uint32_t b1) {
    asm volatile(
        "mma.sync.aligned.m16n8k16.row.col.f32.bf16.bf16.f32 "
        "{%0,%1,%2,%3}, {%4,%5,%6,%7}, {%8,%9}, {%0,%1,%2,%3};"
        : "+f"(c[0]), "+f"(c[1]), "+f"(c[2]), "+f"(c[3])
        : "r"(a0), "r"(a1), "r"(a2), "r"(a3), "r"(b0), "r"(b1));
}

__device__ __forceinline__ void cp16(uint32_t dst, const void* src) {
    asm volatile("cp.async.cg.shared.global [%0], [%1], 16;"
                 :: "r"(dst), "l"(src) : "memory");
}

// exp(x)-1, |x| < ~0.15 : deg-3 Taylor (x^4/24 < 4e-9, below bf16 rounding)
__device__ __forceinline__ float expm1_poly(float x) {
    float p = fmaf(x, 1.0f / 6.0f, 0.5f);
    p = fmaf(x, p, 1.0f);
    return x * p;
}

// =============================================================================
// Projection GEMM, 128 rows x 64 cols per CTA
// =============================================================================
template <bool BF16OUT>
__device__ __forceinline__ void gemm_tile64(const float* __restrict__ W,
                                            const float* __restrict__ bias,
                                            const float* __restrict__ inb,
                                            void* __restrict__ outb,
                                            int n0, float* WsT, float* Bs)
{
    const int tid = threadIdx.x;
    {
        const int m  = tid & 127;
        const int ch = (tid >> 7) * 64;
#pragma unroll
        for (int cc = 0; cc < 64; cc += 4) {
            float4 w = *(const float4*)(W + m * 128 + ch + cc);
            WsT[(ch + cc + 0) * 128 + m] = w.x;
            WsT[(ch + cc + 1) * 128 + m] = w.y;
            WsT[(ch + cc + 2) * 128 + m] = w.z;
            WsT[(ch + cc + 3) * 128 + m] = w.w;
        }
    }
    {
#pragma unroll
        for (int it = 0; it < 8; ++it) {
            int idx = tid + it * 256;
            int row = idx >> 4;
            int col = idx & 15;
            ((float4*)Bs)[idx] = *(const float4*)(inb + (size_t)row * NT + n0 + col * 4);
        }
    }
    __syncthreads();

    const int ty = tid >> 4, tx = tid & 15;
    float acc[8][4];
#pragma unroll
    for (int i = 0; i < 8; ++i)
#pragma unroll
        for (int j = 0; j < 4; ++j) acc[i][j] = 0.f;

#pragma unroll 8
    for (int c = 0; c < 128; ++c) {
        float4 a0 = *(const float4*)(WsT + c * 128 + ty * 8);
        float4 a1 = *(const float4*)(WsT + c * 128 + ty * 8 + 4);
        float4 b0 = *(const float4*)(Bs + c * 64 + tx * 4);
        float av[8] = {a0.x, a0.y, a0.z, a0.w, a1.x, a1.y, a1.z, a1.w};
        float bv[4] = {b0.x, b0.y, b0.z, b0.w};
#pragma unroll
        for (int i = 0; i < 8; ++i)
#pragma unroll
            for (int j = 0; j < 4; ++j) acc[i][j] += av[i] * bv[j];
    }

#pragma unroll
    for (int i = 0; i < 8; ++i) {
        const int m = ty * 8 + i;
        const float bb = bias[m];
        float r0 = acc[i][0] + bb, r1 = acc[i][1] + bb;
        float r2 = acc[i][2] + bb, r3 = acc[i][3] + bb;
        if (BF16OUT) {
            __nv_bfloat16* dst = (__nv_bfloat16*)outb + (size_t)m * NT + n0 + tx * 4;
            *(uint2*)dst = make_uint2(packbf(r0, r1), packbf(r2, r3));
        } else {
            float* dst = (float*)outb + (size_t)m * NT + n0 + tx * 4;
            *(float4*)dst = make_float4(r0, r1, r2, r3);
        }
    }
}

__global__ void __launch_bounds__(256, 2)
proj_qkv_kernel(const float* __restrict__ x, const float* __restrict__ cx,
                const float* __restrict__ Wq, const float* __restrict__ bq,
                const float* __restrict__ Wk, const float* __restrict__ bk,
                const float* __restrict__ Wv, const float* __restrict__ bv)
{
    extern __shared__ float smp[];
    float* WsT = smp;
    float* Bs  = smp + 128 * 128;
    const int n0 = blockIdx.x * 64;
    const int b  = blockIdx.y;
    const int wh = blockIdx.z;
    const size_t boff = (size_t)b * CC * NT;
    if (wh == 0)
        gemm_tile64<false>(Wq, bq, x + boff, g_q + boff, n0, WsT, Bs);
    else if (wh == 1)
        gemm_tile64<false>(Wk, bk, cx + boff, g_k + boff, n0, WsT, Bs);
    else
        gemm_tile64<true>(Wv, bv, cx + boff, g_vb + boff, n0, WsT, Bs);
}

__global__ void __launch_bounds__(256, 2)
proj_out_kernel(const float* __restrict__ Wo, const float* __restrict__ bo,
                float* __restrict__ out)
{
    extern __shared__ float smp[];
    float* WsT = smp;
    float* Bs  = smp + 128 * 128;
    const int n0 = blockIdx.x * 64;
    const int b  = blockIdx.y;
    const size_t boff = (size_t)b * CC * NT;
    gemm_tile64<false>(Wo, bo, g_att + boff, out + boff, n0, WsT, Bs);
}

// =============================================================================
// L2 normalize q,k rows over the spatial axis; write bf16 (SCALE folded into q)
// =============================================================================
__global__ void __launch_bounds__(256, 1) norm_kernel()
{
    const int row = blockIdx.x;
    const float* p = (blockIdx.y == 0 ? g_q : g_k) + (size_t)row * NT;
    __nv_bfloat16* ob = (blockIdx.y == 0 ? g_qb : g_kb) + (size_t)row * NT;
    const int tid = threadIdx.x;

    float s = 0.f;
#pragma unroll
    for (int it = 0; it < 4; ++it) {
        float4 v = ((const float4*)p)[tid + it * 256];
        s += v.x * v.x + v.y * v.y + v.z * v.z + v.w * v.w;
    }
#pragma unroll
    for (int o = 16; o > 0; o >>= 1) s += __shfl_xor_sync(0xffffffffu, s, o);

    __shared__ float red[8];
    if ((tid & 31) == 0) red[tid >> 5] = s;
    __syncthreads();
    if (tid < 32) {
        float v = (tid < 8) ? red[tid] : 0.f;
#pragma unroll
        for (int o = 4; o > 0; o >>= 1) v += __shfl_xor_sync(0xffffffffu, v, o);
        if (tid == 0) red[0] = v;
    }
    __syncthreads();
    const float tot = red[0];
    const float scl = (blockIdx.y == 0 ? SCALE_F : 1.0f) / fmaxf(sqrtf(tot), 1e-12f);

#pragma unroll
    for (int it = 0; it < 4; ++it) {
        float4 v = ((const float4*)p)[tid + it * 256];
        ((uint2*)ob)[tid + it * 256] =
            make_uint2(packbf(v.x * scl, v.y * scl), packbf(v.z * scl, v.w * scl));
    }
}

// colsum[b][c] = sum_n cond_x[b][c][n]
__global__ void __launch_bounds__(256, 1) colsum_kernel(const float* __restrict__ cx)
{
    const int row = blockIdx.x;
    const float* p = cx + (size_t)row * NT;
    const int tid = threadIdx.x;
    float s = 0.f;
#pragma unroll
    for (int it = 0; it < 4; ++it) {
        float4 v = ((const float4*)p)[tid + it * 256];
        s += v.x + v.y + v.z + v.w;
    }
#pragma unroll
    for (int o = 16; o > 0; o >>= 1) s += __shfl_xor_sync(0xffffffffu, s, o);
    __shared__ float red[8];
    if ((tid & 31) == 0) red[tid >> 5] = s;
    __syncthreads();
    if (tid == 0)
        g_colsum[row] = red[0] + red[1] + red[2] + red[3] +
                        red[4] + red[5] + red[6] + red[7];
}

// g_sumv[b][m] = Wv[m,:] . colsum[b,:] + NT * bv[m]
__global__ void __launch_bounds__(128, 1)
sumv_mat_kernel(const float* __restrict__ Wv, const float* __restrict__ bv)
{
    const int o = blockIdx.x;
    const int b = o >> 7, m = o & 127;
    const int tid = threadIdx.x;
    float s = Wv[m * 128 + tid] * g_colsum[b * 128 + tid];
#pragma unroll
    for (int off = 16; off > 0; off >>= 1) s += __shfl_xor_sync(0xffffffffu, s, off);
    __shared__ float red[4];
    if ((tid & 31) == 0) red[tid >> 5] = s;
    __syncthreads();
    if (tid == 0)
        g_sumv[o] = red[0] + red[1] + red[2] + red[3] + (float)NT * bv[m];
}

// =============================================================================
// mma.sync flash attention (R4 layout, interleaved chunks).
// CTA = 128 queries x (b,h); 8 warps x 16 i-rows. Each 128-j tile is processed
// as 4 independent 32-j chunks: ldsmK -> S-mma -> expm1/pack -> ldsmV -> PV-mma,
// so tensor-pipe work of chunk u+1 overlaps fma-pipe work of chunk u.
// =============================================================================
#define QS_STRIDE 80    // bytes per Q row (32 bf16 = 64B data + pad)
#define KS_STRIDE 272   // bytes per K/V row (128 bf16 = 256B + 16B pad)

__global__ void __launch_bounds__(256, 2) attn_mma_kernel()
{
    __shared__ __align__(16) unsigned char Qs[128 * QS_STRIDE];    // [i][d]
    __shared__ __align__(16) unsigned char Kb[2][32 * KS_STRIDE];  // [d][j]
    __shared__ __align__(16) unsigned char Vb[2][32 * KS_STRIDE];  // [d][j]

    const int tid  = threadIdx.x;
    const int w    = tid >> 5;
    const int lane = tid & 31;
    const int i0 = blockIdx.x * 128;
    const int hh = blockIdx.y;
    const int b  = blockIdx.z;
    const int cb = b * CC + hh * DH;
    const __nv_bfloat16* qg = g_qb + (size_t)cb * NT;
    const __nv_bfloat16* kg = g_kb + (size_t)cb * NT;
    const __nv_bfloat16* vg = g_vb + (size_t)cb * NT;

    const uint32_t uQs = smem_u32(Qs);
    const uint32_t uK0 = smem_u32(Kb[0]), uK1 = smem_u32(Kb[1]);
    const uint32_t uV0 = smem_u32(Vb[0]), uV1 = smem_u32(Vb[1]);

    // ---- stage Q tile [128 i][32 d] bf16 (once) ----
    {
        const int i  = tid & 127;
        const int dh = (tid >> 7) * 16;
#pragma unroll
        for (int v = 0; v < 8; ++v) {
            uint32_t lo = *(const uint16_t*)(qg + (size_t)(dh + 2 * v) * NT + i0 + i);
            uint32_t hi = *(const uint16_t*)(qg + (size_t)(dh + 2 * v + 1) * NT + i0 + i);
            *(uint32_t*)(Qs + i * QS_STRIDE + (dh + 2 * v) * 2) = lo | (hi << 16);
        }
    }

    // ---- prefetch K/V tile 0 ----
    {
#pragma unroll
        for (int r = 0; r < 2; ++r) {
            const int idx = tid + r * 256;
            const int d = idx >> 4, ch = idx & 15;
            cp16(uK0 + d * KS_STRIDE + ch * 16, kg + (size_t)d * NT + ch * 8);
            cp16(uV0 + d * KS_STRIDE + ch * 16, vg + (size_t)d * NT + ch * 8);
        }
        asm volatile("cp.async.commit_group;" ::: "memory");
    }
    __syncthreads();   // Q visible

    // ---- Q A-fragments (2 ksteps over d) ----
    uint32_t qa[2][4];
    {
        const int q = lane >> 3, r = lane & 7;
#pragma unroll
        for (int ks = 0; ks < 2; ++ks) {
            uint32_t addr = uQs + (w * 16 + (q & 1) * 8 + r) * QS_STRIDE
                                + (ks * 16 + (q >> 1) * 8) * 2;
            ldsm4(qa[ks][0], qa[ks][1], qa[ks][2], qa[ks][3], addr);
        }
    }

    float oc[4][4];
#pragma unroll
    for (int dn = 0; dn < 4; ++dn)
#pragma unroll
        for (int u = 0; u < 4; ++u) oc[dn][u] = 0.f;
    float dev_lo = 0.f, dev_hi = 0.f;

    const int lq = lane >> 3, lr = lane & 7;

    for (int t = 0; t < 32; ++t) {
        asm volatile("cp.async.wait_group 0;" ::: "memory");
        __syncthreads();   // tile t resident; buffer t-2 consumed by all warps

        if (t < 31) {      // prefetch t+1 into the other buffer
            const uint32_t uKn = ((t + 1) & 1) ? uK1 : uK0;
            const uint32_t uVn = ((t + 1) & 1) ? uV1 : uV0;
            const int j0n = (t + 1) * 128;
#pragma unroll
            for (int r = 0; r < 2; ++r) {
                const int idx = tid + r * 256;
                const int d = idx >> 4, ch = idx & 15;
                cp16(uKn + d * KS_STRIDE + ch * 16, kg + (size_t)d * NT + j0n + ch * 8);
                cp16(uVn + d * KS_STRIDE + ch * 16, vg + (size_t)d * NT + j0n + ch * 8);
            }
            asm volatile("cp.async.commit_group;" ::: "memory");
        }

        const uint32_t uKs = (t & 1) ? uK1 : uK0;
        const uint32_t uVs = (t & 1) ? uV1 : uV0;
        const uint32_t kAddrBase = uKs + lane * KS_STRIDE;

        // ---- 4 independent 32-j chunks ----
#pragma unroll
        for (int u = 0; u < 4; ++u) {
            // S = Q K^T for nt = 4u .. 4u+3
            float sc[4][4];
            uint32_t pl[4], ph[4];
#pragma unroll
            for (int q2 = 0; q2 < 4; ++q2) {
                uint32_t b0, b1, b2, b3;
                ldsm4t(b0, b1, b2, b3, kAddrBase + (4 * u + q2) * 16);
                sc[q2][0] = sc[q2][1] = sc[q2][2] = sc[q2][3] = 0.f;
                mma16816(sc[q2], qa[0][0], qa[0][1], qa[0][2], qa[0][3], b0, b1);
                mma16816(sc[q2], qa[1][0], qa[1][1], qa[1][2], qa[1][3], b2, b3);
            }
            // dev = expm1(S); pack; accumulate row sums
#pragma unroll
            for (int q2 = 0; q2 < 4; ++q2) {
                float d0 = expm1_poly(sc[q2][0]);
                float d1 = expm1_poly(sc[q2][1]);
                float d2 = expm1_poly(sc[q2][2]);
                float d3 = expm1_poly(sc[q2][3]);
                dev_lo += d0 + d1;
                dev_hi += d2 + d3;
                pl[q2] = packbf(d0, d1);
                ph[q2] = packbf(d2, d3);
            }
            // O += dev @ V for this 32-j chunk (2 ksteps)
#pragma unroll
            for (int dn = 0; dn < 4; ++dn) {
                uint32_t b0, b1, b2, b3;
                ldsm4(b0, b1, b2, b3,
                      uVs + (dn * 8 + lr) * KS_STRIDE + (4 * u + lq) * 16);
                mma16816(oc[dn], pl[0], ph[0], pl[1], ph[1], b0, b1);
                mma16816(oc[dn], pl[2], ph[2], pl[3], ph[3], b2, b3);
            }
        }
    }

    // ---- epilogue: quad-reduce row sums, rank-1 + denominator ----
    dev_lo += __shfl_xor_sync(0xffffffffu, dev_lo, 1);
    dev_lo += __shfl_xor_sync(0xffffffffu, dev_lo, 2);
    dev_hi += __shfl_xor_sync(0xffffffffu, dev_hi, 1);
    dev_hi += __shfl_xor_sync(0xffffffffu, dev_hi, 2);

    const int tq = lane & 3, g = lane >> 2;
    const int i_lo = i0 + w * 16 + g;
    const int i_hi = i_lo + 8;
    const float inv_lo = 1.0f / (4096.0f + dev_lo);
    const float inv_hi = 1.0f / (4096.0f + dev_hi);
    float* att = g_att + (size_t)cb * NT;
    const float* sv = g_sumv + cb;

#pragma unroll
    for (int dn = 0; dn < 4; ++dn) {
        const int d0 = dn * 8 + 2 * tq;
        const float s0 = sv[d0], s1 = sv[d0 + 1];
        att[(size_t)d0 * NT + i_lo]       = (oc[dn][0] + s0) * inv_lo;
        att[(size_t)(d0 + 1) * NT + i_lo] = (oc[dn][1] + s1) * inv_lo;
        att[(size_t)d0 * NT + i_hi]       = (oc[dn][2] + s0) * inv_hi;
        att[(size_t)(d0 + 1) * NT + i_hi] = (oc[dn][3] + s1) * inv_hi;
    }
}

// =============================================================================
// Launch
// =============================================================================
extern "C" void kernel_launch(void* const* d_in, const int* in_sizes, int n_in,
                              void* d_out, int out_size)
{
    (void)in_sizes; (void)n_in; (void)out_size;
    const float* x  = (const float*)d_in[0];
    const float* cx = (const float*)d_in[1];
    const float* Wq = (const float*)d_in[2];
    const float* bq = (const float*)d_in[3];
    const float* Wk = (const float*)d_in[4];
    const float* bk = (const float*)d_in[5];
    const float* Wv = (const float*)d_in[6];
    const float* bv = (const float*)d_in[7];
    const float* Wo = (const float*)d_in[8];
    const float* bo = (const float*)d_in[9];
    float* out = (float*)d_out;

    const int PROJ_SMEM = (128 * 128 + 128 * 64) * (int)sizeof(float);  // 96 KB

    cudaFuncSetAttribute(proj_qkv_kernel, cudaFuncAttributeMaxDynamicSharedMemorySize, PROJ_SMEM);
    cudaFuncSetAttribute(proj_out_kernel, cudaFuncAttributeMaxDynamicSharedMemorySize, PROJ_SMEM);

    proj_qkv_kernel<<<dim3(NT / 64, BB, 3), 256, PROJ_SMEM>>>(x, cx, Wq, bq, Wk, bk, Wv, bv);
    colsum_kernel<<<dim3(BB * CC), 256>>>(cx);
    sumv_mat_kernel<<<dim3(BB * CC), 128>>>(Wv, bv);
    norm_kernel<<<dim3(BB * CC, 2), 256>>>();
    attn_mma_kernel<<<dim3(NT / 128, NH, BB), 256>>>();
    proj_out_kernel<<<dim3(NT / 64, BB), 256, PROJ_SMEM>>>(Wo, bo, out);
}

// round 8
// speedup vs baseline: 1.2437x; 1.2288x over previous
#include <cuda_runtime.h>
#include <cuda_bf16.h>
#include <cstdint>
#include <math.h>

#define BB 2
#define CC 128
#define NH 4
#define DH 32
#define NT 4096
#define SCALE_F 10.0f

// ---------------- scratch (static device memory; no allocations) -------------
static __device__ float g_q[BB * CC * NT];            // fp32 q (pre-norm)
static __device__ float g_k[BB * CC * NT];            // fp32 k (pre-norm)
static __device__ __nv_bfloat16 g_qb[BB * CC * NT];   // bf16 normalized*SCALE q
static __device__ __nv_bfloat16 g_kb[BB * CC * NT];   // bf16 normalized k
static __device__ __nv_bfloat16 g_vb[BB * CC * NT];   // bf16 v
static __device__ float g_att[BB * CC * NT];
static __device__ float g_colsum[BB * CC];

// =============================================================================
// helpers
// =============================================================================
__device__ __forceinline__ uint32_t smem_u32(const void* p) {
    uint32_t a;
    asm("{ .reg .u64 t; cvta.to.shared.u64 t, %1; cvt.u32.u64 %0, t; }"
        : "=r"(a) : "l"(p));
    return a;
}

__device__ __forceinline__ uint32_t packbf(float a, float b) {
    uint32_t r;
    asm("cvt.rn.bf16x2.f32 %0, %2, %1;" : "=r"(r) : "f"(a), "f"(b));
    return r;  // lo = a, hi = b
}

__device__ __forceinline__ void ldsm4(uint32_t& r0, uint32_t& r1, uint32_t& r2,
                                      uint32_t& r3, uint32_t addr) {
    asm volatile("ldmatrix.sync.aligned.m8n8.x4.shared.b16 {%0,%1,%2,%3}, [%4];"
                 : "=r"(r0), "=r"(r1), "=r"(r2), "=r"(r3) : "r"(addr));
}

__device__ __forceinline__ void ldsm4t(uint32_t& r0, uint32_t& r1, uint32_t& r2,
                                       uint32_t& r3, uint32_t addr) {
    asm volatile("ldmatrix.sync.aligned.m8n8.x4.trans.shared.b16 {%0,%1,%2,%3}, [%4];"
                 : "=r"(r0), "=r"(r1), "=r"(r2), "=r"(r3) : "r"(addr));
}

__device__ __forceinline__ void mma16816(float* c, uint32_t a0, uint32_t a1,
                                         uint32_t a2, uint32_t a3,
                                         uint32_t b0, uint32_t b1) {
    asm volatile(
        "mma.sync.aligned.m16n8k16.row.col.f32.bf16.bf16.f32 "
        "{%0,%1,%2,%3}, {%4,%5,%6,%7}, {%8,%9}, {%0,%1,%2,%3};"
        : "+f"(c[0]), "+f"(c[1]), "+f"(c[2]), "+f"(c[3])
        : "r"(a0), "r"(a1), "r"(a2), "r"(a3), "r"(b0), "r"(b1));
}

__device__ __forceinline__ void cp16(uint32_t dst, const void* src) {
    asm volatile("cp.async.cg.shared.global [%0], [%1], 16;"
                 :: "r"(dst), "l"(src) : "memory");
}

// exp(x)-1, |x| < ~0.15 : deg-3 Taylor (x^4/24 < 4e-9, below bf16 rounding)
__device__ __forceinline__ float expm1_poly(float x) {
    float p = fmaf(x, 1.0f / 6.0f, 0.5f);
    p = fmaf(x, p, 1.0f);
    return x * p;
}

// =============================================================================
// Tensor-core projection GEMMs (hi/lo bf16 split of fp32 operands).
// out[m,n] = sum_c W[m,c] * in[c,n] + bias[m].
//   A = W   [m][c] row-major bf16, ldsm4  (same mapping as attn Q)
//   B = in  [c][n] row-major bf16, ldsm4t (same mapping as attn K)
// =============================================================================
#define PW_STRIDE 272    // 128 bf16 cols = 256B + 16B pad (conflict-free)
#define PB64_STRIDE 144  // 64 bf16 cols = 128B + 16B pad

// qkv: 2-pass Whi @ (in_hi + in_lo). CTA = 128 m x 128 n.
__global__ void __launch_bounds__(256, 2)
proj_qkv_mma(const float* __restrict__ x, const float* __restrict__ cx,
             const float* __restrict__ Wq, const float* __restrict__ bq,
             const float* __restrict__ Wk, const float* __restrict__ bk,
             const float* __restrict__ Wv, const float* __restrict__ bv)
{
    extern __shared__ unsigned char psm[];
    unsigned char* Wh = psm;                          // 128*272
    unsigned char* Bh = psm + 128 * PW_STRIDE;        // in hi
    unsigned char* Bl = Bh + 128 * PW_STRIDE;         // in lo

    const int tid = threadIdx.x, w = tid >> 5, lane = tid & 31;
    const int n0 = blockIdx.x * 128, b = blockIdx.y, wh = blockIdx.z;
    const float *W, *bias, *inb;
    if (wh == 0)      { W = Wq; bias = bq; inb = x  + (size_t)b * CC * NT; }
    else if (wh == 1) { W = Wk; bias = bk; inb = cx + (size_t)b * CC * NT; }
    else              { W = Wv; bias = bv; inb = cx + (size_t)b * CC * NT; }

    // stage W (hi only)
#pragma unroll
    for (int it = 0; it < 16; ++it) {
        const int idx = tid + it * 256;
        const int m = idx >> 5, c4 = idx & 31;
        float4 ww = *(const float4*)(W + m * 128 + c4 * 4);
        *(uint2*)(Wh + m * PW_STRIDE + c4 * 8) =
            make_uint2(packbf(ww.x, ww.y), packbf(ww.z, ww.w));
    }
    // stage input tile hi/lo
#pragma unroll
    for (int it = 0; it < 16; ++it) {
        const int idx = tid + it * 256;
        const int c = idx >> 5, c4 = idx & 31;
        float4 v = *(const float4*)(inb + (size_t)c * NT + n0 + c4 * 4);
        uint32_t h0 = packbf(v.x, v.y), h1 = packbf(v.z, v.w);
        float l0 = v.x - __uint_as_float(h0 << 16);
        float l1 = v.y - __uint_as_float(h0 & 0xffff0000u);
        float l2 = v.z - __uint_as_float(h1 << 16);
        float l3 = v.w - __uint_as_float(h1 & 0xffff0000u);
        *(uint2*)(Bh + c * PW_STRIDE + c4 * 8) = make_uint2(h0, h1);
        *(uint2*)(Bl + c * PW_STRIDE + c4 * 8) =
            make_uint2(packbf(l0, l1), packbf(l2, l3));
    }
    __syncthreads();

    const uint32_t uWh = smem_u32(Wh), uBh = smem_u32(Bh), uBl = smem_u32(Bl);
    uint32_t A[8][4];
    {
        const int q = lane >> 3, r = lane & 7;
#pragma unroll
        for (int ks = 0; ks < 8; ++ks)
            ldsm4(A[ks][0], A[ks][1], A[ks][2], A[ks][3],
                  uWh + (w * 16 + (q & 1) * 8 + r) * PW_STRIDE
                      + (ks * 16 + (q >> 1) * 8) * 2);
    }
    const int g = lane >> 2, tq = lane & 3;
    const int m0 = w * 16 + g, m1 = m0 + 8;
    const float bb0 = bias[m0], bb1 = bias[m1];

#pragma unroll
    for (int nh = 0; nh < 2; ++nh) {
        float acc[8][4];
#pragma unroll
        for (int nt = 0; nt < 8; ++nt)
            acc[nt][0] = acc[nt][1] = acc[nt][2] = acc[nt][3] = 0.f;

#pragma unroll
        for (int nt = 0; nt < 8; ++nt) {
            const uint32_t colb = nh * 128 + nt * 16;
#pragma unroll
            for (int cb = 0; cb < 4; ++cb) {
                uint32_t b0, b1, b2, b3;
                ldsm4t(b0, b1, b2, b3, uBh + (cb * 32 + lane) * PW_STRIDE + colb);
                mma16816(acc[nt], A[2*cb][0], A[2*cb][1], A[2*cb][2], A[2*cb][3], b0, b1);
                mma16816(acc[nt], A[2*cb+1][0], A[2*cb+1][1], A[2*cb+1][2], A[2*cb+1][3], b2, b3);
            }
#pragma unroll
            for (int cb = 0; cb < 4; ++cb) {
                uint32_t b0, b1, b2, b3;
                ldsm4t(b0, b1, b2, b3, uBl + (cb * 32 + lane) * PW_STRIDE + colb);
                mma16816(acc[nt], A[2*cb][0], A[2*cb][1], A[2*cb][2], A[2*cb][3], b0, b1);
                mma16816(acc[nt], A[2*cb+1][0], A[2*cb+1][1], A[2*cb+1][2], A[2*cb+1][3], b2, b3);
            }
        }
        if (wh == 2) {
            __nv_bfloat16* vb = g_vb + (size_t)(b * CC) * NT;
#pragma unroll
            for (int nt = 0; nt < 8; ++nt) {
                const int n = n0 + nh * 64 + nt * 8 + tq * 2;
                *(uint32_t*)(vb + (size_t)m0 * NT + n) = packbf(acc[nt][0] + bb0, acc[nt][1] + bb0);
                *(uint32_t*)(vb + (size_t)m1 * NT + n) = packbf(acc[nt][2] + bb1, acc[nt][3] + bb1);
            }
        } else {
            float* og = (wh == 0 ? g_q : g_k) + (size_t)(b * CC) * NT;
#pragma unroll
            for (int nt = 0; nt < 8; ++nt) {
                const int n = n0 + nh * 64 + nt * 8 + tq * 2;
                *(float2*)(og + (size_t)m0 * NT + n) = make_float2(acc[nt][0] + bb0, acc[nt][1] + bb0);
                *(float2*)(og + (size_t)m1 * NT + n) = make_float2(acc[nt][2] + bb1, acc[nt][3] + bb1);
            }
        }
    }
}

// proj_out: 3-pass Whi@hi + Whi@lo + Wlo@hi. CTA = 128 m x 64 n.
__global__ void __launch_bounds__(256, 2)
proj_out_mma(const float* __restrict__ Wo, const float* __restrict__ bo,
             float* __restrict__ out)
{
    extern __shared__ unsigned char psm[];
    unsigned char* Wh = psm;                          // 128*272
    unsigned char* Wl = psm + 128 * PW_STRIDE;        // 128*272
    unsigned char* Bh = Wl + 128 * PW_STRIDE;         // 128*144
    unsigned char* Bl = Bh + 128 * PB64_STRIDE;       // 128*144

    const int tid = threadIdx.x, w = tid >> 5, lane = tid & 31;
    const int n0 = blockIdx.x * 64, b = blockIdx.y;
    const float* inb = g_att + (size_t)b * CC * NT;

    // stage W hi + lo
#pragma unroll
    for (int it = 0; it < 16; ++it) {
        const int idx = tid + it * 256;
        const int m = idx >> 5, c4 = idx & 31;
        float4 ww = *(const float4*)(Wo + m * 128 + c4 * 4);
        uint32_t h0 = packbf(ww.x, ww.y), h1 = packbf(ww.z, ww.w);
        float l0 = ww.x - __uint_as_float(h0 << 16);
        float l1 = ww.y - __uint_as_float(h0 & 0xffff0000u);
        float l2 = ww.z - __uint_as_float(h1 << 16);
        float l3 = ww.w - __uint_as_float(h1 & 0xffff0000u);
        *(uint2*)(Wh + m * PW_STRIDE + c4 * 8) = make_uint2(h0, h1);
        *(uint2*)(Wl + m * PW_STRIDE + c4 * 8) =
            make_uint2(packbf(l0, l1), packbf(l2, l3));
    }
    // stage input tile hi/lo (128c x 64n)
#pragma unroll
    for (int it = 0; it < 8; ++it) {
        const int idx = tid + it * 256;
        const int c = idx >> 4, c4 = idx & 15;
        float4 v = *(const float4*)(inb + (size_t)c * NT + n0 + c4 * 4);
        uint32_t h0 = packbf(v.x, v.y), h1 = packbf(v.z, v.w);
        float l0 = v.x - __uint_as_float(h0 << 16);
        float l1 = v.y - __uint_as_float(h0 & 0xffff0000u);
        float l2 = v.z - __uint_as_float(h1 << 16);
        float l3 = v.w - __uint_as_float(h1 & 0xffff0000u);
        *(uint2*)(Bh + c * PB64_STRIDE + c4 * 8) = make_uint2(h0, h1);
        *(uint2*)(Bl + c * PB64_STRIDE + c4 * 8) =
            make_uint2(packbf(l0, l1), packbf(l2, l3));
    }
    __syncthreads();

    const uint32_t uWh = smem_u32(Wh), uWl = smem_u32(Wl);
    const uint32_t uBh = smem_u32(Bh), uBl = smem_u32(Bl);
    uint32_t Ah[8][4], Al[8][4];
    {
        const int q = lane >> 3, r = lane & 7;
#pragma unroll
        for (int ks = 0; ks < 8; ++ks) {
            const uint32_t off = (w * 16 + (q & 1) * 8 + r) * PW_STRIDE
                               + (ks * 16 + (q >> 1) * 8) * 2;
            ldsm4(Ah[ks][0], Ah[ks][1], Ah[ks][2], Ah[ks][3], uWh + off);
            ldsm4(Al[ks][0], Al[ks][1], Al[ks][2], Al[ks][3], uWl + off);
        }
    }
    float acc[8][4];
#pragma unroll
    for (int nt = 0; nt < 8; ++nt)
        acc[nt][0] = acc[nt][1] = acc[nt][2] = acc[nt][3] = 0.f;

#pragma unroll
    for (int nt = 0; nt < 8; ++nt) {
        const uint32_t colb = nt * 16;
#pragma unroll
        for (int cb = 0; cb < 4; ++cb) {       // Whi @ hi
            uint32_t b0, b1, b2, b3;
            ldsm4t(b0, b1, b2, b3, uBh + (cb * 32 + lane) * PB64_STRIDE + colb);
            mma16816(acc[nt], Ah[2*cb][0], Ah[2*cb][1], Ah[2*cb][2], Ah[2*cb][3], b0, b1);
            mma16816(acc[nt], Ah[2*cb+1][0], Ah[2*cb+1][1], Ah[2*cb+1][2], Ah[2*cb+1][3], b2, b3);
        }
#pragma unroll
        for (int cb = 0; cb < 4; ++cb) {       // Whi @ lo
            uint32_t b0, b1, b2, b3;
            ldsm4t(b0, b1, b2, b3, uBl + (cb * 32 + lane) * PB64_STRIDE + colb);
            mma16816(acc[nt], Ah[2*cb][0], Ah[2*cb][1], Ah[2*cb][2], Ah[2*cb][3], b0, b1);
            mma16816(acc[nt], Ah[2*cb+1][0], Ah[2*cb+1][1], Ah[2*cb+1][2], Ah[2*cb+1][3], b2, b3);
        }
#pragma unroll
        for (int cb = 0; cb < 4; ++cb) {       // Wlo @ hi
            uint32_t b0, b1, b2, b3;
            ldsm4t(b0, b1, b2, b3, uBh + (cb * 32 + lane) * PB64_STRIDE + colb);
            mma16816(acc[nt], Al[2*cb][0], Al[2*cb][1], Al[2*cb][2], Al[2*cb][3], b0, b1);
            mma16816(acc[nt], Al[2*cb+1][0], Al[2*cb+1][1], Al[2*cb+1][2], Al[2*cb+1][3], b2, b3);
        }
    }
    const int g = lane >> 2, tq = lane & 3;
    const int m0 = w * 16 + g, m1 = m0 + 8;
    const float bb0 = bo[m0], bb1 = bo[m1];
    float* og = out + (size_t)(b * CC) * NT;
#pragma unroll
    for (int nt = 0; nt < 8; ++nt) {
        const int n = n0 + nt * 8 + tq * 2;
        *(float2*)(og + (size_t)m0 * NT + n) = make_float2(acc[nt][0] + bb0, acc[nt][1] + bb0);
        *(float2*)(og + (size_t)m1 * NT + n) = make_float2(acc[nt][2] + bb1, acc[nt][3] + bb1);
    }
}

// =============================================================================
// L2 normalize q,k rows over the spatial axis; write bf16 (SCALE folded into q)
// =============================================================================
__global__ void __launch_bounds__(256, 1) norm_kernel()
{
    const int row = blockIdx.x;
    const float* p = (blockIdx.y == 0 ? g_q : g_k) + (size_t)row * NT;
    __nv_bfloat16* ob = (blockIdx.y == 0 ? g_qb : g_kb) + (size_t)row * NT;
    const int tid = threadIdx.x;

    float s = 0.f;
#pragma unroll
    for (int it = 0; it < 4; ++it) {
        float4 v = ((const float4*)p)[tid + it * 256];
        s += v.x * v.x + v.y * v.y + v.z * v.z + v.w * v.w;
    }
#pragma unroll
    for (int o = 16; o > 0; o >>= 1) s += __shfl_xor_sync(0xffffffffu, s, o);

    __shared__ float red[8];
    if ((tid & 31) == 0) red[tid >> 5] = s;
    __syncthreads();
    if (tid < 32) {
        float v = (tid < 8) ? red[tid] : 0.f;
#pragma unroll
        for (int o = 4; o > 0; o >>= 1) v += __shfl_xor_sync(0xffffffffu, v, o);
        if (tid == 0) red[0] = v;
    }
    __syncthreads();
    const float tot = red[0];
    const float scl = (blockIdx.y == 0 ? SCALE_F : 1.0f) / fmaxf(sqrtf(tot), 1e-12f);

#pragma unroll
    for (int it = 0; it < 4; ++it) {
        float4 v = ((const float4*)p)[tid + it * 256];
        ((uint2*)ob)[tid + it * 256] =
            make_uint2(packbf(v.x * scl, v.y * scl), packbf(v.z * scl, v.w * scl));
    }
}

// colsum[b][c] = sum_n cond_x[b][c][n]   (exact fp32; feeds attn's sumv)
__global__ void __launch_bounds__(256, 1) colsum_kernel(const float* __restrict__ cx)
{
    const int row = blockIdx.x;
    const float* p = cx + (size_t)row * NT;
    const int tid = threadIdx.x;
    float s = 0.f;
#pragma unroll
    for (int it = 0; it < 4; ++it) {
        float4 v = ((const float4*)p)[tid + it * 256];
        s += v.x + v.y + v.z + v.w;
    }
#pragma unroll
    for (int o = 16; o > 0; o >>= 1) s += __shfl_xor_sync(0xffffffffu, s, o);
    __shared__ float red[8];
    if ((tid & 31) == 0) red[tid >> 5] = s;
    __syncthreads();
    if (tid == 0)
        g_colsum[row] = red[0] + red[1] + red[2] + red[3] +
                        red[4] + red[5] + red[6] + red[7];
}

// =============================================================================
// mma.sync flash attention (proven 120.8us compute loop) + in-kernel sumv.
// =============================================================================
#define QS_STRIDE 80
#define KS_STRIDE 272

__global__ void __launch_bounds__(256, 2)
attn_mma_kernel(const float* __restrict__ Wv, const float* __restrict__ bv)
{
    __shared__ __align__(16) unsigned char Qs[128 * QS_STRIDE];
    __shared__ __align__(16) unsigned char Kb[2][32 * KS_STRIDE];
    __shared__ __align__(16) unsigned char Vb[2][32 * KS_STRIDE];
    __shared__ float svs[DH];

    const int tid  = threadIdx.x;
    const int w    = tid >> 5;
    const int lane = tid & 31;
    const int i0 = blockIdx.x * 128;
    const int hh = blockIdx.y;
    const int b  = blockIdx.z;
    const int cb = b * CC + hh * DH;
    const __nv_bfloat16* qg = g_qb + (size_t)cb * NT;
    const __nv_bfloat16* kg = g_kb + (size_t)cb * NT;
    const __nv_bfloat16* vg = g_vb + (size_t)cb * NT;

    const uint32_t uQs = smem_u32(Qs);
    const uint32_t uK0 = smem_u32(Kb[0]), uK1 = smem_u32(Kb[1]);
    const uint32_t uV0 = smem_u32(Vb[0]), uV1 = smem_u32(Vb[1]);

    {
        const int i  = tid & 127;
        const int dh = (tid >> 7) * 16;
#pragma unroll
        for (int v = 0; v < 8; ++v) {
            uint32_t lo = *(const uint16_t*)(qg + (size_t)(dh + 2 * v) * NT + i0 + i);
            uint32_t hi = *(const uint16_t*)(qg + (size_t)(dh + 2 * v + 1) * NT + i0 + i);
            *(uint32_t*)(Qs + i * QS_STRIDE + (dh + 2 * v) * 2) = lo | (hi << 16);
        }
    }
    {
#pragma unroll
        for (int r = 0; r < 2; ++r) {
            const int idx = tid + r * 256;
            const int d = idx >> 4, ch = idx & 15;
            cp16(uK0 + d * KS_STRIDE + ch * 16, kg + (size_t)d * NT + ch * 8);
            cp16(uV0 + d * KS_STRIDE + ch * 16, vg + (size_t)d * NT + ch * 8);
        }
        asm volatile("cp.async.commit_group;" ::: "memory");
    }
    __syncthreads();

    uint32_t qa[2][4];
    {
        const int q = lane >> 3, r = lane & 7;
#pragma unroll
        for (int ks = 0; ks < 2; ++ks) {
            uint32_t addr = uQs + (w * 16 + (q & 1) * 8 + r) * QS_STRIDE
                                + (ks * 16 + (q >> 1) * 8) * 2;
            ldsm4(qa[ks][0], qa[ks][1], qa[ks][2], qa[ks][3], addr);
        }
    }

    float oc[4][4];
#pragma unroll
    for (int dn = 0; dn < 4; ++dn)
#pragma unroll
        for (int u = 0; u < 4; ++u) oc[dn][u] = 0.f;
    float dev_lo = 0.f, dev_hi = 0.f;

    const int lq = lane >> 3, lr = lane & 7;

    for (int t = 0; t < 32; ++t) {
        asm volatile("cp.async.wait_group 0;" ::: "memory");
        __syncthreads();

        if (t < 31) {
            const uint32_t uKn = ((t + 1) & 1) ? uK1 : uK0;
            const uint32_t uVn = ((t + 1) & 1) ? uV1 : uV0;
            const int j0n = (t + 1) * 128;
#pragma unroll
            for (int r = 0; r < 2; ++r) {
                const int idx = tid + r * 256;
                const int d = idx >> 4, ch = idx & 15;
                cp16(uKn + d * KS_STRIDE + ch * 16, kg + (size_t)d * NT + j0n + ch * 8);
                cp16(uVn + d * KS_STRIDE + ch * 16, vg + (size_t)d * NT + j0n + ch * 8);
            }
            asm volatile("cp.async.commit_group;" ::: "memory");
        }

        const uint32_t uKs = (t & 1) ? uK1 : uK0;
        const uint32_t uVs = (t & 1) ? uV1 : uV0;
        const uint32_t kAddrBase = uKs + lane * KS_STRIDE;

#pragma unroll
        for (int u = 0; u < 4; ++u) {
            float sc[4][4];
            uint32_t pl[4], ph[4];
#pragma unroll
            for (int q2 = 0; q2 < 4; ++q2) {
                uint32_t b0, b1, b2, b3;
                ldsm4t(b0, b1, b2, b3, kAddrBase + (4 * u + q2) * 16);
                sc[q2][0] = sc[q2][1] = sc[q2][2] = sc[q2][3] = 0.f;
                mma16816(sc[q2], qa[0][0], qa[0][1], qa[0][2], qa[0][3], b0, b1);
                mma16816(sc[q2], qa[1][0], qa[1][1], qa[1][2], qa[1][3], b2, b3);
            }
#pragma unroll
            for (int q2 = 0; q2 < 4; ++q2) {
                float d0 = expm1_poly(sc[q2][0]);
                float d1 = expm1_poly(sc[q2][1]);
                float d2 = expm1_poly(sc[q2][2]);
                float d3 = expm1_poly(sc[q2][3]);
                dev_lo += d0 + d1;
                dev_hi += d2 + d3;
                pl[q2] = packbf(d0, d1);
                ph[q2] = packbf(d2, d3);
            }
#pragma unroll
            for (int dn = 0; dn < 4; ++dn) {
                uint32_t b0, b1, b2, b3;
                ldsm4(b0, b1, b2, b3,
                      uVs + (dn * 8 + lr) * KS_STRIDE + (4 * u + lq) * 16);
                mma16816(oc[dn], pl[0], ph[0], pl[1], ph[1], b0, b1);
                mma16816(oc[dn], pl[2], ph[2], pl[3], ph[3], b2, b3);
            }
        }
    }

    // ---- in-kernel sumv: svs[d] = Wv[hh*32+d,:] . colsum[b,:] + NT*bv ----
    {
#pragma unroll
        for (int mi = 0; mi < 4; ++mi) {
            const int d = w * 4 + mi;
            const int m = hh * DH + d;
            float s = 0.f;
#pragma unroll
            for (int c4 = 0; c4 < 4; ++c4) {
                const int c = c4 * 32 + lane;
                s += Wv[m * 128 + c] * g_colsum[b * CC + c];
            }
#pragma unroll
            for (int o = 16; o > 0; o >>= 1) s += __shfl_xor_sync(0xffffffffu, s, o);
            if (lane == 0) svs[d] = s + (float)NT * bv[m];
        }
    }
    __syncthreads();

    // ---- epilogue: quad-reduce row sums, rank-1 + denominator ----
    dev_lo += __shfl_xor_sync(0xffffffffu, dev_lo, 1);
    dev_lo += __shfl_xor_sync(0xffffffffu, dev_lo, 2);
    dev_hi += __shfl_xor_sync(0xffffffffu, dev_hi, 1);
    dev_hi += __shfl_xor_sync(0xffffffffu, dev_hi, 2);

    const int tq = lane & 3, g = lane >> 2;
    const int i_lo = i0 + w * 16 + g;
    const int i_hi = i_lo + 8;
    const float inv_lo = 1.0f / (4096.0f + dev_lo);
    const float inv_hi = 1.0f / (4096.0f + dev_hi);
    float* att = g_att + (size_t)cb * NT;

#pragma unroll
    for (int dn = 0; dn < 4; ++dn) {
        const int d0 = dn * 8 + 2 * tq;
        const float s0 = svs[d0], s1 = svs[d0 + 1];
        att[(size_t)d0 * NT + i_lo]       = (oc[dn][0] + s0) * inv_lo;
        att[(size_t)(d0 + 1) * NT + i_lo] = (oc[dn][1] + s1) * inv_lo;
        att[(size_t)d0 * NT + i_hi]       = (oc[dn][2] + s0) * inv_hi;
        att[(size_t)(d0 + 1) * NT + i_hi] = (oc[dn][3] + s1) * inv_hi;
    }
}

// =============================================================================
// Launch  (attn is the 4th launch -> it is the kernel ncu captures)
// =============================================================================
extern "C" void kernel_launch(void* const* d_in, const int* in_sizes, int n_in,
                              void* d_out, int out_size)
{
    (void)in_sizes; (void)n_in; (void)out_size;
    const float* x  = (const float*)d_in[0];
    const float* cx = (const float*)d_in[1];
    const float* Wq = (const float*)d_in[2];
    const float* bq = (const float*)d_in[3];
    const float* Wk = (const float*)d_in[4];
    const float* bk = (const float*)d_in[5];
    const float* Wv = (const float*)d_in[6];
    const float* bv = (const float*)d_in[7];
    const float* Wo = (const float*)d_in[8];
    const float* bo = (const float*)d_in[9];
    float* out = (float*)d_out;

    const int QKV_SMEM = 3 * 128 * PW_STRIDE;                      // 104448
    const int OUT_SMEM = 2 * 128 * PW_STRIDE + 2 * 128 * PB64_STRIDE;  // 106496

    cudaFuncSetAttribute(proj_qkv_mma, cudaFuncAttributeMaxDynamicSharedMemorySize, QKV_SMEM);
    cudaFuncSetAttribute(proj_out_mma, cudaFuncAttributeMaxDynamicSharedMemorySize, OUT_SMEM);

    proj_qkv_mma<<<dim3(NT / 128, BB, 3), 256, QKV_SMEM>>>(x, cx, Wq, bq, Wk, bk, Wv, bv);
    colsum_kernel<<<dim3(BB * CC), 256>>>(cx);
    norm_kernel<<<dim3(BB * CC, 2), 256>>>();
    attn_mma_kernel<<<dim3(NT / 128, NH, BB), 256>>>(Wv, bv);
    proj_out_mma<<<dim3(NT / 64, BB), 256, OUT_SMEM>>>(Wo, bo, out);
}

// round 9
// speedup vs baseline: 1.3243x; 1.0648x over previous
#include <cuda_runtime.h>
#include <cuda_bf16.h>
#include <cstdint>
#include <math.h>

#define BB 2
#define CC 128
#define NH 4
#define DH 32
#define NT 4096
#define SCALE_F 10.0f

// ---------------- scratch (static device memory; no allocations) -------------
static __device__ float g_q[BB * CC * NT];            // fp32 q (pre-norm)
static __device__ float g_k[BB * CC * NT];            // fp32 k (pre-norm)
static __device__ __nv_bfloat16 g_qb[BB * CC * NT];   // bf16 normalized*SCALE q
static __device__ __nv_bfloat16 g_kb[BB * CC * NT];   // bf16 normalized k
static __device__ __nv_bfloat16 g_vb[BB * CC * NT];   // bf16 v
static __device__ float g_att[BB * CC * NT];
static __device__ float g_colsum[BB * CC];

// =============================================================================
// helpers
// =============================================================================
__device__ __forceinline__ uint32_t smem_u32(const void* p) {
    uint32_t a;
    asm("{ .reg .u64 t; cvta.to.shared.u64 t, %1; cvt.u32.u64 %0, t; }"
        : "=r"(a) : "l"(p));
    return a;
}

__device__ __forceinline__ uint32_t packbf(float a, float b) {
    uint32_t r;
    asm("cvt.rn.bf16x2.f32 %0, %2, %1;" : "=r"(r) : "f"(a), "f"(b));
    return r;  // lo = a, hi = b
}

// packed bf16x2 fma (non-volatile: scheduler may interleave with mma stream)
__device__ __forceinline__ uint32_t bffma2(uint32_t a, uint32_t b, uint32_t c) {
    uint32_t d;
    asm("fma.rn.bf16x2 %0, %1, %2, %3;" : "=r"(d) : "r"(a), "r"(b), "r"(c));
    return d;
}

__device__ __forceinline__ void ldsm4(uint32_t& r0, uint32_t& r1, uint32_t& r2,
                                      uint32_t& r3, uint32_t addr) {
    asm volatile("ldmatrix.sync.aligned.m8n8.x4.shared.b16 {%0,%1,%2,%3}, [%4];"
                 : "=r"(r0), "=r"(r1), "=r"(r2), "=r"(r3) : "r"(addr));
}

__device__ __forceinline__ void ldsm4t(uint32_t& r0, uint32_t& r1, uint32_t& r2,
                                       uint32_t& r3, uint32_t addr) {
    asm volatile("ldmatrix.sync.aligned.m8n8.x4.trans.shared.b16 {%0,%1,%2,%3}, [%4];"
                 : "=r"(r0), "=r"(r1), "=r"(r2), "=r"(r3) : "r"(addr));
}

__device__ __forceinline__ void mma16816(float* c, uint32_t a0, uint32_t a1,
                                         uint32_t a2, uint32_t a3,
                                         uint32_t b0, uint32_t b1) {
    asm volatile(
        "mma.sync.aligned.m16n8k16.row.col.f32.bf16.bf16.f32 "
        "{%0,%1,%2,%3}, {%4,%5,%6,%7}, {%8,%9}, {%0,%1,%2,%3};"
        : "+f"(c[0]), "+f"(c[1]), "+f"(c[2]), "+f"(c[3])
        : "r"(a0), "r"(a1), "r"(a2), "r"(a3), "r"(b0), "r"(b1));
}

__device__ __forceinline__ void cp16(uint32_t dst, const void* src) {
    asm volatile("cp.async.cg.shared.global [%0], [%1], 16;"
                 :: "r"(dst), "l"(src) : "memory");
}

// =============================================================================
// Tensor-core projection GEMMs (hi/lo bf16 split of fp32 operands) — unchanged.
// =============================================================================
#define PW_STRIDE 272
#define PB64_STRIDE 144

__global__ void __launch_bounds__(256, 2)
proj_qkv_mma(const float* __restrict__ x, const float* __restrict__ cx,
             const float* __restrict__ Wq, const float* __restrict__ bq,
             const float* __restrict__ Wk, const float* __restrict__ bk,
             const float* __restrict__ Wv, const float* __restrict__ bv)
{
    extern __shared__ unsigned char psm[];
    unsigned char* Wh = psm;
    unsigned char* Bh = psm + 128 * PW_STRIDE;
    unsigned char* Bl = Bh + 128 * PW_STRIDE;

    const int tid = threadIdx.x, w = tid >> 5, lane = tid & 31;
    const int n0 = blockIdx.x * 128, b = blockIdx.y, wh = blockIdx.z;
    const float *W, *bias, *inb;
    if (wh == 0)      { W = Wq; bias = bq; inb = x  + (size_t)b * CC * NT; }
    else if (wh == 1) { W = Wk; bias = bk; inb = cx + (size_t)b * CC * NT; }
    else              { W = Wv; bias = bv; inb = cx + (size_t)b * CC * NT; }

#pragma unroll
    for (int it = 0; it < 16; ++it) {
        const int idx = tid + it * 256;
        const int m = idx >> 5, c4 = idx & 31;
        float4 ww = *(const float4*)(W + m * 128 + c4 * 4);
        *(uint2*)(Wh + m * PW_STRIDE + c4 * 8) =
            make_uint2(packbf(ww.x, ww.y), packbf(ww.z, ww.w));
    }
#pragma unroll
    for (int it = 0; it < 16; ++it) {
        const int idx = tid + it * 256;
        const int c = idx >> 5, c4 = idx & 31;
        float4 v = *(const float4*)(inb + (size_t)c * NT + n0 + c4 * 4);
        uint32_t h0 = packbf(v.x, v.y), h1 = packbf(v.z, v.w);
        float l0 = v.x - __uint_as_float(h0 << 16);
        float l1 = v.y - __uint_as_float(h0 & 0xffff0000u);
        float l2 = v.z - __uint_as_float(h1 << 16);
        float l3 = v.w - __uint_as_float(h1 & 0xffff0000u);
        *(uint2*)(Bh + c * PW_STRIDE + c4 * 8) = make_uint2(h0, h1);
        *(uint2*)(Bl + c * PW_STRIDE + c4 * 8) =
            make_uint2(packbf(l0, l1), packbf(l2, l3));
    }
    __syncthreads();

    const uint32_t uWh = smem_u32(Wh), uBh = smem_u32(Bh), uBl = smem_u32(Bl);
    uint32_t A[8][4];
    {
        const int q = lane >> 3, r = lane & 7;
#pragma unroll
        for (int ks = 0; ks < 8; ++ks)
            ldsm4(A[ks][0], A[ks][1], A[ks][2], A[ks][3],
                  uWh + (w * 16 + (q & 1) * 8 + r) * PW_STRIDE
                      + (ks * 16 + (q >> 1) * 8) * 2);
    }
    const int g = lane >> 2, tq = lane & 3;
    const int m0 = w * 16 + g, m1 = m0 + 8;
    const float bb0 = bias[m0], bb1 = bias[m1];

#pragma unroll
    for (int nh = 0; nh < 2; ++nh) {
        float acc[8][4];
#pragma unroll
        for (int nt = 0; nt < 8; ++nt)
            acc[nt][0] = acc[nt][1] = acc[nt][2] = acc[nt][3] = 0.f;

#pragma unroll
        for (int nt = 0; nt < 8; ++nt) {
            const uint32_t colb = nh * 128 + nt * 16;
#pragma unroll
            for (int cb = 0; cb < 4; ++cb) {
                uint32_t b0, b1, b2, b3;
                ldsm4t(b0, b1, b2, b3, uBh + (cb * 32 + lane) * PW_STRIDE + colb);
                mma16816(acc[nt], A[2*cb][0], A[2*cb][1], A[2*cb][2], A[2*cb][3], b0, b1);
                mma16816(acc[nt], A[2*cb+1][0], A[2*cb+1][1], A[2*cb+1][2], A[2*cb+1][3], b2, b3);
            }
#pragma unroll
            for (int cb = 0; cb < 4; ++cb) {
                uint32_t b0, b1, b2, b3;
                ldsm4t(b0, b1, b2, b3, uBl + (cb * 32 + lane) * PW_STRIDE + colb);
                mma16816(acc[nt], A[2*cb][0], A[2*cb][1], A[2*cb][2], A[2*cb][3], b0, b1);
                mma16816(acc[nt], A[2*cb+1][0], A[2*cb+1][1], A[2*cb+1][2], A[2*cb+1][3], b2, b3);
            }
        }
        if (wh == 2) {
            __nv_bfloat16* vb = g_vb + (size_t)(b * CC) * NT;
#pragma unroll
            for (int nt = 0; nt < 8; ++nt) {
                const int n = n0 + nh * 64 + nt * 8 + tq * 2;
                *(uint32_t*)(vb + (size_t)m0 * NT + n) = packbf(acc[nt][0] + bb0, acc[nt][1] + bb0);
                *(uint32_t*)(vb + (size_t)m1 * NT + n) = packbf(acc[nt][2] + bb1, acc[nt][3] + bb1);
            }
        } else {
            float* og = (wh == 0 ? g_q : g_k) + (size_t)(b * CC) * NT;
#pragma unroll
            for (int nt = 0; nt < 8; ++nt) {
                const int n = n0 + nh * 64 + nt * 8 + tq * 2;
                *(float2*)(og + (size_t)m0 * NT + n) = make_float2(acc[nt][0] + bb0, acc[nt][1] + bb0);
                *(float2*)(og + (size_t)m1 * NT + n) = make_float2(acc[nt][2] + bb1, acc[nt][3] + bb1);
            }
        }
    }
}

__global__ void __launch_bounds__(256, 2)
proj_out_mma(const float* __restrict__ Wo, const float* __restrict__ bo,
             float* __restrict__ out)
{
    extern __shared__ unsigned char psm[];
    unsigned char* Wh = psm;
    unsigned char* Wl = psm + 128 * PW_STRIDE;
    unsigned char* Bh = Wl + 128 * PW_STRIDE;
    unsigned char* Bl = Bh + 128 * PB64_STRIDE;

    const int tid = threadIdx.x, w = tid >> 5, lane = tid & 31;
    const int n0 = blockIdx.x * 64, b = blockIdx.y;
    const float* inb = g_att + (size_t)b * CC * NT;

#pragma unroll
    for (int it = 0; it < 16; ++it) {
        const int idx = tid + it * 256;
        const int m = idx >> 5, c4 = idx & 31;
        float4 ww = *(const float4*)(Wo + m * 128 + c4 * 4);
        uint32_t h0 = packbf(ww.x, ww.y), h1 = packbf(ww.z, ww.w);
        float l0 = ww.x - __uint_as_float(h0 << 16);
        float l1 = ww.y - __uint_as_float(h0 & 0xffff0000u);
        float l2 = ww.z - __uint_as_float(h1 << 16);
        float l3 = ww.w - __uint_as_float(h1 & 0xffff0000u);
        *(uint2*)(Wh + m * PW_STRIDE + c4 * 8) = make_uint2(h0, h1);
        *(uint2*)(Wl + m * PW_STRIDE + c4 * 8) =
            make_uint2(packbf(l0, l1), packbf(l2, l3));
    }
#pragma unroll
    for (int it = 0; it < 8; ++it) {
        const int idx = tid + it * 256;
        const int c = idx >> 4, c4 = idx & 15;
        float4 v = *(const float4*)(inb + (size_t)c * NT + n0 + c4 * 4);
        uint32_t h0 = packbf(v.x, v.y), h1 = packbf(v.z, v.w);
        float l0 = v.x - __uint_as_float(h0 << 16);
        float l1 = v.y - __uint_as_float(h0 & 0xffff0000u);
        float l2 = v.z - __uint_as_float(h1 << 16);
        float l3 = v.w - __uint_as_float(h1 & 0xffff0000u);
        *(uint2*)(Bh + c * PB64_STRIDE + c4 * 8) = make_uint2(h0, h1);
        *(uint2*)(Bl + c * PB64_STRIDE + c4 * 8) =
            make_uint2(packbf(l0, l1), packbf(l2, l3));
    }
    __syncthreads();

    const uint32_t uWh = smem_u32(Wh), uWl = smem_u32(Wl);
    const uint32_t uBh = smem_u32(Bh), uBl = smem_u32(Bl);
    uint32_t Ah[8][4], Al[8][4];
    {
        const int q = lane >> 3, r = lane & 7;
#pragma unroll
        for (int ks = 0; ks < 8; ++ks) {
            const uint32_t off = (w * 16 + (q & 1) * 8 + r) * PW_STRIDE
                               + (ks * 16 + (q >> 1) * 8) * 2;
            ldsm4(Ah[ks][0], Ah[ks][1], Ah[ks][2], Ah[ks][3], uWh + off);
            ldsm4(Al[ks][0], Al[ks][1], Al[ks][2], Al[ks][3], uWl + off);
        }
    }
    float acc[8][4];
#pragma unroll
    for (int nt = 0; nt < 8; ++nt)
        acc[nt][0] = acc[nt][1] = acc[nt][2] = acc[nt][3] = 0.f;

#pragma unroll
    for (int nt = 0; nt < 8; ++nt) {
        const uint32_t colb = nt * 16;
#pragma unroll
        for (int cb = 0; cb < 4; ++cb) {
            uint32_t b0, b1, b2, b3;
            ldsm4t(b0, b1, b2, b3, uBh + (cb * 32 + lane) * PB64_STRIDE + colb);
            mma16816(acc[nt], Ah[2*cb][0], Ah[2*cb][1], Ah[2*cb][2], Ah[2*cb][3], b0, b1);
            mma16816(acc[nt], Ah[2*cb+1][0], Ah[2*cb+1][1], Ah[2*cb+1][2], Ah[2*cb+1][3], b2, b3);
        }
#pragma unroll
        for (int cb = 0; cb < 4; ++cb) {
            uint32_t b0, b1, b2, b3;
            ldsm4t(b0, b1, b2, b3, uBl + (cb * 32 + lane) * PB64_STRIDE + colb);
            mma16816(acc[nt], Ah[2*cb][0], Ah[2*cb][1], Ah[2*cb][2], Ah[2*cb][3], b0, b1);
            mma16816(acc[nt], Ah[2*cb+1][0], Ah[2*cb+1][1], Ah[2*cb+1][2], Ah[2*cb+1][3], b2, b3);
        }
#pragma unroll
        for (int cb = 0; cb < 4; ++cb) {
            uint32_t b0, b1, b2, b3;
            ldsm4t(b0, b1, b2, b3, uBh + (cb * 32 + lane) * PB64_STRIDE + colb);
            mma16816(acc[nt], Al[2*cb][0], Al[2*cb][1], Al[2*cb][2], Al[2*cb][3], b0, b1);
            mma16816(acc[nt], Al[2*cb+1][0], Al[2*cb+1][1], Al[2*cb+1][2], Al[2*cb+1][3], b2, b3);
        }
    }
    const int g = lane >> 2, tq = lane & 3;
    const int m0 = w * 16 + g, m1 = m0 + 8;
    const float bb0 = bo[m0], bb1 = bo[m1];
    float* og = out + (size_t)(b * CC) * NT;
#pragma unroll
    for (int nt = 0; nt < 8; ++nt) {
        const int n = n0 + nt * 8 + tq * 2;
        *(float2*)(og + (size_t)m0 * NT + n) = make_float2(acc[nt][0] + bb0, acc[nt][1] + bb0);
        *(float2*)(og + (size_t)m1 * NT + n) = make_float2(acc[nt][2] + bb1, acc[nt][3] + bb1);
    }
}

// =============================================================================
// L2 normalize q,k rows (spatial axis); single pass — values stay in registers.
// =============================================================================
__global__ void __launch_bounds__(256, 1) norm_kernel()
{
    const int row = blockIdx.x;
    const float* p = (blockIdx.y == 0 ? g_q : g_k) + (size_t)row * NT;
    __nv_bfloat16* ob = (blockIdx.y == 0 ? g_qb : g_kb) + (size_t)row * NT;
    const int tid = threadIdx.x;

    float4 v[4];
    float s = 0.f;
#pragma unroll
    for (int it = 0; it < 4; ++it) {
        v[it] = ((const float4*)p)[tid + it * 256];
        s += v[it].x * v[it].x + v[it].y * v[it].y +
             v[it].z * v[it].z + v[it].w * v[it].w;
    }
#pragma unroll
    for (int o = 16; o > 0; o >>= 1) s += __shfl_xor_sync(0xffffffffu, s, o);

    __shared__ float red[8];
    if ((tid & 31) == 0) red[tid >> 5] = s;
    __syncthreads();
    if (tid < 32) {
        float vv = (tid < 8) ? red[tid] : 0.f;
#pragma unroll
        for (int o = 4; o > 0; o >>= 1) vv += __shfl_xor_sync(0xffffffffu, vv, o);
        if (tid == 0) red[0] = vv;
    }
    __syncthreads();
    const float tot = red[0];
    const float scl = (blockIdx.y == 0 ? SCALE_F : 1.0f) / fmaxf(sqrtf(tot), 1e-12f);

#pragma unroll
    for (int it = 0; it < 4; ++it) {
        ((uint2*)ob)[tid + it * 256] =
            make_uint2(packbf(v[it].x * scl, v[it].y * scl),
                       packbf(v[it].z * scl, v[it].w * scl));
    }
}

// colsum[b][c] = sum_n cond_x[b][c][n]
__global__ void __launch_bounds__(256, 1) colsum_kernel(const float* __restrict__ cx)
{
    const int row = blockIdx.x;
    const float* p = cx + (size_t)row * NT;
    const int tid = threadIdx.x;
    float s = 0.f;
#pragma unroll
    for (int it = 0; it < 4; ++it) {
        float4 v = ((const float4*)p)[tid + it * 256];
        s += v.x + v.y + v.z + v.w;
    }
#pragma unroll
    for (int o = 16; o > 0; o >>= 1) s += __shfl_xor_sync(0xffffffffu, s, o);
    __shared__ float red[8];
    if ((tid & 31) == 0) red[tid >> 5] = s;
    __syncthreads();
    if (tid == 0)
        g_colsum[row] = red[0] + red[1] + red[2] + red[3] +
                        red[4] + red[5] + red[6] + red[7];
}

// =============================================================================
// mma.sync flash attention; softmax arithmetic in packed bf16x2.
// dev = expm1(s) computed as bf16x2 poly: d = x*(1 + x*(1/2 + x/6)); row sums
// accumulated as bf16x2 (error << 1e-5 of denominator).
// =============================================================================
#define QS_STRIDE 80
#define KS_STRIDE 272

__global__ void __launch_bounds__(256, 2)
attn_mma_kernel(const float* __restrict__ Wv, const float* __restrict__ bv)
{
    __shared__ __align__(16) unsigned char Qs[128 * QS_STRIDE];
    __shared__ __align__(16) unsigned char Kb[2][32 * KS_STRIDE];
    __shared__ __align__(16) unsigned char Vb[2][32 * KS_STRIDE];
    __shared__ float svs[DH];

    const int tid  = threadIdx.x;
    const int w    = tid >> 5;
    const int lane = tid & 31;
    const int i0 = blockIdx.x * 128;
    const int hh = blockIdx.y;
    const int b  = blockIdx.z;
    const int cb = b * CC + hh * DH;
    const __nv_bfloat16* qg = g_qb + (size_t)cb * NT;
    const __nv_bfloat16* kg = g_kb + (size_t)cb * NT;
    const __nv_bfloat16* vg = g_vb + (size_t)cb * NT;

    const uint32_t uQs = smem_u32(Qs);
    const uint32_t uK0 = smem_u32(Kb[0]), uK1 = smem_u32(Kb[1]);
    const uint32_t uV0 = smem_u32(Vb[0]), uV1 = smem_u32(Vb[1]);

    // bf16x2 poly constants
    const uint32_t C6 = packbf(1.0f / 6.0f, 1.0f / 6.0f);
    const uint32_t C2 = packbf(0.5f, 0.5f);
    const uint32_t C1 = packbf(1.0f, 1.0f);

    {
        const int i  = tid & 127;
        const int dh = (tid >> 7) * 16;
#pragma unroll
        for (int v = 0; v < 8; ++v) {
            uint32_t lo = *(const uint16_t*)(qg + (size_t)(dh + 2 * v) * NT + i0 + i);
            uint32_t hi = *(const uint16_t*)(qg + (size_t)(dh + 2 * v + 1) * NT + i0 + i);
            *(uint32_t*)(Qs + i * QS_STRIDE + (dh + 2 * v) * 2) = lo | (hi << 16);
        }
    }
    {
#pragma unroll
        for (int r = 0; r < 2; ++r) {
            const int idx = tid + r * 256;
            const int d = idx >> 4, ch = idx & 15;
            cp16(uK0 + d * KS_STRIDE + ch * 16, kg + (size_t)d * NT + ch * 8);
            cp16(uV0 + d * KS_STRIDE + ch * 16, vg + (size_t)d * NT + ch * 8);
        }
        asm volatile("cp.async.commit_group;" ::: "memory");
    }
    __syncthreads();

    uint32_t qa[2][4];
    {
        const int q = lane >> 3, r = lane & 7;
#pragma unroll
        for (int ks = 0; ks < 2; ++ks) {
            uint32_t addr = uQs + (w * 16 + (q & 1) * 8 + r) * QS_STRIDE
                                + (ks * 16 + (q >> 1) * 8) * 2;
            ldsm4(qa[ks][0], qa[ks][1], qa[ks][2], qa[ks][3], addr);
        }
    }

    float oc[4][4];
#pragma unroll
    for (int dn = 0; dn < 4; ++dn)
#pragma unroll
        for (int u = 0; u < 4; ++u) oc[dn][u] = 0.f;
    uint32_t s01 = 0, s23 = 0;   // packed bf16x2 row-sum accumulators

    const int lq = lane >> 3, lr = lane & 7;

    for (int t = 0; t < 32; ++t) {
        asm volatile("cp.async.wait_group 0;" ::: "memory");
        __syncthreads();

        if (t < 31) {
            const uint32_t uKn = ((t + 1) & 1) ? uK1 : uK0;
            const uint32_t uVn = ((t + 1) & 1) ? uV1 : uV0;
            const int j0n = (t + 1) * 128;
#pragma unroll
            for (int r = 0; r < 2; ++r) {
                const int idx = tid + r * 256;
                const int d = idx >> 4, ch = idx & 15;
                cp16(uKn + d * KS_STRIDE + ch * 16, kg + (size_t)d * NT + j0n + ch * 8);
                cp16(uVn + d * KS_STRIDE + ch * 16, vg + (size_t)d * NT + j0n + ch * 8);
            }
            asm volatile("cp.async.commit_group;" ::: "memory");
        }

        const uint32_t uKs = (t & 1) ? uK1 : uK0;
        const uint32_t uVs = (t & 1) ? uV1 : uV0;
        const uint32_t kAddrBase = uKs + lane * KS_STRIDE;

#pragma unroll
        for (int u = 0; u < 4; ++u) {
            float sc[4][4];
            uint32_t pl[4], ph[4];
#pragma unroll
            for (int q2 = 0; q2 < 4; ++q2) {
                uint32_t b0, b1, b2, b3;
                ldsm4t(b0, b1, b2, b3, kAddrBase + (4 * u + q2) * 16);
                sc[q2][0] = sc[q2][1] = sc[q2][2] = sc[q2][3] = 0.f;
                mma16816(sc[q2], qa[0][0], qa[0][1], qa[0][2], qa[0][3], b0, b1);
                mma16816(sc[q2], qa[1][0], qa[1][1], qa[1][2], qa[1][3], b2, b3);
            }
#pragma unroll
            for (int q2 = 0; q2 < 4; ++q2) {
                uint32_t x01 = packbf(sc[q2][0], sc[q2][1]);
                uint32_t x23 = packbf(sc[q2][2], sc[q2][3]);
                uint32_t p01 = bffma2(x01, C6, C2);     // x/6 + 1/2
                uint32_t p23 = bffma2(x23, C6, C2);
                p01 = bffma2(x01, p01, C1);             // x^2/6 + x/2 + 1
                p23 = bffma2(x23, p23, C1);
                uint32_t d01 = bffma2(x01, p01, 0u);    // dev = x * p
                uint32_t d23 = bffma2(x23, p23, 0u);
                s01 = bffma2(d01, C1, s01);             // row-sum += dev
                s23 = bffma2(d23, C1, s23);
                pl[q2] = d01;
                ph[q2] = d23;
            }
#pragma unroll
            for (int dn = 0; dn < 4; ++dn) {
                uint32_t b0, b1, b2, b3;
                ldsm4(b0, b1, b2, b3,
                      uVs + (dn * 8 + lr) * KS_STRIDE + (4 * u + lq) * 16);
                mma16816(oc[dn], pl[0], ph[0], pl[1], ph[1], b0, b1);
                mma16816(oc[dn], pl[2], ph[2], pl[3], ph[3], b2, b3);
            }
        }
    }

    // ---- in-kernel sumv: svs[d] = Wv[hh*32+d,:] . colsum[b,:] + NT*bv ----
    {
#pragma unroll
        for (int mi = 0; mi < 4; ++mi) {
            const int d = w * 4 + mi;
            const int m = hh * DH + d;
            float s = 0.f;
#pragma unroll
            for (int c4 = 0; c4 < 4; ++c4) {
                const int c = c4 * 32 + lane;
                s += Wv[m * 128 + c] * g_colsum[b * CC + c];
            }
#pragma unroll
            for (int o = 16; o > 0; o >>= 1) s += __shfl_xor_sync(0xffffffffu, s, o);
            if (lane == 0) svs[d] = s + (float)NT * bv[m];
        }
    }
    __syncthreads();

    // ---- epilogue: unpack packed row-sums, quad-reduce, rank-1 + denom ----
    float dev_lo = __uint_as_float(s01 << 16) +
                   __uint_as_float(s01 & 0xffff0000u);
    float dev_hi = __uint_as_float(s23 << 16) +
                   __uint_as_float(s23 & 0xffff0000u);
    dev_lo += __shfl_xor_sync(0xffffffffu, dev_lo, 1);
    dev_lo += __shfl_xor_sync(0xffffffffu, dev_lo, 2);
    dev_hi += __shfl_xor_sync(0xffffffffu, dev_hi, 1);
    dev_hi += __shfl_xor_sync(0xffffffffu, dev_hi, 2);

    const int tq = lane & 3, g = lane >> 2;
    const int i_lo = i0 + w * 16 + g;
    const int i_hi = i_lo + 8;
    const float inv_lo = 1.0f / (4096.0f + dev_lo);
    const float inv_hi = 1.0f / (4096.0f + dev_hi);
    float* att = g_att + (size_t)cb * NT;

#pragma unroll
    for (int dn = 0; dn < 4; ++dn) {
        const int d0 = dn * 8 + 2 * tq;
        const float s0 = svs[d0], s1 = svs[d0 + 1];
        att[(size_t)d0 * NT + i_lo]       = (oc[dn][0] + s0) * inv_lo;
        att[(size_t)(d0 + 1) * NT + i_lo] = (oc[dn][1] + s1) * inv_lo;
        att[(size_t)d0 * NT + i_hi]       = (oc[dn][2] + s0) * inv_hi;
        att[(size_t)(d0 + 1) * NT + i_hi] = (oc[dn][3] + s1) * inv_hi;
    }
}

// =============================================================================
// Launch  (attn is the 4th launch -> ncu captures it)
// =============================================================================
extern "C" void kernel_launch(void* const* d_in, const int* in_sizes, int n_in,
                              void* d_out, int out_size)
{
    (void)in_sizes; (void)n_in; (void)out_size;
    const float* x  = (const float*)d_in[0];
    const float* cx = (const float*)d_in[1];
    const float* Wq = (const float*)d_in[2];
    const float* bq = (const float*)d_in[3];
    const float* Wk = (const float*)d_in[4];
    const float* bk = (const float*)d_in[5];
    const float* Wv = (const float*)d_in[6];
    const float* bv = (const float*)d_in[7];
    const float* Wo = (const float*)d_in[8];
    const float* bo = (const float*)d_in[9];
    float* out = (float*)d_out;

    const int QKV_SMEM = 3 * 128 * PW_STRIDE;
    const int OUT_SMEM = 2 * 128 * PW_STRIDE + 2 * 128 * PB64_STRIDE;

    cudaFuncSetAttribute(proj_qkv_mma, cudaFuncAttributeMaxDynamicSharedMemorySize, QKV_SMEM);
    cudaFuncSetAttribute(proj_out_mma, cudaFuncAttributeMaxDynamicSharedMemorySize, OUT_SMEM);

    proj_qkv_mma<<<dim3(NT / 128, BB, 3), 256, QKV_SMEM>>>(x, cx, Wq, bq, Wk, bk, Wv, bv);
    colsum_kernel<<<dim3(BB * CC), 256>>>(cx);
    norm_kernel<<<dim3(BB * CC, 2), 256>>>();
    attn_mma_kernel<<<dim3(NT / 128, NH, BB), 256>>>(Wv, bv);
    proj_out_mma<<<dim3(NT / 64, BB), 256, OUT_SMEM>>>(Wo, bo, out);
}

// round 10
// speedup vs baseline: 1.3266x; 1.0017x over previous
#include <cuda_runtime.h>
#include <cuda_bf16.h>
#include <cstdint>
#include <math.h>

#define BB 2
#define CC 128
#define NH 4
#define DH 32
#define NT 4096
#define SCALE_F 10.0f

// ---------------- scratch (static device memory; no allocations) -------------
static __device__ float g_q[BB * CC * NT];            // fp32 q (pre-norm)
static __device__ float g_k[BB * CC * NT];            // fp32 k (pre-norm)
static __device__ __nv_bfloat16 g_qb[BB * CC * NT];   // bf16 normalized*SCALE q
static __device__ __nv_bfloat16 g_kb[BB * CC * NT];   // bf16 normalized k
static __device__ __nv_bfloat16 g_vb[BB * CC * NT];   // bf16 v
static __device__ float g_att[BB * CC * NT];
static __device__ float g_colsum[BB * CC];

// =============================================================================
// helpers
// =============================================================================
__device__ __forceinline__ uint32_t smem_u32(const void* p) {
    uint32_t a;
    asm("{ .reg .u64 t; cvta.to.shared.u64 t, %1; cvt.u32.u64 %0, t; }"
        : "=r"(a) : "l"(p));
    return a;
}

__device__ __forceinline__ uint32_t packbf(float a, float b) {
    uint32_t r;
    asm("cvt.rn.bf16x2.f32 %0, %2, %1;" : "=r"(r) : "f"(a), "f"(b));
    return r;  // lo = a, hi = b
}

// packed bf16x2 fma (non-volatile: scheduler may interleave with mma stream)
__device__ __forceinline__ uint32_t bffma2(uint32_t a, uint32_t b, uint32_t c) {
    uint32_t d;
    asm("fma.rn.bf16x2 %0, %1, %2, %3;" : "=r"(d) : "r"(a), "r"(b), "r"(c));
    return d;
}

__device__ __forceinline__ void ldsm4(uint32_t& r0, uint32_t& r1, uint32_t& r2,
                                      uint32_t& r3, uint32_t addr) {
    asm volatile("ldmatrix.sync.aligned.m8n8.x4.shared.b16 {%0,%1,%2,%3}, [%4];"
                 : "=r"(r0), "=r"(r1), "=r"(r2), "=r"(r3) : "r"(addr));
}

__device__ __forceinline__ void ldsm4t(uint32_t& r0, uint32_t& r1, uint32_t& r2,
                                       uint32_t& r3, uint32_t addr) {
    asm volatile("ldmatrix.sync.aligned.m8n8.x4.trans.shared.b16 {%0,%1,%2,%3}, [%4];"
                 : "=r"(r0), "=r"(r1), "=r"(r2), "=r"(r3) : "r"(addr));
}

__device__ __forceinline__ void mma16816(float* c, uint32_t a0, uint32_t a1,
                                         uint32_t a2, uint32_t a3,
                                         uint32_t b0, uint32_t b1) {
    asm volatile(
        "mma.sync.aligned.m16n8k16.row.col.f32.bf16.bf16.f32 "
        "{%0,%1,%2,%3}, {%4,%5,%6,%7}, {%8,%9}, {%0,%1,%2,%3};"
        : "+f"(c[0]), "+f"(c[1]), "+f"(c[2]), "+f"(c[3])
        : "r"(a0), "r"(a1), "r"(a2), "r"(a3), "r"(b0), "r"(b1));
}

__device__ __forceinline__ void cp16(uint32_t dst, const void* src) {
    asm volatile("cp.async.cg.shared.global [%0], [%1], 16;"
                 :: "r"(dst), "l"(src) : "memory");
}

// =============================================================================
// Tensor-core projection GEMMs (hi/lo bf16 split of fp32 operands) — unchanged.
// =============================================================================
#define PW_STRIDE 272
#define PB64_STRIDE 144

__global__ void __launch_bounds__(256, 2)
proj_qkv_mma(const float* __restrict__ x, const float* __restrict__ cx,
             const float* __restrict__ Wq, const float* __restrict__ bq,
             const float* __restrict__ Wk, const float* __restrict__ bk,
             const float* __restrict__ Wv, const float* __restrict__ bv)
{
    extern __shared__ unsigned char psm[];
    unsigned char* Wh = psm;
    unsigned char* Bh = psm + 128 * PW_STRIDE;
    unsigned char* Bl = Bh + 128 * PW_STRIDE;

    const int tid = threadIdx.x, w = tid >> 5, lane = tid & 31;
    const int n0 = blockIdx.x * 128, b = blockIdx.y, wh = blockIdx.z;
    const float *W, *bias, *inb;
    if (wh == 0)      { W = Wq; bias = bq; inb = x  + (size_t)b * CC * NT; }
    else if (wh == 1) { W = Wk; bias = bk; inb = cx + (size_t)b * CC * NT; }
    else              { W = Wv; bias = bv; inb = cx + (size_t)b * CC * NT; }

#pragma unroll
    for (int it = 0; it < 16; ++it) {
        const int idx = tid + it * 256;
        const int m = idx >> 5, c4 = idx & 31;
        float4 ww = *(const float4*)(W + m * 128 + c4 * 4);
        *(uint2*)(Wh + m * PW_STRIDE + c4 * 8) =
            make_uint2(packbf(ww.x, ww.y), packbf(ww.z, ww.w));
    }
#pragma unroll
    for (int it = 0; it < 16; ++it) {
        const int idx = tid + it * 256;
        const int c = idx >> 5, c4 = idx & 31;
        float4 v = *(const float4*)(inb + (size_t)c * NT + n0 + c4 * 4);
        uint32_t h0 = packbf(v.x, v.y), h1 = packbf(v.z, v.w);
        float l0 = v.x - __uint_as_float(h0 << 16);
        float l1 = v.y - __uint_as_float(h0 & 0xffff0000u);
        float l2 = v.z - __uint_as_float(h1 << 16);
        float l3 = v.w - __uint_as_float(h1 & 0xffff0000u);
        *(uint2*)(Bh + c * PW_STRIDE + c4 * 8) = make_uint2(h0, h1);
        *(uint2*)(Bl + c * PW_STRIDE + c4 * 8) =
            make_uint2(packbf(l0, l1), packbf(l2, l3));
    }
    __syncthreads();

    const uint32_t uWh = smem_u32(Wh), uBh = smem_u32(Bh), uBl = smem_u32(Bl);
    uint32_t A[8][4];
    {
        const int q = lane >> 3, r = lane & 7;
#pragma unroll
        for (int ks = 0; ks < 8; ++ks)
            ldsm4(A[ks][0], A[ks][1], A[ks][2], A[ks][3],
                  uWh + (w * 16 + (q & 1) * 8 + r) * PW_STRIDE
                      + (ks * 16 + (q >> 1) * 8) * 2);
    }
    const int g = lane >> 2, tq = lane & 3;
    const int m0 = w * 16 + g, m1 = m0 + 8;
    const float bb0 = bias[m0], bb1 = bias[m1];

#pragma unroll
    for (int nh = 0; nh < 2; ++nh) {
        float acc[8][4];
#pragma unroll
        for (int nt = 0; nt < 8; ++nt)
            acc[nt][0] = acc[nt][1] = acc[nt][2] = acc[nt][3] = 0.f;

#pragma unroll
        for (int nt = 0; nt < 8; ++nt) {
            const uint32_t colb = nh * 128 + nt * 16;
#pragma unroll
            for (int cb = 0; cb < 4; ++cb) {
                uint32_t b0, b1, b2, b3;
                ldsm4t(b0, b1, b2, b3, uBh + (cb * 32 + lane) * PW_STRIDE + colb);
                mma16816(acc[nt], A[2*cb][0], A[2*cb][1], A[2*cb][2], A[2*cb][3], b0, b1);
                mma16816(acc[nt], A[2*cb+1][0], A[2*cb+1][1], A[2*cb+1][2], A[2*cb+1][3], b2, b3);
            }
#pragma unroll
            for (int cb = 0; cb < 4; ++cb) {
                uint32_t b0, b1, b2, b3;
                ldsm4t(b0, b1, b2, b3, uBl + (cb * 32 + lane) * PW_STRIDE + colb);
                mma16816(acc[nt], A[2*cb][0], A[2*cb][1], A[2*cb][2], A[2*cb][3], b0, b1);
                mma16816(acc[nt], A[2*cb+1][0], A[2*cb+1][1], A[2*cb+1][2], A[2*cb+1][3], b2, b3);
            }
        }
        if (wh == 2) {
            __nv_bfloat16* vb = g_vb + (size_t)(b * CC) * NT;
#pragma unroll
            for (int nt = 0; nt < 8; ++nt) {
                const int n = n0 + nh * 64 + nt * 8 + tq * 2;
                *(uint32_t*)(vb + (size_t)m0 * NT + n) = packbf(acc[nt][0] + bb0, acc[nt][1] + bb0);
                *(uint32_t*)(vb + (size_t)m1 * NT + n) = packbf(acc[nt][2] + bb1, acc[nt][3] + bb1);
            }
        } else {
            float* og = (wh == 0 ? g_q : g_k) + (size_t)(b * CC) * NT;
#pragma unroll
            for (int nt = 0; nt < 8; ++nt) {
                const int n = n0 + nh * 64 + nt * 8 + tq * 2;
                *(float2*)(og + (size_t)m0 * NT + n) = make_float2(acc[nt][0] + bb0, acc[nt][1] + bb0);
                *(float2*)(og + (size_t)m1 * NT + n) = make_float2(acc[nt][2] + bb1, acc[nt][3] + bb1);
            }
        }
    }
}

__global__ void __launch_bounds__(256, 2)
proj_out_mma(const float* __restrict__ Wo, const float* __restrict__ bo,
             float* __restrict__ out)
{
    extern __shared__ unsigned char psm[];
    unsigned char* Wh = psm;
    unsigned char* Wl = psm + 128 * PW_STRIDE;
    unsigned char* Bh = Wl + 128 * PW_STRIDE;
    unsigned char* Bl = Bh + 128 * PB64_STRIDE;

    const int tid = threadIdx.x, w = tid >> 5, lane = tid & 31;
    const int n0 = blockIdx.x * 64, b = blockIdx.y;
    const float* inb = g_att + (size_t)b * CC * NT;

#pragma unroll
    for (int it = 0; it < 16; ++it) {
        const int idx = tid + it * 256;
        const int m = idx >> 5, c4 = idx & 31;
        float4 ww = *(const float4*)(Wo + m * 128 + c4 * 4);
        uint32_t h0 = packbf(ww.x, ww.y), h1 = packbf(ww.z, ww.w);
        float l0 = ww.x - __uint_as_float(h0 << 16);
        float l1 = ww.y - __uint_as_float(h0 & 0xffff0000u);
        float l2 = ww.z - __uint_as_float(h1 << 16);
        float l3 = ww.w - __uint_as_float(h1 & 0xffff0000u);
        *(uint2*)(Wh + m * PW_STRIDE + c4 * 8) = make_uint2(h0, h1);
        *(uint2*)(Wl + m * PW_STRIDE + c4 * 8) =
            make_uint2(packbf(l0, l1), packbf(l2, l3));
    }
#pragma unroll
    for (int it = 0; it < 8; ++it) {
        const int idx = tid + it * 256;
        const int c = idx >> 4, c4 = idx & 15;
        float4 v = *(const float4*)(inb + (size_t)c * NT + n0 + c4 * 4);
        uint32_t h0 = packbf(v.x, v.y), h1 = packbf(v.z, v.w);
        float l0 = v.x - __uint_as_float(h0 << 16);
        float l1 = v.y - __uint_as_float(h0 & 0xffff0000u);
        float l2 = v.z - __uint_as_float(h1 << 16);
        float l3 = v.w - __uint_as_float(h1 & 0xffff0000u);
        *(uint2*)(Bh + c * PB64_STRIDE + c4 * 8) = make_uint2(h0, h1);
        *(uint2*)(Bl + c * PB64_STRIDE + c4 * 8) =
            make_uint2(packbf(l0, l1), packbf(l2, l3));
    }
    __syncthreads();

    const uint32_t uWh = smem_u32(Wh), uWl = smem_u32(Wl);
    const uint32_t uBh = smem_u32(Bh), uBl = smem_u32(Bl);
    uint32_t Ah[8][4], Al[8][4];
    {
        const int q = lane >> 3, r = lane & 7;
#pragma unroll
        for (int ks = 0; ks < 8; ++ks) {
            const uint32_t off = (w * 16 + (q & 1) * 8 + r) * PW_STRIDE
                               + (ks * 16 + (q >> 1) * 8) * 2;
            ldsm4(Ah[ks][0], Ah[ks][1], Ah[ks][2], Ah[ks][3], uWh + off);
            ldsm4(Al[ks][0], Al[ks][1], Al[ks][2], Al[ks][3], uWl + off);
        }
    }
    float acc[8][4];
#pragma unroll
    for (int nt = 0; nt < 8; ++nt)
        acc[nt][0] = acc[nt][1] = acc[nt][2] = acc[nt][3] = 0.f;

#pragma unroll
    for (int nt = 0; nt < 8; ++nt) {
        const uint32_t colb = nt * 16;
#pragma unroll
        for (int cb = 0; cb < 4; ++cb) {
            uint32_t b0, b1, b2, b3;
            ldsm4t(b0, b1, b2, b3, uBh + (cb * 32 + lane) * PB64_STRIDE + colb);
            mma16816(acc[nt], Ah[2*cb][0], Ah[2*cb][1], Ah[2*cb][2], Ah[2*cb][3], b0, b1);
            mma16816(acc[nt], Ah[2*cb+1][0], Ah[2*cb+1][1], Ah[2*cb+1][2], Ah[2*cb+1][3], b2, b3);
        }
#pragma unroll
        for (int cb = 0; cb < 4; ++cb) {
            uint32_t b0, b1, b2, b3;
            ldsm4t(b0, b1, b2, b3, uBl + (cb * 32 + lane) * PB64_STRIDE + colb);
            mma16816(acc[nt], Ah[2*cb][0], Ah[2*cb][1], Ah[2*cb][2], Ah[2*cb][3], b0, b1);
            mma16816(acc[nt], Ah[2*cb+1][0], Ah[2*cb+1][1], Ah[2*cb+1][2], Ah[2*cb+1][3], b2, b3);
        }
#pragma unroll
        for (int cb = 0; cb < 4; ++cb) {
            uint32_t b0, b1, b2, b3;
            ldsm4t(b0, b1, b2, b3, uBh + (cb * 32 + lane) * PB64_STRIDE + colb);
            mma16816(acc[nt], Al[2*cb][0], Al[2*cb][1], Al[2*cb][2], Al[2*cb][3], b0, b1);
            mma16816(acc[nt], Al[2*cb+1][0], Al[2*cb+1][1], Al[2*cb+1][2], Al[2*cb+1][3], b2, b3);
        }
    }
    const int g = lane >> 2, tq = lane & 3;
    const int m0 = w * 16 + g, m1 = m0 + 8;
    const float bb0 = bo[m0], bb1 = bo[m1];
    float* og = out + (size_t)(b * CC) * NT;
#pragma unroll
    for (int nt = 0; nt < 8; ++nt) {
        const int n = n0 + nt * 8 + tq * 2;
        *(float2*)(og + (size_t)m0 * NT + n) = make_float2(acc[nt][0] + bb0, acc[nt][1] + bb0);
        *(float2*)(og + (size_t)m1 * NT + n) = make_float2(acc[nt][2] + bb1, acc[nt][3] + bb1);
    }
}

// =============================================================================
// L2 normalize q,k rows (spatial axis); single pass — values stay in registers.
// =============================================================================
__global__ void __launch_bounds__(256, 1) norm_kernel()
{
    const int row = blockIdx.x;
    const float* p = (blockIdx.y == 0 ? g_q : g_k) + (size_t)row * NT;
    __nv_bfloat16* ob = (blockIdx.y == 0 ? g_qb : g_kb) + (size_t)row * NT;
    const int tid = threadIdx.x;

    float4 v[4];
    float s = 0.f;
#pragma unroll
    for (int it = 0; it < 4; ++it) {
        v[it] = ((const float4*)p)[tid + it * 256];
        s += v[it].x * v[it].x + v[it].y * v[it].y +
             v[it].z * v[it].z + v[it].w * v[it].w;
    }
#pragma unroll
    for (int o = 16; o > 0; o >>= 1) s += __shfl_xor_sync(0xffffffffu, s, o);

    __shared__ float red[8];
    if ((tid & 31) == 0) red[tid >> 5] = s;
    __syncthreads();
    if (tid < 32) {
        float vv = (tid < 8) ? red[tid] : 0.f;
#pragma unroll
        for (int o = 4; o > 0; o >>= 1) vv += __shfl_xor_sync(0xffffffffu, vv, o);
        if (tid == 0) red[0] = vv;
    }
    __syncthreads();
    const float tot = red[0];
    const float scl = (blockIdx.y == 0 ? SCALE_F : 1.0f) / fmaxf(sqrtf(tot), 1e-12f);

#pragma unroll
    for (int it = 0; it < 4; ++it) {
        ((uint2*)ob)[tid + it * 256] =
            make_uint2(packbf(v[it].x * scl, v[it].y * scl),
                       packbf(v[it].z * scl, v[it].w * scl));
    }
}

// colsum[b][c] = sum_n cond_x[b][c][n]
__global__ void __launch_bounds__(256, 1) colsum_kernel(const float* __restrict__ cx)
{
    const int row = blockIdx.x;
    const float* p = cx + (size_t)row * NT;
    const int tid = threadIdx.x;
    float s = 0.f;
#pragma unroll
    for (int it = 0; it < 4; ++it) {
        float4 v = ((const float4*)p)[tid + it * 256];
        s += v.x + v.y + v.z + v.w;
    }
#pragma unroll
    for (int o = 16; o > 0; o >>= 1) s += __shfl_xor_sync(0xffffffffu, s, o);
    __shared__ float red[8];
    if ((tid & 31) == 0) red[tid >> 5] = s;
    __syncthreads();
    if (tid == 0)
        g_colsum[row] = red[0] + red[1] + red[2] + red[3] +
                        red[4] + red[5] + red[6] + red[7];
}

// =============================================================================
// mma.sync flash attention; softmax arithmetic in packed bf16x2.
// dev = expm1(s) computed as bf16x2 poly: d = x*(1 + x*(1/2 + x/6)); row sums
// accumulated as bf16x2 (error << 1e-5 of denominator).
// =============================================================================
#define QS_STRIDE 80
#define KS_STRIDE 272

__global__ void __launch_bounds__(256, 2)
attn_mma_kernel(const float* __restrict__ Wv, const float* __restrict__ bv)
{
    __shared__ __align__(16) unsigned char Qs[128 * QS_STRIDE];
    __shared__ __align__(16) unsigned char Kb[2][32 * KS_STRIDE];
    __shared__ __align__(16) unsigned char Vb[2][32 * KS_STRIDE];
    __shared__ float svs[DH];

    const int tid  = threadIdx.x;
    const int w    = tid >> 5;
    const int lane = tid & 31;
    const int i0 = blockIdx.x * 128;
    const int hh = blockIdx.y;
    const int b  = blockIdx.z;
    const int cb = b * CC + hh * DH;
    const __nv_bfloat16* qg = g_qb + (size_t)cb * NT;
    const __nv_bfloat16* kg = g_kb + (size_t)cb * NT;
    const __nv_bfloat16* vg = g_vb + (size_t)cb * NT;

    const uint32_t uQs = smem_u32(Qs);
    const uint32_t uK0 = smem_u32(Kb[0]), uK1 = smem_u32(Kb[1]);
    const uint32_t uV0 = smem_u32(Vb[0]), uV1 = smem_u32(Vb[1]);

    // bf16x2 poly constants
    const uint32_t C6 = packbf(1.0f / 6.0f, 1.0f / 6.0f);
    const uint32_t C2 = packbf(0.5f, 0.5f);
    const uint32_t C1 = packbf(1.0f, 1.0f);

    {
        const int i  = tid & 127;
        const int dh = (tid >> 7) * 16;
#pragma unroll
        for (int v = 0; v < 8; ++v) {
            uint32_t lo = *(const uint16_t*)(qg + (size_t)(dh + 2 * v) * NT + i0 + i);
            uint32_t hi = *(const uint16_t*)(qg + (size_t)(dh + 2 * v + 1) * NT + i0 + i);
            *(uint32_t*)(Qs + i * QS_STRIDE + (dh + 2 * v) * 2) = lo | (hi << 16);
        }
    }
    {
#pragma unroll
        for (int r = 0; r < 2; ++r) {
            const int idx = tid + r * 256;
            const int d = idx >> 4, ch = idx & 15;
            cp16(uK0 + d * KS_STRIDE + ch * 16, kg + (size_t)d * NT + ch * 8);
            cp16(uV0 + d * KS_STRIDE + ch * 16, vg + (size_t)d * NT + ch * 8);
        }
        asm volatile("cp.async.commit_group;" ::: "memory");
    }
    __syncthreads();

    uint32_t qa[2][4];
    {
        const int q = lane >> 3, r = lane & 7;
#pragma unroll
        for (int ks = 0; ks < 2; ++ks) {
            uint32_t addr = uQs + (w * 16 + (q & 1) * 8 + r) * QS_STRIDE
                                + (ks * 16 + (q >> 1) * 8) * 2;
            ldsm4(qa[ks][0], qa[ks][1], qa[ks][2], qa[ks][3], addr);
        }
    }

    float oc[4][4];
#pragma unroll
    for (int dn = 0; dn < 4; ++dn)
#pragma unroll
        for (int u = 0; u < 4; ++u) oc[dn][u] = 0.f;
    uint32_t s01 = 0, s23 = 0;   // packed bf16x2 row-sum accumulators

    const int lq = lane >> 3, lr = lane & 7;

    for (int t = 0; t < 32; ++t) {
        asm volatile("cp.async.wait_group 0;" ::: "memory");
        __syncthreads();

        if (t < 31) {
            const uint32_t uKn = ((t + 1) & 1) ? uK1 : uK0;
            const uint32_t uVn = ((t + 1) & 1) ? uV1 : uV0;
            const int j0n = (t + 1) * 128;
#pragma unroll
            for (int r = 0; r < 2; ++r) {
                const int idx = tid + r * 256;
                const int d = idx >> 4, ch = idx & 15;
                cp16(uKn + d * KS_STRIDE + ch * 16, kg + (size_t)d * NT + j0n + ch * 8);
                cp16(uVn + d * KS_STRIDE + ch * 16, vg + (size_t)d * NT + j0n + ch * 8);
            }
            asm volatile("cp.async.commit_group;" ::: "memory");
        }

        const uint32_t uKs = (t & 1) ? uK1 : uK0;
        const uint32_t uVs = (t & 1) ? uV1 : uV0;
        const uint32_t kAddrBase = uKs + lane * KS_STRIDE;

#pragma unroll
        for (int u = 0; u < 4; ++u) {
            float sc[4][4];
            uint32_t pl[4], ph[4];
#pragma unroll
            for (int q2 = 0; q2 < 4; ++q2) {
                uint32_t b0, b1, b2, b3;
                ldsm4t(b0, b1, b2, b3, kAddrBase + (4 * u + q2) * 16);
                sc[q2][0] = sc[q2][1] = sc[q2][2] = sc[q2][3] = 0.f;
                mma16816(sc[q2], qa[0][0], qa[0][1], qa[0][2], qa[0][3], b0, b1);
                mma16816(sc[q2], qa[1][0], qa[1][1], qa[1][2], qa[1][3], b2, b3);
            }
#pragma unroll
            for (int q2 = 0; q2 < 4; ++q2) {
                uint32_t x01 = packbf(sc[q2][0], sc[q2][1]);
                uint32_t x23 = packbf(sc[q2][2], sc[q2][3]);
                uint32_t p01 = bffma2(x01, C6, C2);     // x/6 + 1/2
                uint32_t p23 = bffma2(x23, C6, C2);
                p01 = bffma2(x01, p01, C1);             // x^2/6 + x/2 + 1
                p23 = bffma2(x23, p23, C1);
                uint32_t d01 = bffma2(x01, p01, 0u);    // dev = x * p
                uint32_t d23 = bffma2(x23, p23, 0u);
                s01 = bffma2(d01, C1, s01);             // row-sum += dev
                s23 = bffma2(d23, C1, s23);
                pl[q2] = d01;
                ph[q2] = d23;
            }
#pragma unroll
            for (int dn = 0; dn < 4; ++dn) {
                uint32_t b0, b1, b2, b3;
                ldsm4(b0, b1, b2, b3,
                      uVs + (dn * 8 + lr) * KS_STRIDE + (4 * u + lq) * 16);
                mma16816(oc[dn], pl[0], ph[0], pl[1], ph[1], b0, b1);
                mma16816(oc[dn], pl[2], ph[2], pl[3], ph[3], b2, b3);
            }
        }
    }

    // ---- in-kernel sumv: svs[d] = Wv[hh*32+d,:] . colsum[b,:] + NT*bv ----
    {
#pragma unroll
        for (int mi = 0; mi < 4; ++mi) {
            const int d = w * 4 + mi;
            const int m = hh * DH + d;
            float s = 0.f;
#pragma unroll
            for (int c4 = 0; c4 < 4; ++c4) {
                const int c = c4 * 32 + lane;
                s += Wv[m * 128 + c] * g_colsum[b * CC + c];
            }
#pragma unroll
            for (int o = 16; o > 0; o >>= 1) s += __shfl_xor_sync(0xffffffffu, s, o);
            if (lane == 0) svs[d] = s + (float)NT * bv[m];
        }
    }
    __syncthreads();

    // ---- epilogue: unpack packed row-sums, quad-reduce, rank-1 + denom ----
    float dev_lo = __uint_as_float(s01 << 16) +
                   __uint_as_float(s01 & 0xffff0000u);
    float dev_hi = __uint_as_float(s23 << 16) +
                   __uint_as_float(s23 & 0xffff0000u);
    dev_lo += __shfl_xor_sync(0xffffffffu, dev_lo, 1);
    dev_lo += __shfl_xor_sync(0xffffffffu, dev_lo, 2);
    dev_hi += __shfl_xor_sync(0xffffffffu, dev_hi, 1);
    dev_hi += __shfl_xor_sync(0xffffffffu, dev_hi, 2);

    const int tq = lane & 3, g = lane >> 2;
    const int i_lo = i0 + w * 16 + g;
    const int i_hi = i_lo + 8;
    const float inv_lo = 1.0f / (4096.0f + dev_lo);
    const float inv_hi = 1.0f / (4096.0f + dev_hi);
    float* att = g_att + (size_t)cb * NT;

#pragma unroll
    for (int dn = 0; dn < 4; ++dn) {
        const int d0 = dn * 8 + 2 * tq;
        const float s0 = svs[d0], s1 = svs[d0 + 1];
        att[(size_t)d0 * NT + i_lo]       = (oc[dn][0] + s0) * inv_lo;
        att[(size_t)(d0 + 1) * NT + i_lo] = (oc[dn][1] + s1) * inv_lo;
        att[(size_t)d0 * NT + i_hi]       = (oc[dn][2] + s0) * inv_hi;
        att[(size_t)(d0 + 1) * NT + i_hi] = (oc[dn][3] + s1) * inv_hi;
    }
}

// =============================================================================
// Launch  (attn is the 4th launch -> ncu captures it)
// =============================================================================
extern "C" void kernel_launch(void* const* d_in, const int* in_sizes, int n_in,
                              void* d_out, int out_size)
{
    (void)in_sizes; (void)n_in; (void)out_size;
    const float* x  = (const float*)d_in[0];
    const float* cx = (const float*)d_in[1];
    const float* Wq = (const float*)d_in[2];
    const float* bq = (const float*)d_in[3];
    const float* Wk = (const float*)d_in[4];
    const float* bk = (const float*)d_in[5];
    const float* Wv = (const float*)d_in[6];
    const float* bv = (const float*)d_in[7];
    const float* Wo = (const float*)d_in[8];
    const float* bo = (const float*)d_in[9];
    float* out = (float*)d_out;

    const int QKV_SMEM = 3 * 128 * PW_STRIDE;
    const int OUT_SMEM = 2 * 128 * PW_STRIDE + 2 * 128 * PB64_STRIDE;

    cudaFuncSetAttribute(proj_qkv_mma, cudaFuncAttributeMaxDynamicSharedMemorySize, QKV_SMEM);
    cudaFuncSetAttribute(proj_out_mma, cudaFuncAttributeMaxDynamicSharedMemorySize, OUT_SMEM);

    proj_qkv_mma<<<dim3(NT / 128, BB, 3), 256, QKV_SMEM>>>(x, cx, Wq, bq, Wk, bk, Wv, bv);
    colsum_kernel<<<dim3(BB * CC), 256>>>(cx);
    norm_kernel<<<dim3(BB * CC, 2), 256>>>();
    attn_mma_kernel<<<dim3(NT / 128, NH, BB), 256>>>(Wv, bv);
    proj_out_mma<<<dim3(NT / 64, BB), 256, OUT_SMEM>>>(Wo, bo, out);
}

// round 11
// speedup vs baseline: 1.3572x; 1.0231x over previous
#include <cuda_runtime.h>
#include <cuda_bf16.h>
#include <cstdint>
#include <math.h>

#define BB 2
#define CC 128
#define NH 4
#define DH 32
#define NT 4096
#define SCALE_F 10.0f

#define NF 640        // padded features (560 real)
#define NFB 5
#define NE 40         // padded output cols (33 used)
#define TS 272        // tile row stride bytes (128 bf16 + pad)
#define GSS 1296      // G smem row stride bytes (640 bf16 + pad)
#define JSPLIT 4

static __device__ float g_q[BB * CC * NT];
static __device__ float g_k[BB * CC * NT];
static __device__ __nv_bfloat16 g_qb[BB * CC * NT];
static __device__ __nv_bfloat16 g_kb[BB * CC * NT];
static __device__ __nv_bfloat16 g_vb[BB * CC * NT];
static __device__ float g_att[BB * CC * NT];
static __device__ float g_colsum[BB * CC];
static __device__ float g_G2[8 * JSPLIT * NE * NF];
static __device__ __nv_bfloat16 g_Gb[8 * NE * NF];

// ---------------------------------------------------------------- helpers ----
__device__ __forceinline__ uint32_t smem_u32(const void* p) {
    uint32_t a;
    asm("{ .reg .u64 t; cvta.to.shared.u64 t, %1; cvt.u32.u64 %0, t; }"
        : "=r"(a) : "l"(p));
    return a;
}
__device__ __forceinline__ uint32_t packbf(float a, float b) {
    uint32_t r;
    asm("cvt.rn.bf16x2.f32 %0, %2, %1;" : "=r"(r) : "f"(a), "f"(b));
    return r;
}
__device__ __forceinline__ uint32_t bffma2(uint32_t a, uint32_t b, uint32_t c) {
    uint32_t d;
    asm("fma.rn.bf16x2 %0, %1, %2, %3;" : "=r"(d) : "r"(a), "r"(b), "r"(c));
    return d;
}
__device__ __forceinline__ void ldsm4(uint32_t& r0, uint32_t& r1, uint32_t& r2,
                                      uint32_t& r3, uint32_t addr) {
    asm volatile("ldmatrix.sync.aligned.m8n8.x4.shared.b16 {%0,%1,%2,%3}, [%4];"
                 : "=r"(r0), "=r"(r1), "=r"(r2), "=r"(r3) : "r"(addr));
}
__device__ __forceinline__ void ldsm4t(uint32_t& r0, uint32_t& r1, uint32_t& r2,
                                       uint32_t& r3, uint32_t addr) {
    asm volatile("ldmatrix.sync.aligned.m8n8.x4.trans.shared.b16 {%0,%1,%2,%3}, [%4];"
                 : "=r"(r0), "=r"(r1), "=r"(r2), "=r"(r3) : "r"(addr));
}
__device__ __forceinline__ void mma16816(float* c, uint32_t a0, uint32_t a1,
                                         uint32_t a2, uint32_t a3,
                                         uint32_t b0, uint32_t b1) {
    asm volatile(
        "mma.sync.aligned.m16n8k16.row.col.f32.bf16.bf16.f32 "
        "{%0,%1,%2,%3}, {%4,%5,%6,%7}, {%8,%9}, {%0,%1,%2,%3};"
        : "+f"(c[0]), "+f"(c[1]), "+f"(c[2]), "+f"(c[3])
        : "r"(a0), "r"(a1), "r"(a2), "r"(a3), "r"(b0), "r"(b1));
}
__device__ __forceinline__ void cp16(uint32_t dst, const void* src) {
    asm volatile("cp.async.cg.shared.global [%0], [%1], 16;"
                 :: "r"(dst), "l"(src) : "memory");
}

// feature LUT: f -> a | b<<8 | wsel<<16 (rows 32=ones, 33=zeros in tiles)
__device__ __forceinline__ void build_lut(uint32_t* lut, int tid) {
    for (int f = tid; f < NF; f += 256) {
        uint32_t a, b, ws;
        if (f < 32) { a = f; b = 32; ws = 0; }
        else if (f < 560) {
            int p = f - 32;
            int aa = 0;
            while (p >= 32 - aa) { p -= 32 - aa; ++aa; }
            a = aa; b = aa + p; ws = (a == b) ? 1u : 0u;
        } else { a = 33; b = 33; ws = 2; }
        lut[f] = a | (b << 8) | (ws << 16);
    }
}

// ============================= projections (unchanged, proven) ===============
#define PW_STRIDE 272
#define PB64_STRIDE 144

__global__ void __launch_bounds__(256, 2)
proj_qkv_mma(const float* __restrict__ x, const float* __restrict__ cx,
             const float* __restrict__ Wq, const float* __restrict__ bq,
             const float* __restrict__ Wk, const float* __restrict__ bk,
             const float* __restrict__ Wv, const float* __restrict__ bv)
{
    extern __shared__ unsigned char psm[];
    unsigned char* Wh = psm;
    unsigned char* Bh = psm + 128 * PW_STRIDE;
    unsigned char* Bl = Bh + 128 * PW_STRIDE;

    const int tid = threadIdx.x, w = tid >> 5, lane = tid & 31;
    const int n0 = blockIdx.x * 128, b = blockIdx.y, wh = blockIdx.z;
    const float *W, *bias, *inb;
    if (wh == 0)      { W = Wq; bias = bq; inb = x  + (size_t)b * CC * NT; }
    else if (wh == 1) { W = Wk; bias = bk; inb = cx + (size_t)b * CC * NT; }
    else              { W = Wv; bias = bv; inb = cx + (size_t)b * CC * NT; }

#pragma unroll
    for (int it = 0; it < 16; ++it) {
        const int idx = tid + it * 256;
        const int m = idx >> 5, c4 = idx & 31;
        float4 ww = *(const float4*)(W + m * 128 + c4 * 4);
        *(uint2*)(Wh + m * PW_STRIDE + c4 * 8) =
            make_uint2(packbf(ww.x, ww.y), packbf(ww.z, ww.w));
    }
#pragma unroll
    for (int it = 0; it < 16; ++it) {
        const int idx = tid + it * 256;
        const int c = idx >> 5, c4 = idx & 31;
        float4 v = *(const float4*)(inb + (size_t)c * NT + n0 + c4 * 4);
        uint32_t h0 = packbf(v.x, v.y), h1 = packbf(v.z, v.w);
        float l0 = v.x - __uint_as_float(h0 << 16);
        float l1 = v.y - __uint_as_float(h0 & 0xffff0000u);
        float l2 = v.z - __uint_as_float(h1 << 16);
        float l3 = v.w - __uint_as_float(h1 & 0xffff0000u);
        *(uint2*)(Bh + c * PW_STRIDE + c4 * 8) = make_uint2(h0, h1);
        *(uint2*)(Bl + c * PW_STRIDE + c4 * 8) =
            make_uint2(packbf(l0, l1), packbf(l2, l3));
    }
    __syncthreads();

    const uint32_t uWh = smem_u32(Wh), uBh = smem_u32(Bh), uBl = smem_u32(Bl);
    uint32_t A[8][4];
    {
        const int q = lane >> 3, r = lane & 7;
#pragma unroll
        for (int ks = 0; ks < 8; ++ks)
            ldsm4(A[ks][0], A[ks][1], A[ks][2], A[ks][3],
                  uWh + (w * 16 + (q & 1) * 8 + r) * PW_STRIDE
                      + (ks * 16 + (q >> 1) * 8) * 2);
    }
    const int g = lane >> 2, tq = lane & 3;
    const int m0 = w * 16 + g, m1 = m0 + 8;
    const float bb0 = bias[m0], bb1 = bias[m1];

#pragma unroll
    for (int nh = 0; nh < 2; ++nh) {
        float acc[8][4];
#pragma unroll
        for (int nt = 0; nt < 8; ++nt)
            acc[nt][0] = acc[nt][1] = acc[nt][2] = acc[nt][3] = 0.f;
#pragma unroll
        for (int nt = 0; nt < 8; ++nt) {
            const uint32_t colb = nh * 128 + nt * 16;
#pragma unroll
            for (int cb = 0; cb < 4; ++cb) {
                uint32_t b0, b1, b2, b3;
                ldsm4t(b0, b1, b2, b3, uBh + (cb * 32 + lane) * PW_STRIDE + colb);
                mma16816(acc[nt], A[2*cb][0], A[2*cb][1], A[2*cb][2], A[2*cb][3], b0, b1);
                mma16816(acc[nt], A[2*cb+1][0], A[2*cb+1][1], A[2*cb+1][2], A[2*cb+1][3], b2, b3);
            }
#pragma unroll
            for (int cb = 0; cb < 4; ++cb) {
                uint32_t b0, b1, b2, b3;
                ldsm4t(b0, b1, b2, b3, uBl + (cb * 32 + lane) * PW_STRIDE + colb);
                mma16816(acc[nt], A[2*cb][0], A[2*cb][1], A[2*cb][2], A[2*cb][3], b0, b1);
                mma16816(acc[nt], A[2*cb+1][0], A[2*cb+1][1], A[2*cb+1][2], A[2*cb+1][3], b2, b3);
            }
        }
        if (wh == 2) {
            __nv_bfloat16* vb = g_vb + (size_t)(b * CC) * NT;
#pragma unroll
            for (int nt = 0; nt < 8; ++nt) {
                const int n = n0 + nh * 64 + nt * 8 + tq * 2;
                *(uint32_t*)(vb + (size_t)m0 * NT + n) = packbf(acc[nt][0] + bb0, acc[nt][1] + bb0);
                *(uint32_t*)(vb + (size_t)m1 * NT + n) = packbf(acc[nt][2] + bb1, acc[nt][3] + bb1);
            }
        } else {
            float* og = (wh == 0 ? g_q : g_k) + (size_t)(b * CC) * NT;
#pragma unroll
            for (int nt = 0; nt < 8; ++nt) {
                const int n = n0 + nh * 64 + nt * 8 + tq * 2;
                *(float2*)(og + (size_t)m0 * NT + n) = make_float2(acc[nt][0] + bb0, acc[nt][1] + bb0);
                *(float2*)(og + (size_t)m1 * NT + n) = make_float2(acc[nt][2] + bb1, acc[nt][3] + bb1);
            }
        }
    }
}

__global__ void __launch_bounds__(256, 2)
proj_out_mma(const float* __restrict__ Wo, const float* __restrict__ bo,
             float* __restrict__ out)
{
    extern __shared__ unsigned char psm[];
    unsigned char* Wh = psm;
    unsigned char* Wl = psm + 128 * PW_STRIDE;
    unsigned char* Bh = Wl + 128 * PW_STRIDE;
    unsigned char* Bl = Bh + 128 * PB64_STRIDE;

    const int tid = threadIdx.x, w = tid >> 5, lane = tid & 31;
    const int n0 = blockIdx.x * 64, b = blockIdx.y;
    const float* inb = g_att + (size_t)b * CC * NT;

#pragma unroll
    for (int it = 0; it < 16; ++it) {
        const int idx = tid + it * 256;
        const int m = idx >> 5, c4 = idx & 31;
        float4 ww = *(const float4*)(Wo + m * 128 + c4 * 4);
        uint32_t h0 = packbf(ww.x, ww.y), h1 = packbf(ww.z, ww.w);
        float l0 = ww.x - __uint_as_float(h0 << 16);
        float l1 = ww.y - __uint_as_float(h0 & 0xffff0000u);
        float l2 = ww.z - __uint_as_float(h1 << 16);
        float l3 = ww.w - __uint_as_float(h1 & 0xffff0000u);
        *(uint2*)(Wh + m * PW_STRIDE + c4 * 8) = make_uint2(h0, h1);
        *(uint2*)(Wl + m * PW_STRIDE + c4 * 8) =
            make_uint2(packbf(l0, l1), packbf(l2, l3));
    }
#pragma unroll
    for (int it = 0; it < 8; ++it) {
        const int idx = tid + it * 256;
        const int c = idx >> 4, c4 = idx & 15;
        float4 v = *(const float4*)(inb + (size_t)c * NT + n0 + c4 * 4);
        uint32_t h0 = packbf(v.x, v.y), h1 = packbf(v.z, v.w);
        float l0 = v.x - __uint_as_float(h0 << 16);
        float l1 = v.y - __uint_as_float(h0 & 0xffff0000u);
        float l2 = v.z - __uint_as_float(h1 << 16);
        float l3 = v.w - __uint_as_float(h1 & 0xffff0000u);
        *(uint2*)(Bh + c * PB64_STRIDE + c4 * 8) = make_uint2(h0, h1);
        *(uint2*)(Bl + c * PB64_STRIDE + c4 * 8) =
            make_uint2(packbf(l0, l1), packbf(l2, l3));
    }
    __syncthreads();

    const uint32_t uWh = smem_u32(Wh), uWl = smem_u32(Wl);
    const uint32_t uBh = smem_u32(Bh), uBl = smem_u32(Bl);
    uint32_t Ah[8][4], Al[8][4];
    {
        const int q = lane >> 3, r = lane & 7;
#pragma unroll
        for (int ks = 0; ks < 8; ++ks) {
            const uint32_t off = (w * 16 + (q & 1) * 8 + r) * PW_STRIDE
                               + (ks * 16 + (q >> 1) * 8) * 2;
            ldsm4(Ah[ks][0], Ah[ks][1], Ah[ks][2], Ah[ks][3], uWh + off);
            ldsm4(Al[ks][0], Al[ks][1], Al[ks][2], Al[ks][3], uWl + off);
        }
    }
    float acc[8][4];
#pragma unroll
    for (int nt = 0; nt < 8; ++nt)
        acc[nt][0] = acc[nt][1] = acc[nt][2] = acc[nt][3] = 0.f;

#pragma unroll
    for (int nt = 0; nt < 8; ++nt) {
        const uint32_t colb = nt * 16;
#pragma unroll
        for (int cb = 0; cb < 4; ++cb) {
            uint32_t b0, b1, b2, b3;
            ldsm4t(b0, b1, b2, b3, uBh + (cb * 32 + lane) * PB64_STRIDE + colb);
            mma16816(acc[nt], Ah[2*cb][0], Ah[2*cb][1], Ah[2*cb][2], Ah[2*cb][3], b0, b1);
            mma16816(acc[nt], Ah[2*cb+1][0], Ah[2*cb+1][1], Ah[2*cb+1][2], Ah[2*cb+1][3], b2, b3);
        }
#pragma unroll
        for (int cb = 0; cb < 4; ++cb) {
            uint32_t b0, b1, b2, b3;
            ldsm4t(b0, b1, b2, b3, uBl + (cb * 32 + lane) * PB64_STRIDE + colb);
            mma16816(acc[nt], Ah[2*cb][0], Ah[2*cb][1], Ah[2*cb][2], Ah[2*cb][3], b0, b1);
            mma16816(acc[nt], Ah[2*cb+1][0], Ah[2*cb+1][1], Ah[2*cb+1][2], Ah[2*cb+1][3], b2, b3);
        }
#pragma unroll
        for (int cb = 0; cb < 4; ++cb) {
            uint32_t b0, b1, b2, b3;
            ldsm4t(b0, b1, b2, b3, uBh + (cb * 32 + lane) * PB64_STRIDE + colb);
            mma16816(acc[nt], Al[2*cb][0], Al[2*cb][1], Al[2*cb][2], Al[2*cb][3], b0, b1);
            mma16816(acc[nt], Al[2*cb+1][0], Al[2*cb+1][1], Al[2*cb+1][2], Al[2*cb+1][3], b2, b3);
        }
    }
    const int g = lane >> 2, tq = lane & 3;
    const int m0 = w * 16 + g, m1 = m0 + 8;
    const float bb0 = bo[m0], bb1 = bo[m1];
    float* og = out + (size_t)(b * CC) * NT;
#pragma unroll
    for (int nt = 0; nt < 8; ++nt) {
        const int n = n0 + nt * 8 + tq * 2;
        *(float2*)(og + (size_t)m0 * NT + n) = make_float2(acc[nt][0] + bb0, acc[nt][1] + bb0);
        *(float2*)(og + (size_t)m1 * NT + n) = make_float2(acc[nt][2] + bb1, acc[nt][3] + bb1);
    }
}

// =============================== norm / colsum ===============================
__global__ void __launch_bounds__(256, 1) norm_kernel()
{
    const int row = blockIdx.x;
    const float* p = (blockIdx.y == 0 ? g_q : g_k) + (size_t)row * NT;
    __nv_bfloat16* ob = (blockIdx.y == 0 ? g_qb : g_kb) + (size_t)row * NT;
    const int tid = threadIdx.x;

    float4 v[4];
    float s = 0.f;
#pragma unroll
    for (int it = 0; it < 4; ++it) {
        v[it] = ((const float4*)p)[tid + it * 256];
        s += v[it].x * v[it].x + v[it].y * v[it].y +
             v[it].z * v[it].z + v[it].w * v[it].w;
    }
#pragma unroll
    for (int o = 16; o > 0; o >>= 1) s += __shfl_xor_sync(0xffffffffu, s, o);

    __shared__ float red[8];
    if ((tid & 31) == 0) red[tid >> 5] = s;
    __syncthreads();
    if (tid < 32) {
        float vv = (tid < 8) ? red[tid] : 0.f;
#pragma unroll
        for (int o = 4; o > 0; o >>= 1) vv += __shfl_xor_sync(0xffffffffu, vv, o);
        if (tid == 0) red[0] = vv;
    }
    __syncthreads();
    const float scl = (blockIdx.y == 0 ? SCALE_F : 1.0f) /
                      fmaxf(sqrtf(red[0]), 1e-12f);
#pragma unroll
    for (int it = 0; it < 4; ++it) {
        ((uint2*)ob)[tid + it * 256] =
            make_uint2(packbf(v[it].x * scl, v[it].y * scl),
                       packbf(v[it].z * scl, v[it].w * scl));
    }
}

__global__ void __launch_bounds__(256, 1) colsum_kernel(const float* __restrict__ cx)
{
    const int row = blockIdx.x;
    const float* p = cx + (size_t)row * NT;
    const int tid = threadIdx.x;
    float s = 0.f;
#pragma unroll
    for (int it = 0; it < 4; ++it) {
        float4 v = ((const float4*)p)[tid + it * 256];
        s += v.x + v.y + v.z + v.w;
    }
#pragma unroll
    for (int o = 16; o > 0; o >>= 1) s += __shfl_xor_sync(0xffffffffu, s, o);
    __shared__ float red[8];
    if ((tid & 31) == 0) red[tid >> 5] = s;
    __syncthreads();
    if (tid == 0)
        g_colsum[row] = red[0] + red[1] + red[2] + red[3] +
                        red[4] + red[5] + red[6] + red[7];
}

// ========================= Stage B: G[F,e] = phi^T [v;1] =====================
__global__ void __launch_bounds__(256, 2) stageB_kernel()
{
    extern __shared__ unsigned char sm[];
    unsigned char* Kt0 = sm;
    unsigned char* Kt1 = sm + 34 * TS;
    unsigned char* Vt0 = sm + 2 * 34 * TS;
    unsigned char* Vt1 = Vt0 + 40 * TS;
    unsigned char* Phi = Vt1 + 40 * TS;
    uint32_t* lut      = (uint32_t*)(Phi + 128 * TS);

    const int tid = threadIdx.x, w = tid >> 5, lane = tid & 31;
    const int fb = blockIdx.x >> 2, js = blockIdx.x & 3;
    const int bh = blockIdx.y;
    const int cbase = (bh >> 2) * CC + (bh & 3) * DH;
    const __nv_bfloat16* kg = g_kb + (size_t)cbase * NT;
    const __nv_bfloat16* vg = g_vb + (size_t)cbase * NT;
    const int j0 = js * (NT / JSPLIT);

    const uint32_t ONE2 = packbf(1.f, 1.f);
    const uint32_t HALF2 = packbf(0.5f, 0.5f);

    build_lut(lut, tid);
    for (int i = tid; i < 2 * 64; i += 256) {
        unsigned char* Kb = (i >> 6) ? Kt1 : Kt0;
        unsigned char* Vb = (i >> 6) ? Vt1 : Vt0;
        const int c = i & 63;
        *(uint32_t*)(Kb + 32 * TS + c * 4) = ONE2;
        *(uint32_t*)(Kb + 33 * TS + c * 4) = 0u;
        *(uint32_t*)(Vb + 32 * TS + c * 4) = ONE2;
#pragma unroll
        for (int z = 33; z < 40; ++z) *(uint32_t*)(Vb + z * TS + c * 4) = 0u;
    }

    const uint32_t uK[2] = { smem_u32(Kt0), smem_u32(Kt1) };
    const uint32_t uV[2] = { smem_u32(Vt0), smem_u32(Vt1) };
    const uint32_t uPhi = smem_u32(Phi);

    {
#pragma unroll
        for (int r = 0; r < 4; ++r) {
            const int idx = tid + r * 256;
            const int d = idx >> 5, pr = idx & 31;
            const int ch = pr & 15;
            if ((pr >> 4) == 0)
                cp16(uK[0] + d * TS + ch * 16, kg + (size_t)d * NT + j0 + ch * 8);
            else
                cp16(uV[0] + d * TS + ch * 16, vg + (size_t)d * NT + j0 + ch * 8);
        }
        asm volatile("cp.async.commit_group;" ::: "memory");
    }

    float acc[5][4];
#pragma unroll
    for (int nt = 0; nt < 5; ++nt)
        acc[nt][0] = acc[nt][1] = acc[nt][2] = acc[nt][3] = 0.f;

    const int lq = lane >> 3, lr = lane & 7;

    for (int t = 0; t < NT / JSPLIT / 128; ++t) {
        asm volatile("cp.async.wait_group 0;" ::: "memory");
        __syncthreads();

        if (t < NT / JSPLIT / 128 - 1) {
            const int nb = (t + 1) & 1;
            const int jn = j0 + (t + 1) * 128;
#pragma unroll
            for (int r = 0; r < 4; ++r) {
                const int idx = tid + r * 256;
                const int d = idx >> 5, pr = idx & 31;
                const int ch = pr & 15;
                if ((pr >> 4) == 0)
                    cp16(uK[nb] + d * TS + ch * 16, kg + (size_t)d * NT + jn + ch * 8);
                else
                    cp16(uV[nb] + d * TS + ch * 16, vg + (size_t)d * NT + jn + ch * 8);
            }
            asm volatile("cp.async.commit_group;" ::: "memory");
        }

        {   // phi generation from K tile (row per feature)
            const unsigned char* Ks = (t & 1) ? Kt1 : Kt0;
            const int row = tid >> 1;
            const int c0 = (tid & 1) * 32;
            const uint32_t e = lut[fb * 128 + row];
            const int a = e & 0xff, b2 = (e >> 8) & 0xff;
            const uint32_t ws = e >> 16;
            const uint32_t w2 = (ws == 0) ? ONE2 : (ws == 1) ? HALF2 : 0u;
#pragma unroll
            for (int ii = 0; ii < 32; ++ii) {
                uint32_t ka = *(const uint32_t*)(Ks + a * TS + (c0 + ii) * 4);
                uint32_t kb = *(const uint32_t*)(Ks + b2 * TS + (c0 + ii) * 4);
                *(uint32_t*)(Phi + row * TS + (c0 + ii) * 4) =
                    bffma2(bffma2(ka, kb, 0u), w2, 0u);
            }
        }
        __syncthreads();

        const uint32_t uVs = uV[t & 1];
#pragma unroll
        for (int ug = 0; ug < 4; ++ug) {
            uint32_t A0[4], A1[4];
            ldsm4(A0[0], A0[1], A0[2], A0[3],
                  uPhi + (w * 16 + (lq & 1) * 8 + lr) * TS
                       + ((2 * ug) * 16 + (lq >> 1) * 8) * 2);
            ldsm4(A1[0], A1[1], A1[2], A1[3],
                  uPhi + (w * 16 + (lq & 1) * 8 + lr) * TS
                       + ((2 * ug + 1) * 16 + (lq >> 1) * 8) * 2);
#pragma unroll
            for (int nt = 0; nt < 5; ++nt) {
                uint32_t b0, b1, b2, b3;
                ldsm4(b0, b1, b2, b3,
                      uVs + (nt * 8 + lr) * TS + (ug * 4 + lq) * 16);
                mma16816(acc[nt], A0[0], A0[1], A0[2], A0[3], b0, b1);
                mma16816(acc[nt], A1[0], A1[1], A1[2], A1[3], b2, b3);
            }
        }
        __syncthreads();   // Phi consumed before next-iteration overwrite
    }

    const int g = lane >> 2, tq = lane & 3;
    const int fr0 = fb * 128 + w * 16 + g, fr1 = fr0 + 8;
    float* Gp = g_G2 + (size_t)(bh * JSPLIT + js) * NE * NF;
#pragma unroll
    for (int nt = 0; nt < 5; ++nt) {
        const int e0 = nt * 8 + 2 * tq;
        Gp[(size_t)e0 * NF + fr0]       = acc[nt][0];
        Gp[(size_t)(e0 + 1) * NF + fr0] = acc[nt][1];
        Gp[(size_t)e0 * NF + fr1]       = acc[nt][2];
        Gp[(size_t)(e0 + 1) * NF + fr1] = acc[nt][3];
    }
}

// reduce JSPLIT partials -> bf16 G
__global__ void __launch_bounds__(256, 4) greduce_kernel()
{
    const int o = (blockIdx.x * 256 + threadIdx.x) * 2;   // < 8*NE*NF
    const int bh = o / (NE * NF);
    const int r = o - bh * (NE * NF);
    const float* p = g_G2 + (size_t)bh * JSPLIT * NE * NF + r;
    float s0 = 0.f, s1 = 0.f;
#pragma unroll
    for (int js = 0; js < JSPLIT; ++js) {
        s0 += p[(size_t)js * NE * NF];
        s1 += p[(size_t)js * NE * NF + 1];
    }
    *(uint32_t*)(g_Gb + o) = packbf(s0, s1);
}

// ===================== Stage C: Odev = Psi(q) G + epilogue ===================
__global__ void __launch_bounds__(256, 2)
stageC_kernel(const float* __restrict__ Wv, const float* __restrict__ bv)
{
    extern __shared__ unsigned char sm[];
    unsigned char* Qt  = sm;                          // 34*TS
    unsigned char* Psi = Qt + 34 * TS;                // 128*TS
    unsigned char* Gs  = Psi + 128 * TS;              // 40*GSS
    uint32_t* lut      = (uint32_t*)(Gs + NE * GSS);  // NF
    float* svs         = (float*)(lut + NF);          // 32
    float* rd          = svs + 32;                    // 128

    const int tid = threadIdx.x, w = tid >> 5, lane = tid & 31;
    const int i0 = blockIdx.x * 128;
    const int bh = blockIdx.y;
    const int b = bh >> 2, hh = bh & 3;
    const int cbase = b * CC + hh * DH;
    const __nv_bfloat16* qg = g_qb + (size_t)cbase * NT;

    const uint32_t ONE2 = packbf(1.f, 1.f);
    build_lut(lut, tid);
    for (int c = tid; c < 64; c += 256) {
        *(uint32_t*)(Qt + 32 * TS + c * 4) = ONE2;
        *(uint32_t*)(Qt + 33 * TS + c * 4) = 0u;
    }

    const uint32_t uQt = smem_u32(Qt), uPsi = smem_u32(Psi), uGs = smem_u32(Gs);

    {
#pragma unroll
        for (int r = 0; r < 2; ++r) {
            const int idx = tid + r * 256;
            const int d = idx >> 4, ch = idx & 15;
            cp16(uQt + d * TS + ch * 16, qg + (size_t)d * NT + i0 + ch * 8);
        }
        const __nv_bfloat16* Gp = g_Gb + (size_t)bh * NE * NF;
        for (int idx = tid; idx < NE * (NF / 8); idx += 256) {
            const int e = idx / (NF / 8), c = idx % (NF / 8);
            cp16(uGs + e * GSS + c * 16, Gp + (size_t)e * NF + c * 8);
        }
        asm volatile("cp.async.commit_group;" ::: "memory");
        asm volatile("cp.async.wait_group 0;" ::: "memory");
    }
    __syncthreads();

    float acc[5][4];
#pragma unroll
    for (int nt = 0; nt < 5; ++nt)
        acc[nt][0] = acc[nt][1] = acc[nt][2] = acc[nt][3] = 0.f;

    const int lq = lane >> 3, lr = lane & 7;

    for (int fbi = 0; fbi < NFB; ++fbi) {
        if (fbi > 0) __syncthreads();
        {   // psi generation (row = feature, cols = q)
            const int row = tid >> 1;
            const int c0 = (tid & 1) * 32;
            const uint32_t e = lut[fbi * 128 + row];
            const int a = e & 0xff, b2 = (e >> 8) & 0xff;
#pragma unroll
            for (int ii = 0; ii < 32; ++ii) {
                uint32_t qa = *(const uint32_t*)(Qt + a * TS + (c0 + ii) * 4);
                uint32_t qb = *(const uint32_t*)(Qt + b2 * TS + (c0 + ii) * 4);
                *(uint32_t*)(Psi + row * TS + (c0 + ii) * 4) = bffma2(qa, qb, 0u);
            }
        }
        __syncthreads();

#pragma unroll
        for (int ug = 0; ug < 4; ++ug) {
            uint32_t A0[4], A1[4];
            ldsm4t(A0[0], A0[1], A0[2], A0[3],
                   uPsi + ((2 * ug) * 16 + ((lane >> 4) << 3) + (lane & 7)) * TS
                        + (w * 16 + ((lane >> 3) & 1) * 8) * 2);
            ldsm4t(A1[0], A1[1], A1[2], A1[3],
                   uPsi + ((2 * ug + 1) * 16 + ((lane >> 4) << 3) + (lane & 7)) * TS
                        + (w * 16 + ((lane >> 3) & 1) * 8) * 2);
#pragma unroll
            for (int nt = 0; nt < 5; ++nt) {
                uint32_t b0, b1, b2, b3;
                ldsm4(b0, b1, b2, b3,
                      uGs + (nt * 8 + lr) * GSS + fbi * 256 + (ug * 4 + lq) * 16);
                mma16816(acc[nt], A0[0], A0[1], A0[2], A0[3], b0, b1);
                mma16816(acc[nt], A1[0], A1[1], A1[2], A1[3], b2, b3);
            }
        }
    }

    {   // sumv: svs[d] = Wv[hh*32+d,:].colsum[b,:] + NT*bv
#pragma unroll
        for (int mi = 0; mi < 4; ++mi) {
            const int d = w * 4 + mi;
            const int m = hh * DH + d;
            float s = 0.f;
#pragma unroll
            for (int c4 = 0; c4 < 4; ++c4)
                s += Wv[m * 128 + c4 * 32 + lane] * g_colsum[b * CC + c4 * 32 + lane];
#pragma unroll
            for (int o = 16; o > 0; o >>= 1) s += __shfl_xor_sync(0xffffffffu, s, o);
            if (lane == 0) svs[d] = s + (float)NT * bv[m];
        }
    }
    const int g = lane >> 2, tq = lane & 3;
    if (tq == 0) {                         // rowsum column e=32 (nt=4, col 0)
        rd[w * 16 + g]     = acc[4][0];
        rd[w * 16 + g + 8] = acc[4][2];
    }
    __syncthreads();

    const int r0 = w * 16 + g, r1 = r0 + 8;
    const float inv0 = 1.0f / (4096.0f + rd[r0]);
    const float inv1 = 1.0f / (4096.0f + rd[r1]);
    float* att = g_att + (size_t)cbase * NT;
#pragma unroll
    for (int nt = 0; nt < 4; ++nt) {
        const int e0 = nt * 8 + 2 * tq;
        const float s0 = svs[e0], s1 = svs[e0 + 1];
        att[(size_t)e0 * NT + i0 + r0]       = (acc[nt][0] + s0) * inv0;
        att[(size_t)(e0 + 1) * NT + i0 + r0] = (acc[nt][1] + s1) * inv0;
        att[(size_t)e0 * NT + i0 + r1]       = (acc[nt][2] + s0) * inv1;
        att[(size_t)(e0 + 1) * NT + i0 + r1] = (acc[nt][3] + s1) * inv1;
    }
}

// ================================== launch ===================================
extern "C" void kernel_launch(void* const* d_in, const int* in_sizes, int n_in,
                              void* d_out, int out_size)
{
    (void)in_sizes; (void)n_in; (void)out_size;
    const float* x  = (const float*)d_in[0];
    const float* cx = (const float*)d_in[1];
    const float* Wq = (const float*)d_in[2];
    const float* bq = (const float*)d_in[3];
    const float* Wk = (const float*)d_in[4];
    const float* bk = (const float*)d_in[5];
    const float* Wv = (const float*)d_in[6];
    const float* bv = (const float*)d_in[7];
    const float* Wo = (const float*)d_in[8];
    const float* bo = (const float*)d_in[9];
    float* out = (float*)d_out;

    const int QKV_SMEM = 3 * 128 * PW_STRIDE;
    const int OUT_SMEM = 2 * 128 * PW_STRIDE + 2 * 128 * PB64_STRIDE;
    const int SB_SMEM  = 2 * 34 * TS + 2 * 40 * TS + 128 * TS + NF * 4;
    const int SC_SMEM  = 34 * TS + 128 * TS + NE * GSS + NF * 4 + 160 * 4;

    cudaFuncSetAttribute(proj_qkv_mma, cudaFuncAttributeMaxDynamicSharedMemorySize, QKV_SMEM);
    cudaFuncSetAttribute(proj_out_mma, cudaFuncAttributeMaxDynamicSharedMemorySize, OUT_SMEM);
    cudaFuncSetAttribute(stageB_kernel, cudaFuncAttributeMaxDynamicSharedMemorySize, SB_SMEM);
    cudaFuncSetAttribute(stageC_kernel, cudaFuncAttributeMaxDynamicSharedMemorySize, SC_SMEM);

    proj_qkv_mma<<<dim3(NT / 128, BB, 3), 256, QKV_SMEM>>>(x, cx, Wq, bq, Wk, bk, Wv, bv);
    colsum_kernel<<<dim3(BB * CC), 256>>>(cx);
    norm_kernel<<<dim3(BB * CC, 2), 256>>>();
    stageB_kernel<<<dim3(NFB * JSPLIT, BB * NH), 256, SB_SMEM>>>();
    greduce_kernel<<<dim3(8 * NE * NF / 512), 256>>>();
    stageC_kernel<<<dim3(NT / 128, BB * NH), 256, SC_SMEM>>>(Wv, bv);
    proj_out_mma<<<dim3(NT / 64, BB), 256, OUT_SMEM>>>(Wo, bo, out);
}

// round 12
// speedup vs baseline: 1.8097x; 1.3333x over previous
#include <cuda_runtime.h>
#include <cuda_bf16.h>
#include <cstdint>
#include <math.h>

#define BB 2
#define CC 128
#define NH 4
#define DH 32
#define NT 4096
#define SCALE_F 10.0f

#define NF 640
#define NFB 5
#define NE 40
#define TS 272
#define GSS 1296
#define JSPLIT 8

static __device__ float g_q[BB * CC * NT];
static __device__ float g_k[BB * CC * NT];
static __device__ __nv_bfloat16 g_qb[BB * CC * NT];
static __device__ __nv_bfloat16 g_kb[BB * CC * NT];
static __device__ __nv_bfloat16 g_vb[BB * CC * NT];
static __device__ float g_att[BB * CC * NT];
static __device__ float g_colsum[BB * CC];
static __device__ float g_G2[8 * JSPLIT * NE * NF];
static __device__ __nv_bfloat16 g_Gb[8 * NE * NF];

// ---------------------------------------------------------------- helpers ----
__device__ __forceinline__ uint32_t smem_u32(const void* p) {
    uint32_t a;
    asm("{ .reg .u64 t; cvta.to.shared.u64 t, %1; cvt.u32.u64 %0, t; }"
        : "=r"(a) : "l"(p));
    return a;
}
__device__ __forceinline__ uint32_t packbf(float a, float b) {
    uint32_t r;
    asm("cvt.rn.bf16x2.f32 %0, %2, %1;" : "=r"(r) : "f"(a), "f"(b));
    return r;
}
__device__ __forceinline__ uint32_t bffma2(uint32_t a, uint32_t b, uint32_t c) {
    uint32_t d;
    asm("fma.rn.bf16x2 %0, %1, %2, %3;" : "=r"(d) : "r"(a), "r"(b), "r"(c));
    return d;
}
__device__ __forceinline__ void ldsm4(uint32_t& r0, uint32_t& r1, uint32_t& r2,
                                      uint32_t& r3, uint32_t addr) {
    asm volatile("ldmatrix.sync.aligned.m8n8.x4.shared.b16 {%0,%1,%2,%3}, [%4];"
                 : "=r"(r0), "=r"(r1), "=r"(r2), "=r"(r3) : "r"(addr));
}
__device__ __forceinline__ void ldsm4t(uint32_t& r0, uint32_t& r1, uint32_t& r2,
                                       uint32_t& r3, uint32_t addr) {
    asm volatile("ldmatrix.sync.aligned.m8n8.x4.trans.shared.b16 {%0,%1,%2,%3}, [%4];"
                 : "=r"(r0), "=r"(r1), "=r"(r2), "=r"(r3) : "r"(addr));
}
__device__ __forceinline__ void mma16816(float* c, uint32_t a0, uint32_t a1,
                                         uint32_t a2, uint32_t a3,
                                         uint32_t b0, uint32_t b1) {
    asm volatile(
        "mma.sync.aligned.m16n8k16.row.col.f32.bf16.bf16.f32 "
        "{%0,%1,%2,%3}, {%4,%5,%6,%7}, {%8,%9}, {%0,%1,%2,%3};"
        : "+f"(c[0]), "+f"(c[1]), "+f"(c[2]), "+f"(c[3])
        : "r"(a0), "r"(a1), "r"(a2), "r"(a3), "r"(b0), "r"(b1));
}
__device__ __forceinline__ void cp16(uint32_t dst, const void* src) {
    asm volatile("cp.async.cg.shared.global [%0], [%1], 16;"
                 :: "r"(dst), "l"(src) : "memory");
}

// feature LUT: f -> a | b<<8 | wsel<<16 (rows 32=ones, 33=zeros in tiles)
__device__ __forceinline__ void build_lut(uint32_t* lut, int tid) {
    for (int f = tid; f < NF; f += 256) {
        uint32_t a, b, ws;
        if (f < 32) { a = f; b = 32; ws = 0; }
        else if (f < 560) {
            int p = f - 32;
            int aa = 0;
            while (p >= 32 - aa) { p -= 32 - aa; ++aa; }
            a = aa; b = aa + p; ws = (a == b) ? 1u : 0u;
        } else { a = 33; b = 33; ws = 2; }
        lut[f] = a | (b << 8) | (ws << 16);
    }
}

// ============================= projections (unchanged, proven) ===============
#define PW_STRIDE 272
#define PB64_STRIDE 144

__global__ void __launch_bounds__(256, 2)
proj_qkv_mma(const float* __restrict__ x, const float* __restrict__ cx,
             const float* __restrict__ Wq, const float* __restrict__ bq,
             const float* __restrict__ Wk, const float* __restrict__ bk,
             const float* __restrict__ Wv, const float* __restrict__ bv)
{
    extern __shared__ unsigned char psm[];
    unsigned char* Wh = psm;
    unsigned char* Bh = psm + 128 * PW_STRIDE;
    unsigned char* Bl = Bh + 128 * PW_STRIDE;

    const int tid = threadIdx.x, w = tid >> 5, lane = tid & 31;
    const int n0 = blockIdx.x * 128, b = blockIdx.y, wh = blockIdx.z;
    const float *W, *bias, *inb;
    if (wh == 0)      { W = Wq; bias = bq; inb = x  + (size_t)b * CC * NT; }
    else if (wh == 1) { W = Wk; bias = bk; inb = cx + (size_t)b * CC * NT; }
    else              { W = Wv; bias = bv; inb = cx + (size_t)b * CC * NT; }

#pragma unroll
    for (int it = 0; it < 16; ++it) {
        const int idx = tid + it * 256;
        const int m = idx >> 5, c4 = idx & 31;
        float4 ww = *(const float4*)(W + m * 128 + c4 * 4);
        *(uint2*)(Wh + m * PW_STRIDE + c4 * 8) =
            make_uint2(packbf(ww.x, ww.y), packbf(ww.z, ww.w));
    }
#pragma unroll
    for (int it = 0; it < 16; ++it) {
        const int idx = tid + it * 256;
        const int c = idx >> 5, c4 = idx & 31;
        float4 v = *(const float4*)(inb + (size_t)c * NT + n0 + c4 * 4);
        uint32_t h0 = packbf(v.x, v.y), h1 = packbf(v.z, v.w);
        float l0 = v.x - __uint_as_float(h0 << 16);
        float l1 = v.y - __uint_as_float(h0 & 0xffff0000u);
        float l2 = v.z - __uint_as_float(h1 << 16);
        float l3 = v.w - __uint_as_float(h1 & 0xffff0000u);
        *(uint2*)(Bh + c * PW_STRIDE + c4 * 8) = make_uint2(h0, h1);
        *(uint2*)(Bl + c * PW_STRIDE + c4 * 8) =
            make_uint2(packbf(l0, l1), packbf(l2, l3));
    }
    __syncthreads();

    const uint32_t uWh = smem_u32(Wh), uBh = smem_u32(Bh), uBl = smem_u32(Bl);
    uint32_t A[8][4];
    {
        const int q = lane >> 3, r = lane & 7;
#pragma unroll
        for (int ks = 0; ks < 8; ++ks)
            ldsm4(A[ks][0], A[ks][1], A[ks][2], A[ks][3],
                  uWh + (w * 16 + (q & 1) * 8 + r) * PW_STRIDE
                      + (ks * 16 + (q >> 1) * 8) * 2);
    }
    const int g = lane >> 2, tq = lane & 3;
    const int m0 = w * 16 + g, m1 = m0 + 8;
    const float bb0 = bias[m0], bb1 = bias[m1];

#pragma unroll
    for (int nh = 0; nh < 2; ++nh) {
        float acc[8][4];
#pragma unroll
        for (int nt = 0; nt < 8; ++nt)
            acc[nt][0] = acc[nt][1] = acc[nt][2] = acc[nt][3] = 0.f;
#pragma unroll
        for (int nt = 0; nt < 8; ++nt) {
            const uint32_t colb = nh * 128 + nt * 16;
#pragma unroll
            for (int cb = 0; cb < 4; ++cb) {
                uint32_t b0, b1, b2, b3;
                ldsm4t(b0, b1, b2, b3, uBh + (cb * 32 + lane) * PW_STRIDE + colb);
                mma16816(acc[nt], A[2*cb][0], A[2*cb][1], A[2*cb][2], A[2*cb][3], b0, b1);
                mma16816(acc[nt], A[2*cb+1][0], A[2*cb+1][1], A[2*cb+1][2], A[2*cb+1][3], b2, b3);
            }
#pragma unroll
            for (int cb = 0; cb < 4; ++cb) {
                uint32_t b0, b1, b2, b3;
                ldsm4t(b0, b1, b2, b3, uBl + (cb * 32 + lane) * PW_STRIDE + colb);
                mma16816(acc[nt], A[2*cb][0], A[2*cb][1], A[2*cb][2], A[2*cb][3], b0, b1);
                mma16816(acc[nt], A[2*cb+1][0], A[2*cb+1][1], A[2*cb+1][2], A[2*cb+1][3], b2, b3);
            }
        }
        if (wh == 2) {
            __nv_bfloat16* vb = g_vb + (size_t)(b * CC) * NT;
#pragma unroll
            for (int nt = 0; nt < 8; ++nt) {
                const int n = n0 + nh * 64 + nt * 8 + tq * 2;
                *(uint32_t*)(vb + (size_t)m0 * NT + n) = packbf(acc[nt][0] + bb0, acc[nt][1] + bb0);
                *(uint32_t*)(vb + (size_t)m1 * NT + n) = packbf(acc[nt][2] + bb1, acc[nt][3] + bb1);
            }
        } else {
            float* og = (wh == 0 ? g_q : g_k) + (size_t)(b * CC) * NT;
#pragma unroll
            for (int nt = 0; nt < 8; ++nt) {
                const int n = n0 + nh * 64 + nt * 8 + tq * 2;
                *(float2*)(og + (size_t)m0 * NT + n) = make_float2(acc[nt][0] + bb0, acc[nt][1] + bb0);
                *(float2*)(og + (size_t)m1 * NT + n) = make_float2(acc[nt][2] + bb1, acc[nt][3] + bb1);
            }
        }
    }
}

__global__ void __launch_bounds__(256, 2)
proj_out_mma(const float* __restrict__ Wo, const float* __restrict__ bo,
             float* __restrict__ out)
{
    extern __shared__ unsigned char psm[];
    unsigned char* Wh = psm;
    unsigned char* Wl = psm + 128 * PW_STRIDE;
    unsigned char* Bh = Wl + 128 * PW_STRIDE;
    unsigned char* Bl = Bh + 128 * PB64_STRIDE;

    const int tid = threadIdx.x, w = tid >> 5, lane = tid & 31;
    const int n0 = blockIdx.x * 64, b = blockIdx.y;
    const float* inb = g_att + (size_t)b * CC * NT;

#pragma unroll
    for (int it = 0; it < 16; ++it) {
        const int idx = tid + it * 256;
        const int m = idx >> 5, c4 = idx & 31;
        float4 ww = *(const float4*)(Wo + m * 128 + c4 * 4);
        uint32_t h0 = packbf(ww.x, ww.y), h1 = packbf(ww.z, ww.w);
        float l0 = ww.x - __uint_as_float(h0 << 16);
        float l1 = ww.y - __uint_as_float(h0 & 0xffff0000u);
        float l2 = ww.z - __uint_as_float(h1 << 16);
        float l3 = ww.w - __uint_as_float(h1 & 0xffff0000u);
        *(uint2*)(Wh + m * PW_STRIDE + c4 * 8) = make_uint2(h0, h1);
        *(uint2*)(Wl + m * PW_STRIDE + c4 * 8) =
            make_uint2(packbf(l0, l1), packbf(l2, l3));
    }
#pragma unroll
    for (int it = 0; it < 8; ++it) {
        const int idx = tid + it * 256;
        const int c = idx >> 4, c4 = idx & 15;
        float4 v = *(const float4*)(inb + (size_t)c * NT + n0 + c4 * 4);
        uint32_t h0 = packbf(v.x, v.y), h1 = packbf(v.z, v.w);
        float l0 = v.x - __uint_as_float(h0 << 16);
        float l1 = v.y - __uint_as_float(h0 & 0xffff0000u);
        float l2 = v.z - __uint_as_float(h1 << 16);
        float l3 = v.w - __uint_as_float(h1 & 0xffff0000u);
        *(uint2*)(Bh + c * PB64_STRIDE + c4 * 8) = make_uint2(h0, h1);
        *(uint2*)(Bl + c * PB64_STRIDE + c4 * 8) =
            make_uint2(packbf(l0, l1), packbf(l2, l3));
    }
    __syncthreads();

    const uint32_t uWh = smem_u32(Wh), uWl = smem_u32(Wl);
    const uint32_t uBh = smem_u32(Bh), uBl = smem_u32(Bl);
    uint32_t Ah[8][4], Al[8][4];
    {
        const int q = lane >> 3, r = lane & 7;
#pragma unroll
        for (int ks = 0; ks < 8; ++ks) {
            const uint32_t off = (w * 16 + (q & 1) * 8 + r) * PW_STRIDE
                               + (ks * 16 + (q >> 1) * 8) * 2;
            ldsm4(Ah[ks][0], Ah[ks][1], Ah[ks][2], Ah[ks][3], uWh + off);
            ldsm4(Al[ks][0], Al[ks][1], Al[ks][2], Al[ks][3], uWl + off);
        }
    }
    float acc[8][4];
#pragma unroll
    for (int nt = 0; nt < 8; ++nt)
        acc[nt][0] = acc[nt][1] = acc[nt][2] = acc[nt][3] = 0.f;

#pragma unroll
    for (int nt = 0; nt < 8; ++nt) {
        const uint32_t colb = nt * 16;
#pragma unroll
        for (int cb = 0; cb < 4; ++cb) {
            uint32_t b0, b1, b2, b3;
            ldsm4t(b0, b1, b2, b3, uBh + (cb * 32 + lane) * PB64_STRIDE + colb);
            mma16816(acc[nt], Ah[2*cb][0], Ah[2*cb][1], Ah[2*cb][2], Ah[2*cb][3], b0, b1);
            mma16816(acc[nt], Ah[2*cb+1][0], Ah[2*cb+1][1], Ah[2*cb+1][2], Ah[2*cb+1][3], b2, b3);
        }
#pragma unroll
        for (int cb = 0; cb < 4; ++cb) {
            uint32_t b0, b1, b2, b3;
            ldsm4t(b0, b1, b2, b3, uBl + (cb * 32 + lane) * PB64_STRIDE + colb);
            mma16816(acc[nt], Ah[2*cb][0], Ah[2*cb][1], Ah[2*cb][2], Ah[2*cb][3], b0, b1);
            mma16816(acc[nt], Ah[2*cb+1][0], Ah[2*cb+1][1], Ah[2*cb+1][2], Ah[2*cb+1][3], b2, b3);
        }
#pragma unroll
        for (int cb = 0; cb < 4; ++cb) {
            uint32_t b0, b1, b2, b3;
            ldsm4t(b0, b1, b2, b3, uBh + (cb * 32 + lane) * PB64_STRIDE + colb);
            mma16816(acc[nt], Al[2*cb][0], Al[2*cb][1], Al[2*cb][2], Al[2*cb][3], b0, b1);
            mma16816(acc[nt], Al[2*cb+1][0], Al[2*cb+1][1], Al[2*cb+1][2], Al[2*cb+1][3], b2, b3);
        }
    }
    const int g = lane >> 2, tq = lane & 3;
    const int m0 = w * 16 + g, m1 = m0 + 8;
    const float bb0 = bo[m0], bb1 = bo[m1];
    float* og = out + (size_t)(b * CC) * NT;
#pragma unroll
    for (int nt = 0; nt < 8; ++nt) {
        const int n = n0 + nt * 8 + tq * 2;
        *(float2*)(og + (size_t)m0 * NT + n) = make_float2(acc[nt][0] + bb0, acc[nt][1] + bb0);
        *(float2*)(og + (size_t)m1 * NT + n) = make_float2(acc[nt][2] + bb1, acc[nt][3] + bb1);
    }
}

// =============================== norm / colsum ===============================
__global__ void __launch_bounds__(256, 1) norm_kernel()
{
    const int row = blockIdx.x;
    const float* p = (blockIdx.y == 0 ? g_q : g_k) + (size_t)row * NT;
    __nv_bfloat16* ob = (blockIdx.y == 0 ? g_qb : g_kb) + (size_t)row * NT;
    const int tid = threadIdx.x;

    float4 v[4];
    float s = 0.f;
#pragma unroll
    for (int it = 0; it < 4; ++it) {
        v[it] = ((const float4*)p)[tid + it * 256];
        s += v[it].x * v[it].x + v[it].y * v[it].y +
             v[it].z * v[it].z + v[it].w * v[it].w;
    }
#pragma unroll
    for (int o = 16; o > 0; o >>= 1) s += __shfl_xor_sync(0xffffffffu, s, o);

    __shared__ float red[8];
    if ((tid & 31) == 0) red[tid >> 5] = s;
    __syncthreads();
    if (tid < 32) {
        float vv = (tid < 8) ? red[tid] : 0.f;
#pragma unroll
        for (int o = 4; o > 0; o >>= 1) vv += __shfl_xor_sync(0xffffffffu, vv, o);
        if (tid == 0) red[0] = vv;
    }
    __syncthreads();
    const float scl = (blockIdx.y == 0 ? SCALE_F : 1.0f) /
                      fmaxf(sqrtf(red[0]), 1e-12f);
#pragma unroll
    for (int it = 0; it < 4; ++it) {
        ((uint2*)ob)[tid + it * 256] =
            make_uint2(packbf(v[it].x * scl, v[it].y * scl),
                       packbf(v[it].z * scl, v[it].w * scl));
    }
}

__global__ void __launch_bounds__(256, 1) colsum_kernel(const float* __restrict__ cx)
{
    const int row = blockIdx.x;
    const float* p = cx + (size_t)row * NT;
    const int tid = threadIdx.x;
    float s = 0.f;
#pragma unroll
    for (int it = 0; it < 4; ++it) {
        float4 v = ((const float4*)p)[tid + it * 256];
        s += v.x + v.y + v.z + v.w;
    }
#pragma unroll
    for (int o = 16; o > 0; o >>= 1) s += __shfl_xor_sync(0xffffffffu, s, o);
    __shared__ float red[8];
    if ((tid & 31) == 0) red[tid >> 5] = s;
    __syncthreads();
    if (tid == 0)
        g_colsum[row] = red[0] + red[1] + red[2] + red[3] +
                        red[4] + red[5] + red[6] + red[7];
}

// ========================= Stage B: G[F,e] = phi^T [v;1] =====================
__global__ void __launch_bounds__(256, 2) stageB_kernel()
{
    extern __shared__ unsigned char sm[];
    unsigned char* Kt0 = sm;
    unsigned char* Kt1 = sm + 34 * TS;
    unsigned char* Vt0 = sm + 2 * 34 * TS;
    unsigned char* Vt1 = Vt0 + 40 * TS;
    unsigned char* Phi = Vt1 + 40 * TS;
    uint32_t* lut      = (uint32_t*)(Phi + 128 * TS);

    const int tid = threadIdx.x, w = tid >> 5, lane = tid & 31;
    const int fb = blockIdx.x >> 3, js = blockIdx.x & 7;
    const int bh = blockIdx.y;
    const int cbase = (bh >> 2) * CC + (bh & 3) * DH;
    const __nv_bfloat16* kg = g_kb + (size_t)cbase * NT;
    const __nv_bfloat16* vg = g_vb + (size_t)cbase * NT;
    const int j0 = js * (NT / JSPLIT);

    const uint32_t ONE2 = packbf(1.f, 1.f);
    const uint32_t HALF2 = packbf(0.5f, 0.5f);

    build_lut(lut, tid);
    for (int i = tid; i < 2 * 64; i += 256) {
        unsigned char* Kb = (i >> 6) ? Kt1 : Kt0;
        unsigned char* Vb = (i >> 6) ? Vt1 : Vt0;
        const int c = i & 63;
        *(uint32_t*)(Kb + 32 * TS + c * 4) = ONE2;
        *(uint32_t*)(Kb + 33 * TS + c * 4) = 0u;
        *(uint32_t*)(Vb + 32 * TS + c * 4) = ONE2;
#pragma unroll
        for (int z = 33; z < 40; ++z) *(uint32_t*)(Vb + z * TS + c * 4) = 0u;
    }

    const uint32_t uK[2] = { smem_u32(Kt0), smem_u32(Kt1) };
    const uint32_t uV[2] = { smem_u32(Vt0), smem_u32(Vt1) };
    const uint32_t uPhi = smem_u32(Phi);

    {
#pragma unroll
        for (int r = 0; r < 4; ++r) {
            const int idx = tid + r * 256;
            const int d = idx >> 5, pr = idx & 31;
            const int ch = pr & 15;
            if ((pr >> 4) == 0)
                cp16(uK[0] + d * TS + ch * 16, kg + (size_t)d * NT + j0 + ch * 8);
            else
                cp16(uV[0] + d * TS + ch * 16, vg + (size_t)d * NT + j0 + ch * 8);
        }
        asm volatile("cp.async.commit_group;" ::: "memory");
    }

    float acc[5][4];
#pragma unroll
    for (int nt = 0; nt < 5; ++nt)
        acc[nt][0] = acc[nt][1] = acc[nt][2] = acc[nt][3] = 0.f;

    const int lq = lane >> 3, lr = lane & 7;

    for (int t = 0; t < NT / JSPLIT / 128; ++t) {
        asm volatile("cp.async.wait_group 0;" ::: "memory");
        __syncthreads();

        if (t < NT / JSPLIT / 128 - 1) {
            const int nb = (t + 1) & 1;
            const int jn = j0 + (t + 1) * 128;
#pragma unroll
            for (int r = 0; r < 4; ++r) {
                const int idx = tid + r * 256;
                const int d = idx >> 5, pr = idx & 31;
                const int ch = pr & 15;
                if ((pr >> 4) == 0)
                    cp16(uK[nb] + d * TS + ch * 16, kg + (size_t)d * NT + jn + ch * 8);
                else
                    cp16(uV[nb] + d * TS + ch * 16, vg + (size_t)d * NT + jn + ch * 8);
            }
            asm volatile("cp.async.commit_group;" ::: "memory");
        }

        {   // phi generation — warp-per-row, conflict-free uint2 accesses
            const unsigned char* Ks = (t & 1) ? Kt1 : Kt0;
#pragma unroll
            for (int r = 0; r < 16; ++r) {
                const int row = w * 16 + r;
                const uint32_t e = lut[fb * 128 + row];
                const int a = e & 0xff, b2 = (e >> 8) & 0xff;
                const uint32_t ws = e >> 16;
                const uint32_t w2 = (ws == 0) ? ONE2 : (ws == 1) ? HALF2 : 0u;
                uint2 ka = *(const uint2*)(Ks + a * TS + lane * 8);
                uint2 kb = *(const uint2*)(Ks + b2 * TS + lane * 8);
                uint2 ph;
                ph.x = bffma2(bffma2(ka.x, kb.x, 0u), w2, 0u);
                ph.y = bffma2(bffma2(ka.y, kb.y, 0u), w2, 0u);
                *(uint2*)(Phi + row * TS + lane * 8) = ph;
            }
        }
        __syncthreads();

        const uint32_t uVs = uV[t & 1];
#pragma unroll
        for (int ug = 0; ug < 4; ++ug) {
            uint32_t A0[4], A1[4];
            ldsm4(A0[0], A0[1], A0[2], A0[3],
                  uPhi + (w * 16 + (lq & 1) * 8 + lr) * TS
                       + ((2 * ug) * 16 + (lq >> 1) * 8) * 2);
            ldsm4(A1[0], A1[1], A1[2], A1[3],
                  uPhi + (w * 16 + (lq & 1) * 8 + lr) * TS
                       + ((2 * ug + 1) * 16 + (lq >> 1) * 8) * 2);
#pragma unroll
            for (int nt = 0; nt < 5; ++nt) {
                uint32_t b0, b1, b2, b3;
                ldsm4(b0, b1, b2, b3,
                      uVs + (nt * 8 + lr) * TS + (ug * 4 + lq) * 16);
                mma16816(acc[nt], A0[0], A0[1], A0[2], A0[3], b0, b1);
                mma16816(acc[nt], A1[0], A1[1], A1[2], A1[3], b2, b3);
            }
        }
        __syncthreads();   // Phi consumed before next-iteration overwrite
    }

    const int g = lane >> 2, tq = lane & 3;
    const int fr0 = fb * 128 + w * 16 + g, fr1 = fr0 + 8;
    float* Gp = g_G2 + (size_t)(bh * JSPLIT + js) * NE * NF;
#pragma unroll
    for (int nt = 0; nt < 5; ++nt) {
        const int e0 = nt * 8 + 2 * tq;
        Gp[(size_t)e0 * NF + fr0]       = acc[nt][0];
        Gp[(size_t)(e0 + 1) * NF + fr0] = acc[nt][1];
        Gp[(size_t)e0 * NF + fr1]       = acc[nt][2];
        Gp[(size_t)(e0 + 1) * NF + fr1] = acc[nt][3];
    }
}

// reduce JSPLIT partials -> bf16 G
__global__ void __launch_bounds__(256, 4) greduce_kernel()
{
    const int o = (blockIdx.x * 256 + threadIdx.x) * 2;
    const int bh = o / (NE * NF);
    const int r = o - bh * (NE * NF);
    const float* p = g_G2 + (size_t)bh * JSPLIT * NE * NF + r;
    float s0 = 0.f, s1 = 0.f;
#pragma unroll
    for (int js = 0; js < JSPLIT; ++js) {
        s0 += p[(size_t)js * NE * NF];
        s1 += p[(size_t)js * NE * NF + 1];
    }
    *(uint32_t*)(g_Gb + o) = packbf(s0, s1);
}

// ===================== Stage C: Odev = Psi(q) G + epilogue ===================
__global__ void __launch_bounds__(256, 2)
stageC_kernel(const float* __restrict__ Wv, const float* __restrict__ bv)
{
    extern __shared__ unsigned char sm[];
    unsigned char* Qt  = sm;
    unsigned char* Psi = Qt + 34 * TS;
    unsigned char* Gs  = Psi + 128 * TS;
    uint32_t* lut      = (uint32_t*)(Gs + NE * GSS);
    float* svs         = (float*)(lut + NF);
    float* rd          = svs + 32;

    const int tid = threadIdx.x, w = tid >> 5, lane = tid & 31;
    const int i0 = blockIdx.x * 128;
    const int bh = blockIdx.y;
    const int b = bh >> 2, hh = bh & 3;
    const int cbase = b * CC + hh * DH;
    const __nv_bfloat16* qg = g_qb + (size_t)cbase * NT;

    const uint32_t ONE2 = packbf(1.f, 1.f);
    build_lut(lut, tid);
    for (int c = tid; c < 64; c += 256) {
        *(uint32_t*)(Qt + 32 * TS + c * 4) = ONE2;
        *(uint32_t*)(Qt + 33 * TS + c * 4) = 0u;
    }

    const uint32_t uQt = smem_u32(Qt), uPsi = smem_u32(Psi), uGs = smem_u32(Gs);

    {
#pragma unroll
        for (int r = 0; r < 2; ++r) {
            const int idx = tid + r * 256;
            const int d = idx >> 4, ch = idx & 15;
            cp16(uQt + d * TS + ch * 16, qg + (size_t)d * NT + i0 + ch * 8);
        }
        const __nv_bfloat16* Gp = g_Gb + (size_t)bh * NE * NF;
        for (int idx = tid; idx < NE * (NF / 8); idx += 256) {
            const int e = idx / (NF / 8), c = idx % (NF / 8);
            cp16(uGs + e * GSS + c * 16, Gp + (size_t)e * NF + c * 8);
        }
        asm volatile("cp.async.commit_group;" ::: "memory");
        asm volatile("cp.async.wait_group 0;" ::: "memory");
    }
    __syncthreads();

    float acc[5][4];
#pragma unroll
    for (int nt = 0; nt < 5; ++nt)
        acc[nt][0] = acc[nt][1] = acc[nt][2] = acc[nt][3] = 0.f;

    const int lq = lane >> 3, lr = lane & 7;

    for (int fbi = 0; fbi < NFB; ++fbi) {
        if (fbi > 0) __syncthreads();
        {   // psi generation — warp-per-row, conflict-free
#pragma unroll
            for (int r = 0; r < 16; ++r) {
                const int row = w * 16 + r;
                const uint32_t e = lut[fbi * 128 + row];
                const int a = e & 0xff, b2 = (e >> 8) & 0xff;
                uint2 qa = *(const uint2*)(Qt + a * TS + lane * 8);
                uint2 qb = *(const uint2*)(Qt + b2 * TS + lane * 8);
                uint2 ps;
                ps.x = bffma2(qa.x, qb.x, 0u);
                ps.y = bffma2(qa.y, qb.y, 0u);
                *(uint2*)(Psi + row * TS + lane * 8) = ps;
            }
        }
        __syncthreads();

#pragma unroll
        for (int ug = 0; ug < 4; ++ug) {
            uint32_t A0[4], A1[4];
            ldsm4t(A0[0], A0[1], A0[2], A0[3],
                   uPsi + ((2 * ug) * 16 + ((lane >> 4) << 3) + (lane & 7)) * TS
                        + (w * 16 + ((lane >> 3) & 1) * 8) * 2);
            ldsm4t(A1[0], A1[1], A1[2], A1[3],
                   uPsi + ((2 * ug + 1) * 16 + ((lane >> 4) << 3) + (lane & 7)) * TS
                        + (w * 16 + ((lane >> 3) & 1) * 8) * 2);
#pragma unroll
            for (int nt = 0; nt < 5; ++nt) {
                uint32_t b0, b1, b2, b3;
                ldsm4(b0, b1, b2, b3,
                      uGs + (nt * 8 + lr) * GSS + fbi * 256 + (ug * 4 + lq) * 16);
                mma16816(acc[nt], A0[0], A0[1], A0[2], A0[3], b0, b1);
                mma16816(acc[nt], A1[0], A1[1], A1[2], A1[3], b2, b3);
            }
        }
    }

    {   // sumv
#pragma unroll
        for (int mi = 0; mi < 4; ++mi) {
            const int d = w * 4 + mi;
            const int m = hh * DH + d;
            float s = 0.f;
#pragma unroll
            for (int c4 = 0; c4 < 4; ++c4)
                s += Wv[m * 128 + c4 * 32 + lane] * g_colsum[b * CC + c4 * 32 + lane];
#pragma unroll
            for (int o = 16; o > 0; o >>= 1) s += __shfl_xor_sync(0xffffffffu, s, o);
            if (lane == 0) svs[d] = s + (float)NT * bv[m];
        }
    }
    const int g = lane >> 2, tq = lane & 3;
    if (tq == 0) {
        rd[w * 16 + g]     = acc[4][0];
        rd[w * 16 + g + 8] = acc[4][2];
    }
    __syncthreads();

    const int r0 = w * 16 + g, r1 = r0 + 8;
    const float inv0 = 1.0f / (4096.0f + rd[r0]);
    const float inv1 = 1.0f / (4096.0f + rd[r1]);
    float* att = g_att + (size_t)cbase * NT;
#pragma unroll
    for (int nt = 0; nt < 4; ++nt) {
        const int e0 = nt * 8 + 2 * tq;
        const float s0 = svs[e0], s1 = svs[e0 + 1];
        att[(size_t)e0 * NT + i0 + r0]       = (acc[nt][0] + s0) * inv0;
        att[(size_t)(e0 + 1) * NT + i0 + r0] = (acc[nt][1] + s1) * inv0;
        att[(size_t)e0 * NT + i0 + r1]       = (acc[nt][2] + s0) * inv1;
        att[(size_t)(e0 + 1) * NT + i0 + r1] = (acc[nt][3] + s1) * inv1;
    }
}

// ================================== launch ===================================
extern "C" void kernel_launch(void* const* d_in, const int* in_sizes, int n_in,
                              void* d_out, int out_size)
{
    (void)in_sizes; (void)n_in; (void)out_size;
    const float* x  = (const float*)d_in[0];
    const float* cx = (const float*)d_in[1];
    const float* Wq = (const float*)d_in[2];
    const float* bq = (const float*)d_in[3];
    const float* Wk = (const float*)d_in[4];
    const float* bk = (const float*)d_in[5];
    const float* Wv = (const float*)d_in[6];
    const float* bv = (const float*)d_in[7];
    const float* Wo = (const float*)d_in[8];
    const float* bo = (const float*)d_in[9];
    float* out = (float*)d_out;

    const int QKV_SMEM = 3 * 128 * PW_STRIDE;
    const int OUT_SMEM = 2 * 128 * PW_STRIDE + 2 * 128 * PB64_STRIDE;
    const int SB_SMEM  = 2 * 34 * TS + 2 * 40 * TS + 128 * TS + NF * 4;
    const int SC_SMEM  = 34 * TS + 128 * TS + NE * GSS + NF * 4 + 160 * 4;

    cudaFuncSetAttribute(proj_qkv_mma, cudaFuncAttributeMaxDynamicSharedMemorySize, QKV_SMEM);
    cudaFuncSetAttribute(proj_out_mma, cudaFuncAttributeMaxDynamicSharedMemorySize, OUT_SMEM);
    cudaFuncSetAttribute(stageB_kernel, cudaFuncAttributeMaxDynamicSharedMemorySize, SB_SMEM);
    cudaFuncSetAttribute(stageC_kernel, cudaFuncAttributeMaxDynamicSharedMemorySize, SC_SMEM);

    proj_qkv_mma<<<dim3(NT / 128, BB, 3), 256, QKV_SMEM>>>(x, cx, Wq, bq, Wk, bk, Wv, bv);
    colsum_kernel<<<dim3(BB * CC), 256>>>(cx);
    norm_kernel<<<dim3(BB * CC, 2), 256>>>();
    stageB_kernel<<<dim3(NFB * JSPLIT, BB * NH), 256, SB_SMEM>>>();
    greduce_kernel<<<dim3(8 * NE * NF / 512), 256>>>();
    stageC_kernel<<<dim3(NT / 128, BB * NH), 256, SC_SMEM>>>(Wv, bv);
    proj_out_mma<<<dim3(NT / 64, BB), 256, OUT_SMEM>>>(Wo, bo, out);
}

// round 13
// speedup vs baseline: 2.2105x; 1.2215x over previous
#include <cuda_runtime.h>
#include <cuda_bf16.h>
#include <cstdint>
#include <math.h>

#define BB 2
#define CC 128
#define NH 4
#define DH 32
#define NT 4096
#define SCALE_F 10.0f

#define NF 640
#define NFB 5
#define NE 40
#define TS 272
#define GSS 1296
#define JSPLIT 8

static __device__ float g_q[BB * CC * NT];
static __device__ float g_k[BB * CC * NT];
static __device__ __nv_bfloat16 g_qb[BB * CC * NT];
static __device__ __nv_bfloat16 g_kb[BB * CC * NT];
static __device__ __nv_bfloat16 g_vb[BB * CC * NT];
static __device__ float g_att[BB * CC * NT];
static __device__ float g_colsum[BB * CC];
static __device__ float g_G2[8 * JSPLIT * NE * NF];
static __device__ __nv_bfloat16 g_Gb[8 * NE * NF];

// ---------------------------------------------------------------- helpers ----
__device__ __forceinline__ uint32_t smem_u32(const void* p) {
    uint32_t a;
    asm("{ .reg .u64 t; cvta.to.shared.u64 t, %1; cvt.u32.u64 %0, t; }"
        : "=r"(a) : "l"(p));
    return a;
}
__device__ __forceinline__ uint32_t packbf(float a, float b) {
    uint32_t r;
    asm("cvt.rn.bf16x2.f32 %0, %2, %1;" : "=r"(r) : "f"(a), "f"(b));
    return r;
}
__device__ __forceinline__ uint32_t bffma2(uint32_t a, uint32_t b, uint32_t c) {
    uint32_t d;
    asm("fma.rn.bf16x2 %0, %1, %2, %3;" : "=r"(d) : "r"(a), "r"(b), "r"(c));
    return d;
}
__device__ __forceinline__ void ldsm4(uint32_t& r0, uint32_t& r1, uint32_t& r2,
                                      uint32_t& r3, uint32_t addr) {
    asm volatile("ldmatrix.sync.aligned.m8n8.x4.shared.b16 {%0,%1,%2,%3}, [%4];"
                 : "=r"(r0), "=r"(r1), "=r"(r2), "=r"(r3) : "r"(addr));
}
__device__ __forceinline__ void ldsm4t(uint32_t& r0, uint32_t& r1, uint32_t& r2,
                                       uint32_t& r3, uint32_t addr) {
    asm volatile("ldmatrix.sync.aligned.m8n8.x4.trans.shared.b16 {%0,%1,%2,%3}, [%4];"
                 : "=r"(r0), "=r"(r1), "=r"(r2), "=r"(r3) : "r"(addr));
}
__device__ __forceinline__ void mma16816(float* c, uint32_t a0, uint32_t a1,
                                         uint32_t a2, uint32_t a3,
                                         uint32_t b0, uint32_t b1) {
    asm volatile(
        "mma.sync.aligned.m16n8k16.row.col.f32.bf16.bf16.f32 "
        "{%0,%1,%2,%3}, {%4,%5,%6,%7}, {%8,%9}, {%0,%1,%2,%3};"
        : "+f"(c[0]), "+f"(c[1]), "+f"(c[2]), "+f"(c[3])
        : "r"(a0), "r"(a1), "r"(a2), "r"(a3), "r"(b0), "r"(b1));
}
__device__ __forceinline__ void cp16(uint32_t dst, const void* src) {
    asm volatile("cp.async.cg.shared.global [%0], [%1], 16;"
                 :: "r"(dst), "l"(src) : "memory");
}

// feature decomposition f -> (a,b): rows 32=ones, 33=zeros in tiles
__device__ __forceinline__ void fdec(int f, int& a, int& b) {
    if (f < 32) { a = f; b = 32; }
    else if (f < 560) {
        int p = f - 32, aa = 0;
        while (p >= 32 - aa) { p -= 32 - aa; ++aa; }
        a = aa; b = aa + p;
    } else { a = 33; b = 33; }
}
__device__ __forceinline__ float fweight(int f) {
    if (f < 32) return 1.0f;
    if (f >= 560) return 0.0f;
    int a, b; fdec(f, a, b);
    return (a == b) ? 0.5f : 1.0f;
}
// feature LUT for stageC: f -> a | b<<8
__device__ __forceinline__ void build_lut(uint32_t* lut, int tid) {
    for (int f = tid; f < NF; f += 256) {
        int a, b; fdec(f, a, b);
        lut[f] = (uint32_t)a | ((uint32_t)b << 8);
    }
}

// ============================= projections ===================================
#define PW_STRIDE 272
#define PB64_STRIDE 144

// qkv: single-pass Whi @ in_hi (downstream is bf16 anyway)
__global__ void __launch_bounds__(256, 2)
proj_qkv_mma(const float* __restrict__ x, const float* __restrict__ cx,
             const float* __restrict__ Wq, const float* __restrict__ bq,
             const float* __restrict__ Wk, const float* __restrict__ bk,
             const float* __restrict__ Wv, const float* __restrict__ bv)
{
    extern __shared__ unsigned char psm[];
    unsigned char* Wh = psm;
    unsigned char* Bh = psm + 128 * PW_STRIDE;

    const int tid = threadIdx.x, w = tid >> 5, lane = tid & 31;
    const int n0 = blockIdx.x * 128, b = blockIdx.y, wh = blockIdx.z;
    const float *W, *bias, *inb;
    if (wh == 0)      { W = Wq; bias = bq; inb = x  + (size_t)b * CC * NT; }
    else if (wh == 1) { W = Wk; bias = bk; inb = cx + (size_t)b * CC * NT; }
    else              { W = Wv; bias = bv; inb = cx + (size_t)b * CC * NT; }

#pragma unroll
    for (int it = 0; it < 16; ++it) {
        const int idx = tid + it * 256;
        const int m = idx >> 5, c4 = idx & 31;
        float4 ww = *(const float4*)(W + m * 128 + c4 * 4);
        *(uint2*)(Wh + m * PW_STRIDE + c4 * 8) =
            make_uint2(packbf(ww.x, ww.y), packbf(ww.z, ww.w));
    }
#pragma unroll
    for (int it = 0; it < 16; ++it) {
        const int idx = tid + it * 256;
        const int c = idx >> 5, c4 = idx & 31;
        float4 v = *(const float4*)(inb + (size_t)c * NT + n0 + c4 * 4);
        *(uint2*)(Bh + c * PW_STRIDE + c4 * 8) =
            make_uint2(packbf(v.x, v.y), packbf(v.z, v.w));
    }
    __syncthreads();

    const uint32_t uWh = smem_u32(Wh), uBh = smem_u32(Bh);
    uint32_t A[8][4];
    {
        const int q = lane >> 3, r = lane & 7;
#pragma unroll
        for (int ks = 0; ks < 8; ++ks)
            ldsm4(A[ks][0], A[ks][1], A[ks][2], A[ks][3],
                  uWh + (w * 16 + (q & 1) * 8 + r) * PW_STRIDE
                      + (ks * 16 + (q >> 1) * 8) * 2);
    }
    const int g = lane >> 2, tq = lane & 3;
    const int m0 = w * 16 + g, m1 = m0 + 8;
    const float bb0 = bias[m0], bb1 = bias[m1];

#pragma unroll
    for (int nh = 0; nh < 2; ++nh) {
        float acc[8][4];
#pragma unroll
        for (int nt = 0; nt < 8; ++nt)
            acc[nt][0] = acc[nt][1] = acc[nt][2] = acc[nt][3] = 0.f;
#pragma unroll
        for (int nt = 0; nt < 8; ++nt) {
            const uint32_t colb = nh * 128 + nt * 16;
#pragma unroll
            for (int cb = 0; cb < 4; ++cb) {
                uint32_t b0, b1, b2, b3;
                ldsm4t(b0, b1, b2, b3, uBh + (cb * 32 + lane) * PW_STRIDE + colb);
                mma16816(acc[nt], A[2*cb][0], A[2*cb][1], A[2*cb][2], A[2*cb][3], b0, b1);
                mma16816(acc[nt], A[2*cb+1][0], A[2*cb+1][1], A[2*cb+1][2], A[2*cb+1][3], b2, b3);
            }
        }
        if (wh == 2) {
            __nv_bfloat16* vb = g_vb + (size_t)(b * CC) * NT;
#pragma unroll
            for (int nt = 0; nt < 8; ++nt) {
                const int n = n0 + nh * 64 + nt * 8 + tq * 2;
                *(uint32_t*)(vb + (size_t)m0 * NT + n) = packbf(acc[nt][0] + bb0, acc[nt][1] + bb0);
                *(uint32_t*)(vb + (size_t)m1 * NT + n) = packbf(acc[nt][2] + bb1, acc[nt][3] + bb1);
            }
        } else {
            float* og = (wh == 0 ? g_q : g_k) + (size_t)(b * CC) * NT;
#pragma unroll
            for (int nt = 0; nt < 8; ++nt) {
                const int n = n0 + nh * 64 + nt * 8 + tq * 2;
                *(float2*)(og + (size_t)m0 * NT + n) = make_float2(acc[nt][0] + bb0, acc[nt][1] + bb0);
                *(float2*)(og + (size_t)m1 * NT + n) = make_float2(acc[nt][2] + bb1, acc[nt][3] + bb1);
            }
        }
    }
}

// proj_out: 3-pass hi/lo (output precision) — unchanged from R12
__global__ void __launch_bounds__(256, 2)
proj_out_mma(const float* __restrict__ Wo, const float* __restrict__ bo,
             float* __restrict__ out)
{
    extern __shared__ unsigned char psm[];
    unsigned char* Wh = psm;
    unsigned char* Wl = psm + 128 * PW_STRIDE;
    unsigned char* Bh = Wl + 128 * PW_STRIDE;
    unsigned char* Bl = Bh + 128 * PB64_STRIDE;

    const int tid = threadIdx.x, w = tid >> 5, lane = tid & 31;
    const int n0 = blockIdx.x * 64, b = blockIdx.y;
    const float* inb = g_att + (size_t)b * CC * NT;

#pragma unroll
    for (int it = 0; it < 16; ++it) {
        const int idx = tid + it * 256;
        const int m = idx >> 5, c4 = idx & 31;
        float4 ww = *(const float4*)(Wo + m * 128 + c4 * 4);
        uint32_t h0 = packbf(ww.x, ww.y), h1 = packbf(ww.z, ww.w);
        float l0 = ww.x - __uint_as_float(h0 << 16);
        float l1 = ww.y - __uint_as_float(h0 & 0xffff0000u);
        float l2 = ww.z - __uint_as_float(h1 << 16);
        float l3 = ww.w - __uint_as_float(h1 & 0xffff0000u);
        *(uint2*)(Wh + m * PW_STRIDE + c4 * 8) = make_uint2(h0, h1);
        *(uint2*)(Wl + m * PW_STRIDE + c4 * 8) =
            make_uint2(packbf(l0, l1), packbf(l2, l3));
    }
#pragma unroll
    for (int it = 0; it < 8; ++it) {
        const int idx = tid + it * 256;
        const int c = idx >> 4, c4 = idx & 15;
        float4 v = *(const float4*)(inb + (size_t)c * NT + n0 + c4 * 4);
        uint32_t h0 = packbf(v.x, v.y), h1 = packbf(v.z, v.w);
        float l0 = v.x - __uint_as_float(h0 << 16);
        float l1 = v.y - __uint_as_float(h0 & 0xffff0000u);
        float l2 = v.z - __uint_as_float(h1 << 16);
        float l3 = v.w - __uint_as_float(h1 & 0xffff0000u);
        *(uint2*)(Bh + c * PB64_STRIDE + c4 * 8) = make_uint2(h0, h1);
        *(uint2*)(Bl + c * PB64_STRIDE + c4 * 8) =
            make_uint2(packbf(l0, l1), packbf(l2, l3));
    }
    __syncthreads();

    const uint32_t uWh = smem_u32(Wh), uWl = smem_u32(Wl);
    const uint32_t uBh = smem_u32(Bh), uBl = smem_u32(Bl);
    uint32_t Ah[8][4], Al[8][4];
    {
        const int q = lane >> 3, r = lane & 7;
#pragma unroll
        for (int ks = 0; ks < 8; ++ks) {
            const uint32_t off = (w * 16 + (q & 1) * 8 + r) * PW_STRIDE
                               + (ks * 16 + (q >> 1) * 8) * 2;
            ldsm4(Ah[ks][0], Ah[ks][1], Ah[ks][2], Ah[ks][3], uWh + off);
            ldsm4(Al[ks][0], Al[ks][1], Al[ks][2], Al[ks][3], uWl + off);
        }
    }
    float acc[8][4];
#pragma unroll
    for (int nt = 0; nt < 8; ++nt)
        acc[nt][0] = acc[nt][1] = acc[nt][2] = acc[nt][3] = 0.f;

#pragma unroll
    for (int nt = 0; nt < 8; ++nt) {
        const uint32_t colb = nt * 16;
#pragma unroll
        for (int cb = 0; cb < 4; ++cb) {
            uint32_t b0, b1, b2, b3;
            ldsm4t(b0, b1, b2, b3, uBh + (cb * 32 + lane) * PB64_STRIDE + colb);
            mma16816(acc[nt], Ah[2*cb][0], Ah[2*cb][1], Ah[2*cb][2], Ah[2*cb][3], b0, b1);
            mma16816(acc[nt], Ah[2*cb+1][0], Ah[2*cb+1][1], Ah[2*cb+1][2], Ah[2*cb+1][3], b2, b3);
        }
#pragma unroll
        for (int cb = 0; cb < 4; ++cb) {
            uint32_t b0, b1, b2, b3;
            ldsm4t(b0, b1, b2, b3, uBl + (cb * 32 + lane) * PB64_STRIDE + colb);
            mma16816(acc[nt], Ah[2*cb][0], Ah[2*cb][1], Ah[2*cb][2], Ah[2*cb][3], b0, b1);
            mma16816(acc[nt], Ah[2*cb+1][0], Ah[2*cb+1][1], Ah[2*cb+1][2], Ah[2*cb+1][3], b2, b3);
        }
#pragma unroll
        for (int cb = 0; cb < 4; ++cb) {
            uint32_t b0, b1, b2, b3;
            ldsm4t(b0, b1, b2, b3, uBh + (cb * 32 + lane) * PB64_STRIDE + colb);
            mma16816(acc[nt], Al[2*cb][0], Al[2*cb][1], Al[2*cb][2], Al[2*cb][3], b0, b1);
            mma16816(acc[nt], Al[2*cb+1][0], Al[2*cb+1][1], Al[2*cb+1][2], Al[2*cb+1][3], b2, b3);
        }
    }
    const int g = lane >> 2, tq = lane & 3;
    const int m0 = w * 16 + g, m1 = m0 + 8;
    const float bb0 = bo[m0], bb1 = bo[m1];
    float* og = out + (size_t)(b * CC) * NT;
#pragma unroll
    for (int nt = 0; nt < 8; ++nt) {
        const int n = n0 + nt * 8 + tq * 2;
        *(float2*)(og + (size_t)m0 * NT + n) = make_float2(acc[nt][0] + bb0, acc[nt][1] + bb0);
        *(float2*)(og + (size_t)m1 * NT + n) = make_float2(acc[nt][2] + bb1, acc[nt][3] + bb1);
    }
}

// =============================== norm / colsum ===============================
__global__ void __launch_bounds__(256, 1) norm_kernel()
{
    const int row = blockIdx.x;
    const float* p = (blockIdx.y == 0 ? g_q : g_k) + (size_t)row * NT;
    __nv_bfloat16* ob = (blockIdx.y == 0 ? g_qb : g_kb) + (size_t)row * NT;
    const int tid = threadIdx.x;

    float4 v[4];
    float s = 0.f;
#pragma unroll
    for (int it = 0; it < 4; ++it) {
        v[it] = ((const float4*)p)[tid + it * 256];
        s += v[it].x * v[it].x + v[it].y * v[it].y +
             v[it].z * v[it].z + v[it].w * v[it].w;
    }
#pragma unroll
    for (int o = 16; o > 0; o >>= 1) s += __shfl_xor_sync(0xffffffffu, s, o);

    __shared__ float red[8];
    if ((tid & 31) == 0) red[tid >> 5] = s;
    __syncthreads();
    if (tid < 32) {
        float vv = (tid < 8) ? red[tid] : 0.f;
#pragma unroll
        for (int o = 4; o > 0; o >>= 1) vv += __shfl_xor_sync(0xffffffffu, vv, o);
        if (tid == 0) red[0] = vv;
    }
    __syncthreads();
    const float scl = (blockIdx.y == 0 ? SCALE_F : 1.0f) /
                      fmaxf(sqrtf(red[0]), 1e-12f);
#pragma unroll
    for (int it = 0; it < 4; ++it) {
        ((uint2*)ob)[tid + it * 256] =
            make_uint2(packbf(v[it].x * scl, v[it].y * scl),
                       packbf(v[it].z * scl, v[it].w * scl));
    }
}

__global__ void __launch_bounds__(256, 1) colsum_kernel(const float* __restrict__ cx)
{
    const int row = blockIdx.x;
    const float* p = cx + (size_t)row * NT;
    const int tid = threadIdx.x;
    float s = 0.f;
#pragma unroll
    for (int it = 0; it < 4; ++it) {
        float4 v = ((const float4*)p)[tid + it * 256];
        s += v.x + v.y + v.z + v.w;
    }
#pragma unroll
    for (int o = 16; o > 0; o >>= 1) s += __shfl_xor_sync(0xffffffffu, s, o);
    __shared__ float red[8];
    if ((tid & 31) == 0) red[tid >> 5] = s;
    __syncthreads();
    if (tid == 0)
        g_colsum[row] = red[0] + red[1] + red[2] + red[3] +
                        red[4] + red[5] + red[6] + red[7];
}

// ===== Stage B: G[F,e] = phi^T [v;1] — A fragments generated in registers ====
__global__ void __launch_bounds__(256, 3) stageB_kernel()
{
    extern __shared__ unsigned char sm[];
    unsigned char* Kt0 = sm;              // 34 rows x TS
    unsigned char* Kt1 = sm + 34 * TS;
    unsigned char* Vt0 = sm + 2 * 34 * TS;  // 40 rows x TS
    unsigned char* Vt1 = Vt0 + 40 * TS;

    const int tid = threadIdx.x, w = tid >> 5, lane = tid & 31;
    const int fb = blockIdx.x >> 3, js = blockIdx.x & 7;
    const int bh = blockIdx.y;
    const int cbase = (bh >> 2) * CC + (bh & 3) * DH;
    const __nv_bfloat16* kg = g_kb + (size_t)cbase * NT;
    const __nv_bfloat16* vg = g_vb + (size_t)cbase * NT;
    const int j0 = js * (NT / JSPLIT);

    const uint32_t ONE2 = packbf(1.f, 1.f);
    const int g = lane >> 2, tq = lane & 3;

    // per-lane feature rows (constant across tiles)
    int aLo, bLo, aHi, bHi;
    fdec(fb * 128 + w * 16 + g, aLo, bLo);
    fdec(fb * 128 + w * 16 + g + 8, aHi, bHi);

    // constant rows in both buffers
    for (int i = tid; i < 2 * 64; i += 256) {
        unsigned char* Kb = (i >> 6) ? Kt1 : Kt0;
        unsigned char* Vb = (i >> 6) ? Vt1 : Vt0;
        const int c = i & 63;
        *(uint32_t*)(Kb + 32 * TS + c * 4) = ONE2;
        *(uint32_t*)(Kb + 33 * TS + c * 4) = 0u;
        *(uint32_t*)(Vb + 32 * TS + c * 4) = ONE2;
#pragma unroll
        for (int z = 33; z < 40; ++z) *(uint32_t*)(Vb + z * TS + c * 4) = 0u;
    }

    const uint32_t uK[2] = { smem_u32(Kt0), smem_u32(Kt1) };
    const uint32_t uV[2] = { smem_u32(Vt0), smem_u32(Vt1) };

    {
#pragma unroll
        for (int r = 0; r < 4; ++r) {
            const int idx = tid + r * 256;
            const int d = idx >> 5, pr = idx & 31;
            const int ch = pr & 15;
            if ((pr >> 4) == 0)
                cp16(uK[0] + d * TS + ch * 16, kg + (size_t)d * NT + j0 + ch * 8);
            else
                cp16(uV[0] + d * TS + ch * 16, vg + (size_t)d * NT + j0 + ch * 8);
        }
        asm volatile("cp.async.commit_group;" ::: "memory");
    }

    float acc[5][4];
#pragma unroll
    for (int nt = 0; nt < 5; ++nt)
        acc[nt][0] = acc[nt][1] = acc[nt][2] = acc[nt][3] = 0.f;

    const int lq = lane >> 3, lr = lane & 7;

    for (int t = 0; t < NT / JSPLIT / 128; ++t) {
        asm volatile("cp.async.wait_group 0;" ::: "memory");
        __syncthreads();   // tile t ready; prior tile's buffer fully consumed

        if (t < NT / JSPLIT / 128 - 1) {
            const int nb = (t + 1) & 1;
            const int jn = j0 + (t + 1) * 128;
#pragma unroll
            for (int r = 0; r < 4; ++r) {
                const int idx = tid + r * 256;
                const int d = idx >> 5, pr = idx & 31;
                const int ch = pr & 15;
                if ((pr >> 4) == 0)
                    cp16(uK[nb] + d * TS + ch * 16, kg + (size_t)d * NT + jn + ch * 8);
                else
                    cp16(uV[nb] + d * TS + ch * 16, vg + (size_t)d * NT + jn + ch * 8);
            }
            asm volatile("cp.async.commit_group;" ::: "memory");
        }

        const unsigned char* Ks = (t & 1) ? Kt1 : Kt0;
        const unsigned char* rAlo = Ks + aLo * TS;
        const unsigned char* rBlo = Ks + bLo * TS;
        const unsigned char* rAhi = Ks + aHi * TS;
        const unsigned char* rBhi = Ks + bHi * TS;
        const uint32_t uVs = uV[t & 1];

#pragma unroll
        for (int ug = 0; ug < 4; ++ug) {
            // direct A fragments: phi[F row][j col] = k_a * k_b (w applied in greduce)
            uint32_t A0[4], A1[4];
            {
                const int cb0 = (ug * 32 + 2 * tq) * 2;       // ks=0 colbase byte
                A0[0] = bffma2(*(const uint32_t*)(rAlo + cb0),
                               *(const uint32_t*)(rBlo + cb0), 0u);
                A0[1] = bffma2(*(const uint32_t*)(rAhi + cb0),
                               *(const uint32_t*)(rBhi + cb0), 0u);
                A0[2] = bffma2(*(const uint32_t*)(rAlo + cb0 + 16),
                               *(const uint32_t*)(rBlo + cb0 + 16), 0u);
                A0[3] = bffma2(*(const uint32_t*)(rAhi + cb0 + 16),
                               *(const uint32_t*)(rBhi + cb0 + 16), 0u);
                const int cb1 = cb0 + 32;                     // ks=1 colbase byte
                A1[0] = bffma2(*(const uint32_t*)(rAlo + cb1),
                               *(const uint32_t*)(rBlo + cb1), 0u);
                A1[1] = bffma2(*(const uint32_t*)(rAhi + cb1),
                               *(const uint32_t*)(rBhi + cb1), 0u);
                A1[2] = bffma2(*(const uint32_t*)(rAlo + cb1 + 16),
                               *(const uint32_t*)(rBlo + cb1 + 16), 0u);
                A1[3] = bffma2(*(const uint32_t*)(rAhi + cb1 + 16),
                               *(const uint32_t*)(rBhi + cb1 + 16), 0u);
            }
#pragma unroll
            for (int nt = 0; nt < 5; ++nt) {
                uint32_t b0, b1, b2, b3;
                ldsm4(b0, b1, b2, b3,
                      uVs + (nt * 8 + lr) * TS + (ug * 4 + lq) * 16);
                mma16816(acc[nt], A0[0], A0[1], A0[2], A0[3], b0, b1);
                mma16816(acc[nt], A1[0], A1[1], A1[2], A1[3], b2, b3);
            }
        }
    }

    const int fr0 = fb * 128 + w * 16 + g, fr1 = fr0 + 8;
    float* Gp = g_G2 + (size_t)(bh * JSPLIT + js) * NE * NF;
#pragma unroll
    for (int nt = 0; nt < 5; ++nt) {
        const int e0 = nt * 8 + 2 * tq;
        Gp[(size_t)e0 * NF + fr0]       = acc[nt][0];
        Gp[(size_t)(e0 + 1) * NF + fr0] = acc[nt][1];
        Gp[(size_t)e0 * NF + fr1]       = acc[nt][2];
        Gp[(size_t)(e0 + 1) * NF + fr1] = acc[nt][3];
    }
}

// reduce JSPLIT partials -> bf16 G, applying the diag 1/2 feature weight here
__global__ void __launch_bounds__(256, 4) greduce_kernel()
{
    const int o = (blockIdx.x * 256 + threadIdx.x) * 2;
    const int bh = o / (NE * NF);
    const int r = o - bh * (NE * NF);
    const int f = r % NF;
    const float* p = g_G2 + (size_t)bh * JSPLIT * NE * NF + r;
    float s0 = 0.f, s1 = 0.f;
#pragma unroll
    for (int js = 0; js < JSPLIT; ++js) {
        s0 += p[(size_t)js * NE * NF];
        s1 += p[(size_t)js * NE * NF + 1];
    }
    s0 *= fweight(f);
    s1 *= fweight(f + 1);
    *(uint32_t*)(g_Gb + o) = packbf(s0, s1);
}

// ===================== Stage C: Odev = Psi(q) G + epilogue ===================
__global__ void __launch_bounds__(256, 2)
stageC_kernel(const float* __restrict__ Wv, const float* __restrict__ bv)
{
    extern __shared__ unsigned char sm[];
    unsigned char* Qt  = sm;
    unsigned char* Psi = Qt + 34 * TS;
    unsigned char* Gs  = Psi + 128 * TS;
    uint32_t* lut      = (uint32_t*)(Gs + NE * GSS);
    float* svs         = (float*)(lut + NF);
    float* rd          = svs + 32;

    const int tid = threadIdx.x, w = tid >> 5, lane = tid & 31;
    const int i0 = blockIdx.x * 128;
    const int bh = blockIdx.y;
    const int b = bh >> 2, hh = bh & 3;
    const int cbase = b * CC + hh * DH;
    const __nv_bfloat16* qg = g_qb + (size_t)cbase * NT;

    const uint32_t ONE2 = packbf(1.f, 1.f);
    build_lut(lut, tid);
    for (int c = tid; c < 64; c += 256) {
        *(uint32_t*)(Qt + 32 * TS + c * 4) = ONE2;
        *(uint32_t*)(Qt + 33 * TS + c * 4) = 0u;
    }

    const uint32_t uQt = smem_u32(Qt), uPsi = smem_u32(Psi), uGs = smem_u32(Gs);

    {
#pragma unroll
        for (int r = 0; r < 2; ++r) {
            const int idx = tid + r * 256;
            const int d = idx >> 4, ch = idx & 15;
            cp16(uQt + d * TS + ch * 16, qg + (size_t)d * NT + i0 + ch * 8);
        }
        const __nv_bfloat16* Gp = g_Gb + (size_t)bh * NE * NF;
        for (int idx = tid; idx < NE * (NF / 8); idx += 256) {
            const int e = idx / (NF / 8), c = idx % (NF / 8);
            cp16(uGs + e * GSS + c * 16, Gp + (size_t)e * NF + c * 8);
        }
        asm volatile("cp.async.commit_group;" ::: "memory");
        asm volatile("cp.async.wait_group 0;" ::: "memory");
    }
    __syncthreads();

    float acc[5][4];
#pragma unroll
    for (int nt = 0; nt < 5; ++nt)
        acc[nt][0] = acc[nt][1] = acc[nt][2] = acc[nt][3] = 0.f;

    const int lq = lane >> 3, lr = lane & 7;

    for (int fbi = 0; fbi < NFB; ++fbi) {
        if (fbi > 0) __syncthreads();
        {   // psi generation — warp-per-row, conflict-free
#pragma unroll
            for (int r = 0; r < 16; ++r) {
                const int row = w * 16 + r;
                const uint32_t e = lut[fbi * 128 + row];
                const int a = e & 0xff, b2 = (e >> 8) & 0xff;
                uint2 qa = *(const uint2*)(Qt + a * TS + lane * 8);
                uint2 qb = *(const uint2*)(Qt + b2 * TS + lane * 8);
                uint2 ps;
                ps.x = bffma2(qa.x, qb.x, 0u);
                ps.y = bffma2(qa.y, qb.y, 0u);
                *(uint2*)(Psi + row * TS + lane * 8) = ps;
            }
        }
        __syncthreads();

#pragma unroll
        for (int ug = 0; ug < 4; ++ug) {
            uint32_t A0[4], A1[4];
            ldsm4t(A0[0], A0[1], A0[2], A0[3],
                   uPsi + ((2 * ug) * 16 + ((lane >> 4) << 3) + (lane & 7)) * TS
                        + (w * 16 + ((lane >> 3) & 1) * 8) * 2);
            ldsm4t(A1[0], A1[1], A1[2], A1[3],
                   uPsi + ((2 * ug + 1) * 16 + ((lane >> 4) << 3) + (lane & 7)) * TS
                        + (w * 16 + ((lane >> 3) & 1) * 8) * 2);
#pragma unroll
            for (int nt = 0; nt < 5; ++nt) {
                uint32_t b0, b1, b2, b3;
                ldsm4(b0, b1, b2, b3,
                      uGs + (nt * 8 + lr) * GSS + fbi * 256 + (ug * 4 + lq) * 16);
                mma16816(acc[nt], A0[0], A0[1], A0[2], A0[3], b0, b1);
                mma16816(acc[nt], A1[0], A1[1], A1[2], A1[3], b2, b3);
            }
        }
    }

    {   // sumv
#pragma unroll
        for (int mi = 0; mi < 4; ++mi) {
            const int d = w * 4 + mi;
            const int m = hh * DH + d;
            float s = 0.f;
#pragma unroll
            for (int c4 = 0; c4 < 4; ++c4)
                s += Wv[m * 128 + c4 * 32 + lane] * g_colsum[b * CC + c4 * 32 + lane];
#pragma unroll
            for (int o = 16; o > 0; o >>= 1) s += __shfl_xor_sync(0xffffffffu, s, o);
            if (lane == 0) svs[d] = s + (float)NT * bv[m];
        }
    }
    const int g = lane >> 2, tq = lane & 3;
    if (tq == 0) {
        rd[w * 16 + g]     = acc[4][0];
        rd[w * 16 + g + 8] = acc[4][2];
    }
    __syncthreads();

    const int r0 = w * 16 + g, r1 = r0 + 8;
    const float inv0 = 1.0f / (4096.0f + rd[r0]);
    const float inv1 = 1.0f / (4096.0f + rd[r1]);
    float* att = g_att + (size_t)cbase * NT;
#pragma unroll
    for (int nt = 0; nt < 4; ++nt) {
        const int e0 = nt * 8 + 2 * tq;
        const float s0 = svs[e0], s1 = svs[e0 + 1];
        att[(size_t)e0 * NT + i0 + r0]       = (acc[nt][0] + s0) * inv0;
        att[(size_t)(e0 + 1) * NT + i0 + r0] = (acc[nt][1] + s1) * inv0;
        att[(size_t)e0 * NT + i0 + r1]       = (acc[nt][2] + s0) * inv1;
        att[(size_t)(e0 + 1) * NT + i0 + r1] = (acc[nt][3] + s1) * inv1;
    }
}

// ================================== launch ===================================
extern "C" void kernel_launch(void* const* d_in, const int* in_sizes, int n_in,
                              void* d_out, int out_size)
{
    (void)in_sizes; (void)n_in; (void)out_size;
    const float* x  = (const float*)d_in[0];
    const float* cx = (const float*)d_in[1];
    const float* Wq = (const float*)d_in[2];
    const float* bq = (const float*)d_in[3];
    const float* Wk = (const float*)d_in[4];
    const float* bk = (const float*)d_in[5];
    const float* Wv = (const float*)d_in[6];
    const float* bv = (const float*)d_in[7];
    const float* Wo = (const float*)d_in[8];
    const float* bo = (const float*)d_in[9];
    float* out = (float*)d_out;

    const int QKV_SMEM = 2 * 128 * PW_STRIDE;
    const int OUT_SMEM = 2 * 128 * PW_STRIDE + 2 * 128 * PB64_STRIDE;
    const int SB_SMEM  = 2 * 34 * TS + 2 * 40 * TS;
    const int SC_SMEM  = 34 * TS + 128 * TS + NE * GSS + NF * 4 + 160 * 4;

    cudaFuncSetAttribute(proj_qkv_mma, cudaFuncAttributeMaxDynamicSharedMemorySize, QKV_SMEM);
    cudaFuncSetAttribute(proj_out_mma, cudaFuncAttributeMaxDynamicSharedMemorySize, OUT_SMEM);
    cudaFuncSetAttribute(stageB_kernel, cudaFuncAttributeMaxDynamicSharedMemorySize, SB_SMEM);
    cudaFuncSetAttribute(stageC_kernel, cudaFuncAttributeMaxDynamicSharedMemorySize, SC_SMEM);

    proj_qkv_mma<<<dim3(NT / 128, BB, 3), 256, QKV_SMEM>>>(x, cx, Wq, bq, Wk, bk, Wv, bv);
    colsum_kernel<<<dim3(BB * CC), 256>>>(cx);
    norm_kernel<<<dim3(BB * CC, 2), 256>>>();
    stageB_kernel<<<dim3(NFB * JSPLIT, BB * NH), 256, SB_SMEM>>>();
    greduce_kernel<<<dim3(8 * NE * NF / 512), 256>>>();
    stageC_kernel<<<dim3(NT / 128, BB * NH), 256, SC_SMEM>>>(Wv, bv);
    proj_out_mma<<<dim3(NT / 64, BB), 256, OUT_SMEM>>>(Wo, bo, out);
}

// round 14
// speedup vs baseline: 2.3888x; 1.0806x over previous
#include <cuda_runtime.h>
#include <cuda_bf16.h>
#include <cstdint>
#include <math.h>

#define BB 2
#define CC 128
#define NH 4
#define DH 32
#define NT 4096
#define SCALE_F 10.0f

#define NF 640
#define NFB 5
#define NE 40
#define TS 272
#define GSS 1296
#define JSPLIT 16

static __device__ __nv_bfloat16 g_qb[BB * CC * NT];   // pre-norm bf16, scaled in-place
static __device__ __nv_bfloat16 g_kb[BB * CC * NT];
static __device__ __nv_bfloat16 g_vb[BB * CC * NT];
static __device__ float g_att[BB * CC * NT];
static __device__ float g_colsum[BB * CC];
static __device__ float g_nsq[2][BB * CC][32];        // sumsq partials per 128-tile
static __device__ float g_G2[8 * JSPLIT * NE * NF];
static __device__ __nv_bfloat16 g_Gb[8 * NE * NF];

// ---------------------------------------------------------------- helpers ----
__device__ __forceinline__ uint32_t smem_u32(const void* p) {
    uint32_t a;
    asm("{ .reg .u64 t; cvta.to.shared.u64 t, %1; cvt.u32.u64 %0, t; }"
        : "=r"(a) : "l"(p));
    return a;
}
__device__ __forceinline__ uint32_t packbf(float a, float b) {
    uint32_t r;
    asm("cvt.rn.bf16x2.f32 %0, %2, %1;" : "=r"(r) : "f"(a), "f"(b));
    return r;
}
__device__ __forceinline__ uint32_t bffma2(uint32_t a, uint32_t b, uint32_t c) {
    uint32_t d;
    asm("fma.rn.bf16x2 %0, %1, %2, %3;" : "=r"(d) : "r"(a), "r"(b), "r"(c));
    return d;
}
__device__ __forceinline__ void ldsm4(uint32_t& r0, uint32_t& r1, uint32_t& r2,
                                      uint32_t& r3, uint32_t addr) {
    asm volatile("ldmatrix.sync.aligned.m8n8.x4.shared.b16 {%0,%1,%2,%3}, [%4];"
                 : "=r"(r0), "=r"(r1), "=r"(r2), "=r"(r3) : "r"(addr));
}
__device__ __forceinline__ void ldsm4t(uint32_t& r0, uint32_t& r1, uint32_t& r2,
                                       uint32_t& r3, uint32_t addr) {
    asm volatile("ldmatrix.sync.aligned.m8n8.x4.trans.shared.b16 {%0,%1,%2,%3}, [%4];"
                 : "=r"(r0), "=r"(r1), "=r"(r2), "=r"(r3) : "r"(addr));
}
__device__ __forceinline__ void mma16816(float* c, uint32_t a0, uint32_t a1,
                                         uint32_t a2, uint32_t a3,
                                         uint32_t b0, uint32_t b1) {
    asm volatile(
        "mma.sync.aligned.m16n8k16.row.col.f32.bf16.bf16.f32 "
        "{%0,%1,%2,%3}, {%4,%5,%6,%7}, {%8,%9}, {%0,%1,%2,%3};"
        : "+f"(c[0]), "+f"(c[1]), "+f"(c[2]), "+f"(c[3])
        : "r"(a0), "r"(a1), "r"(a2), "r"(a3), "r"(b0), "r"(b1));
}
__device__ __forceinline__ void cp16(uint32_t dst, const void* src) {
    asm volatile("cp.async.cg.shared.global [%0], [%1], 16;"
                 :: "r"(dst), "l"(src) : "memory");
}

__device__ __forceinline__ void fdec(int f, int& a, int& b) {
    if (f < 32) { a = f; b = 32; }
    else if (f < 560) {
        int p = f - 32, aa = 0;
        while (p >= 32 - aa) { p -= 32 - aa; ++aa; }
        a = aa; b = aa + p;
    } else { a = 33; b = 33; }
}
__device__ __forceinline__ float fweight(int f) {
    if (f < 32) return 1.0f;
    if (f >= 560) return 0.0f;
    int a, b; fdec(f, a, b);
    return (a == b) ? 0.5f : 1.0f;
}
__device__ __forceinline__ void build_lut(uint32_t* lut, int tid) {
    for (int f = tid; f < NF; f += 256) {
        int a, b; fdec(f, a, b);
        lut[f] = (uint32_t)a | ((uint32_t)b << 8);
    }
}

// ============================= projections ===================================
#define PW_STRIDE 272
#define PB64_STRIDE 144

// qkv: single-pass bf16 GEMM; q/k written bf16 pre-norm + fp32 sumsq partials
__global__ void __launch_bounds__(256, 2)
proj_qkv_mma(const float* __restrict__ x, const float* __restrict__ cx,
             const float* __restrict__ Wq, const float* __restrict__ bq,
             const float* __restrict__ Wk, const float* __restrict__ bk,
             const float* __restrict__ Wv, const float* __restrict__ bv)
{
    extern __shared__ unsigned char psm[];
    unsigned char* Wh = psm;
    unsigned char* Bh = psm + 128 * PW_STRIDE;

    const int tid = threadIdx.x, w = tid >> 5, lane = tid & 31;
    const int n0 = blockIdx.x * 128, b = blockIdx.y, wh = blockIdx.z;
    const float *W, *bias, *inb;
    if (wh == 0)      { W = Wq; bias = bq; inb = x  + (size_t)b * CC * NT; }
    else if (wh == 1) { W = Wk; bias = bk; inb = cx + (size_t)b * CC * NT; }
    else              { W = Wv; bias = bv; inb = cx + (size_t)b * CC * NT; }

#pragma unroll
    for (int it = 0; it < 16; ++it) {
        const int idx = tid + it * 256;
        const int m = idx >> 5, c4 = idx & 31;
        float4 ww = *(const float4*)(W + m * 128 + c4 * 4);
        *(uint2*)(Wh + m * PW_STRIDE + c4 * 8) =
            make_uint2(packbf(ww.x, ww.y), packbf(ww.z, ww.w));
    }
#pragma unroll
    for (int it = 0; it < 16; ++it) {
        const int idx = tid + it * 256;
        const int c = idx >> 5, c4 = idx & 31;
        float4 v = *(const float4*)(inb + (size_t)c * NT + n0 + c4 * 4);
        *(uint2*)(Bh + c * PW_STRIDE + c4 * 8) =
            make_uint2(packbf(v.x, v.y), packbf(v.z, v.w));
    }
    __syncthreads();

    const uint32_t uWh = smem_u32(Wh), uBh = smem_u32(Bh);
    uint32_t A[8][4];
    {
        const int q = lane >> 3, r = lane & 7;
#pragma unroll
        for (int ks = 0; ks < 8; ++ks)
            ldsm4(A[ks][0], A[ks][1], A[ks][2], A[ks][3],
                  uWh + (w * 16 + (q & 1) * 8 + r) * PW_STRIDE
                      + (ks * 16 + (q >> 1) * 8) * 2);
    }
    const int g = lane >> 2, tq = lane & 3;
    const int m0 = w * 16 + g, m1 = m0 + 8;
    const float bb0 = bias[m0], bb1 = bias[m1];
    float sq0 = 0.f, sq1 = 0.f;

    __nv_bfloat16* qkout = (wh == 0 ? g_qb : g_kb) + (size_t)(b * CC) * NT;
    __nv_bfloat16* vout  = g_vb + (size_t)(b * CC) * NT;

#pragma unroll
    for (int nh = 0; nh < 2; ++nh) {
        float acc[8][4];
#pragma unroll
        for (int nt = 0; nt < 8; ++nt)
            acc[nt][0] = acc[nt][1] = acc[nt][2] = acc[nt][3] = 0.f;
#pragma unroll
        for (int nt = 0; nt < 8; ++nt) {
            const uint32_t colb = nh * 128 + nt * 16;
#pragma unroll
            for (int cb = 0; cb < 4; ++cb) {
                uint32_t b0, b1, b2, b3;
                ldsm4t(b0, b1, b2, b3, uBh + (cb * 32 + lane) * PW_STRIDE + colb);
                mma16816(acc[nt], A[2*cb][0], A[2*cb][1], A[2*cb][2], A[2*cb][3], b0, b1);
                mma16816(acc[nt], A[2*cb+1][0], A[2*cb+1][1], A[2*cb+1][2], A[2*cb+1][3], b2, b3);
            }
        }
#pragma unroll
        for (int nt = 0; nt < 8; ++nt) {
            const int n = n0 + nh * 64 + nt * 8 + tq * 2;
            const float v0 = acc[nt][0] + bb0, v1 = acc[nt][1] + bb0;
            const float v2 = acc[nt][2] + bb1, v3 = acc[nt][3] + bb1;
            if (wh == 2) {
                *(uint32_t*)(vout + (size_t)m0 * NT + n) = packbf(v0, v1);
                *(uint32_t*)(vout + (size_t)m1 * NT + n) = packbf(v2, v3);
            } else {
                *(uint32_t*)(qkout + (size_t)m0 * NT + n) = packbf(v0, v1);
                *(uint32_t*)(qkout + (size_t)m1 * NT + n) = packbf(v2, v3);
                sq0 += v0 * v0 + v1 * v1;
                sq1 += v2 * v2 + v3 * v3;
            }
        }
    }
    if (wh < 2) {
        // reduce over tq quad (lanes g*4 + tq)
        sq0 += __shfl_xor_sync(0xffffffffu, sq0, 1);
        sq0 += __shfl_xor_sync(0xffffffffu, sq0, 2);
        sq1 += __shfl_xor_sync(0xffffffffu, sq1, 1);
        sq1 += __shfl_xor_sync(0xffffffffu, sq1, 2);
        if (tq == 0) {
            g_nsq[wh][b * CC + m0][blockIdx.x] = sq0;
            g_nsq[wh][b * CC + m1][blockIdx.x] = sq1;
        }
    }
}

// proj_out: 3-pass hi/lo — unchanged (proven)
__global__ void __launch_bounds__(256, 2)
proj_out_mma(const float* __restrict__ Wo, const float* __restrict__ bo,
             float* __restrict__ out)
{
    extern __shared__ unsigned char psm[];
    unsigned char* Wh = psm;
    unsigned char* Wl = psm + 128 * PW_STRIDE;
    unsigned char* Bh = Wl + 128 * PW_STRIDE;
    unsigned char* Bl = Bh + 128 * PB64_STRIDE;

    const int tid = threadIdx.x, w = tid >> 5, lane = tid & 31;
    const int n0 = blockIdx.x * 64, b = blockIdx.y;
    const float* inb = g_att + (size_t)b * CC * NT;

#pragma unroll
    for (int it = 0; it < 16; ++it) {
        const int idx = tid + it * 256;
        const int m = idx >> 5, c4 = idx & 31;
        float4 ww = *(const float4*)(Wo + m * 128 + c4 * 4);
        uint32_t h0 = packbf(ww.x, ww.y), h1 = packbf(ww.z, ww.w);
        float l0 = ww.x - __uint_as_float(h0 << 16);
        float l1 = ww.y - __uint_as_float(h0 & 0xffff0000u);
        float l2 = ww.z - __uint_as_float(h1 << 16);
        float l3 = ww.w - __uint_as_float(h1 & 0xffff0000u);
        *(uint2*)(Wh + m * PW_STRIDE + c4 * 8) = make_uint2(h0, h1);
        *(uint2*)(Wl + m * PW_STRIDE + c4 * 8) =
            make_uint2(packbf(l0, l1), packbf(l2, l3));
    }
#pragma unroll
    for (int it = 0; it < 8; ++it) {
        const int idx = tid + it * 256;
        const int c = idx >> 4, c4 = idx & 15;
        float4 v = *(const float4*)(inb + (size_t)c * NT + n0 + c4 * 4);
        uint32_t h0 = packbf(v.x, v.y), h1 = packbf(v.z, v.w);
        float l0 = v.x - __uint_as_float(h0 << 16);
        float l1 = v.y - __uint_as_float(h0 & 0xffff0000u);
        float l2 = v.z - __uint_as_float(h1 << 16);
        float l3 = v.w - __uint_as_float(h1 & 0xffff0000u);
        *(uint2*)(Bh + c * PB64_STRIDE + c4 * 8) = make_uint2(h0, h1);
        *(uint2*)(Bl + c * PB64_STRIDE + c4 * 8) =
            make_uint2(packbf(l0, l1), packbf(l2, l3));
    }
    __syncthreads();

    const uint32_t uWh = smem_u32(Wh), uWl = smem_u32(Wl);
    const uint32_t uBh = smem_u32(Bh), uBl = smem_u32(Bl);
    uint32_t Ah[8][4], Al[8][4];
    {
        const int q = lane >> 3, r = lane & 7;
#pragma unroll
        for (int ks = 0; ks < 8; ++ks) {
            const uint32_t off = (w * 16 + (q & 1) * 8 + r) * PW_STRIDE
                               + (ks * 16 + (q >> 1) * 8) * 2;
            ldsm4(Ah[ks][0], Ah[ks][1], Ah[ks][2], Ah[ks][3], uWh + off);
            ldsm4(Al[ks][0], Al[ks][1], Al[ks][2], Al[ks][3], uWl + off);
        }
    }
    float acc[8][4];
#pragma unroll
    for (int nt = 0; nt < 8; ++nt)
        acc[nt][0] = acc[nt][1] = acc[nt][2] = acc[nt][3] = 0.f;

#pragma unroll
    for (int nt = 0; nt < 8; ++nt) {
        const uint32_t colb = nt * 16;
#pragma unroll
        for (int cb = 0; cb < 4; ++cb) {
            uint32_t b0, b1, b2, b3;
            ldsm4t(b0, b1, b2, b3, uBh + (cb * 32 + lane) * PB64_STRIDE + colb);
            mma16816(acc[nt], Ah[2*cb][0], Ah[2*cb][1], Ah[2*cb][2], Ah[2*cb][3], b0, b1);
            mma16816(acc[nt], Ah[2*cb+1][0], Ah[2*cb+1][1], Ah[2*cb+1][2], Ah[2*cb+1][3], b2, b3);
        }
#pragma unroll
        for (int cb = 0; cb < 4; ++cb) {
            uint32_t b0, b1, b2, b3;
            ldsm4t(b0, b1, b2, b3, uBl + (cb * 32 + lane) * PB64_STRIDE + colb);
            mma16816(acc[nt], Ah[2*cb][0], Ah[2*cb][1], Ah[2*cb][2], Ah[2*cb][3], b0, b1);
            mma16816(acc[nt], Ah[2*cb+1][0], Ah[2*cb+1][1], Ah[2*cb+1][2], Ah[2*cb+1][3], b2, b3);
        }
#pragma unroll
        for (int cb = 0; cb < 4; ++cb) {
            uint32_t b0, b1, b2, b3;
            ldsm4t(b0, b1, b2, b3, uBh + (cb * 32 + lane) * PB64_STRIDE + colb);
            mma16816(acc[nt], Al[2*cb][0], Al[2*cb][1], Al[2*cb][2], Al[2*cb][3], b0, b1);
            mma16816(acc[nt], Al[2*cb+1][0], Al[2*cb+1][1], Al[2*cb+1][2], Al[2*cb+1][3], b2, b3);
        }
    }
    const int g = lane >> 2, tq = lane & 3;
    const int m0 = w * 16 + g, m1 = m0 + 8;
    const float bb0 = bo[m0], bb1 = bo[m1];
    float* og = out + (size_t)(b * CC) * NT;
#pragma unroll
    for (int nt = 0; nt < 8; ++nt) {
        const int n = n0 + nt * 8 + tq * 2;
        *(float2*)(og + (size_t)m0 * NT + n) = make_float2(acc[nt][0] + bb0, acc[nt][1] + bb0);
        *(float2*)(og + (size_t)m1 * NT + n) = make_float2(acc[nt][2] + bb1, acc[nt][3] + bb1);
    }
}

// ======== fused norm-scale (y=0 q, y=1 k) + colsum (y=2) =====================
__global__ void __launch_bounds__(256, 2) normcol_kernel(const float* __restrict__ cx)
{
    const int row = blockIdx.x;   // b*CC + c
    const int yy = blockIdx.y;
    const int tid = threadIdx.x;
    __shared__ float red[8];

    if (yy < 2) {
        // sum the 32 sumsq partials (deterministic order in warp 0)
        if (tid < 32) {
            float s = g_nsq[yy][row][tid];
#pragma unroll
            for (int o = 16; o > 0; o >>= 1) s += __shfl_xor_sync(0xffffffffu, s, o);
            if (tid == 0) red[0] = s;
        }
        __syncthreads();
        const float scl = (yy == 0 ? SCALE_F : 1.0f) /
                          fmaxf(sqrtf(red[0]), 1e-12f);
        uint32_t* p = (uint32_t*)((yy == 0 ? g_qb : g_kb) + (size_t)row * NT);
#pragma unroll
        for (int it = 0; it < 8; ++it) {
            uint32_t u = p[tid + it * 256];
            float lo = __uint_as_float(u << 16) * scl;
            float hi = __uint_as_float(u & 0xffff0000u) * scl;
            p[tid + it * 256] = packbf(lo, hi);
        }
    } else {
        const float* p = cx + (size_t)row * NT;
        float s = 0.f;
#pragma unroll
        for (int it = 0; it < 4; ++it) {
            float4 v = ((const float4*)p)[tid + it * 256];
            s += v.x + v.y + v.z + v.w;
        }
#pragma unroll
        for (int o = 16; o > 0; o >>= 1) s += __shfl_xor_sync(0xffffffffu, s, o);
        if ((tid & 31) == 0) red[tid >> 5] = s;
        __syncthreads();
        if (tid == 0)
            g_colsum[row] = red[0] + red[1] + red[2] + red[3] +
                            red[4] + red[5] + red[6] + red[7];
    }
}

// ===== Stage B: G[F,e] = phi^T [v;1] — A fragments in registers (proven) =====
__global__ void __launch_bounds__(256, 3) stageB_kernel()
{
    extern __shared__ unsigned char sm[];
    unsigned char* Kt0 = sm;
    unsigned char* Kt1 = sm + 34 * TS;
    unsigned char* Vt0 = sm + 2 * 34 * TS;
    unsigned char* Vt1 = Vt0 + 40 * TS;

    const int tid = threadIdx.x, w = tid >> 5, lane = tid & 31;
    const int fb = blockIdx.x >> 4, js = blockIdx.x & 15;
    const int bh = blockIdx.y;
    const int cbase = (bh >> 2) * CC + (bh & 3) * DH;
    const __nv_bfloat16* kg = g_kb + (size_t)cbase * NT;
    const __nv_bfloat16* vg = g_vb + (size_t)cbase * NT;
    const int j0 = js * (NT / JSPLIT);

    const uint32_t ONE2 = packbf(1.f, 1.f);
    const int g = lane >> 2, tq = lane & 3;

    int aLo, bLo, aHi, bHi;
    fdec(fb * 128 + w * 16 + g, aLo, bLo);
    fdec(fb * 128 + w * 16 + g + 8, aHi, bHi);

    for (int i = tid; i < 2 * 64; i += 256) {
        unsigned char* Kb = (i >> 6) ? Kt1 : Kt0;
        unsigned char* Vb = (i >> 6) ? Vt1 : Vt0;
        const int c = i & 63;
        *(uint32_t*)(Kb + 32 * TS + c * 4) = ONE2;
        *(uint32_t*)(Kb + 33 * TS + c * 4) = 0u;
        *(uint32_t*)(Vb + 32 * TS + c * 4) = ONE2;
#pragma unroll
        for (int z = 33; z < 40; ++z) *(uint32_t*)(Vb + z * TS + c * 4) = 0u;
    }

    const uint32_t uK[2] = { smem_u32(Kt0), smem_u32(Kt1) };
    const uint32_t uV[2] = { smem_u32(Vt0), smem_u32(Vt1) };

    {
#pragma unroll
        for (int r = 0; r < 4; ++r) {
            const int idx = tid + r * 256;
            const int d = idx >> 5, pr = idx & 31;
            const int ch = pr & 15;
            if ((pr >> 4) == 0)
                cp16(uK[0] + d * TS + ch * 16, kg + (size_t)d * NT + j0 + ch * 8);
            else
                cp16(uV[0] + d * TS + ch * 16, vg + (size_t)d * NT + j0 + ch * 8);
        }
        asm volatile("cp.async.commit_group;" ::: "memory");
    }

    float acc[5][4];
#pragma unroll
    for (int nt = 0; nt < 5; ++nt)
        acc[nt][0] = acc[nt][1] = acc[nt][2] = acc[nt][3] = 0.f;

    const int lq = lane >> 3, lr = lane & 7;

    for (int t = 0; t < NT / JSPLIT / 128; ++t) {
        asm volatile("cp.async.wait_group 0;" ::: "memory");
        __syncthreads();

        if (t < NT / JSPLIT / 128 - 1) {
            const int nb = (t + 1) & 1;
            const int jn = j0 + (t + 1) * 128;
#pragma unroll
            for (int r = 0; r < 4; ++r) {
                const int idx = tid + r * 256;
                const int d = idx >> 5, pr = idx & 31;
                const int ch = pr & 15;
                if ((pr >> 4) == 0)
                    cp16(uK[nb] + d * TS + ch * 16, kg + (size_t)d * NT + jn + ch * 8);
                else
                    cp16(uV[nb] + d * TS + ch * 16, vg + (size_t)d * NT + jn + ch * 8);
            }
            asm volatile("cp.async.commit_group;" ::: "memory");
        }

        const unsigned char* Ks = (t & 1) ? Kt1 : Kt0;
        const unsigned char* rAlo = Ks + aLo * TS;
        const unsigned char* rBlo = Ks + bLo * TS;
        const unsigned char* rAhi = Ks + aHi * TS;
        const unsigned char* rBhi = Ks + bHi * TS;
        const uint32_t uVs = uV[t & 1];

#pragma unroll
        for (int ug = 0; ug < 4; ++ug) {
            uint32_t A0[4], A1[4];
            {
                const int cb0 = (ug * 32 + 2 * tq) * 2;
                A0[0] = bffma2(*(const uint32_t*)(rAlo + cb0),
                               *(const uint32_t*)(rBlo + cb0), 0u);
                A0[1] = bffma2(*(const uint32_t*)(rAhi + cb0),
                               *(const uint32_t*)(rBhi + cb0), 0u);
                A0[2] = bffma2(*(const uint32_t*)(rAlo + cb0 + 16),
                               *(const uint32_t*)(rBlo + cb0 + 16), 0u);
                A0[3] = bffma2(*(const uint32_t*)(rAhi + cb0 + 16),
                               *(const uint32_t*)(rBhi + cb0 + 16), 0u);
                const int cb1 = cb0 + 32;
                A1[0] = bffma2(*(const uint32_t*)(rAlo + cb1),
                               *(const uint32_t*)(rBlo + cb1), 0u);
                A1[1] = bffma2(*(const uint32_t*)(rAhi + cb1),
                               *(const uint32_t*)(rBhi + cb1), 0u);
                A1[2] = bffma2(*(const uint32_t*)(rAlo + cb1 + 16),
                               *(const uint32_t*)(rBlo + cb1 + 16), 0u);
                A1[3] = bffma2(*(const uint32_t*)(rAhi + cb1 + 16),
                               *(const uint32_t*)(rBhi + cb1 + 16), 0u);
            }
#pragma unroll
            for (int nt = 0; nt < 5; ++nt) {
                uint32_t b0, b1, b2, b3;
                ldsm4(b0, b1, b2, b3,
                      uVs + (nt * 8 + lr) * TS + (ug * 4 + lq) * 16);
                mma16816(acc[nt], A0[0], A0[1], A0[2], A0[3], b0, b1);
                mma16816(acc[nt], A1[0], A1[1], A1[2], A1[3], b2, b3);
            }
        }
    }

    const int fr0 = fb * 128 + w * 16 + g, fr1 = fr0 + 8;
    float* Gp = g_G2 + (size_t)(bh * JSPLIT + js) * NE * NF;
#pragma unroll
    for (int nt = 0; nt < 5; ++nt) {
        const int e0 = nt * 8 + 2 * tq;
        Gp[(size_t)e0 * NF + fr0]       = acc[nt][0];
        Gp[(size_t)(e0 + 1) * NF + fr0] = acc[nt][1];
        Gp[(size_t)e0 * NF + fr1]       = acc[nt][2];
        Gp[(size_t)(e0 + 1) * NF + fr1] = acc[nt][3];
    }
}

// reduce JSPLIT partials -> bf16 G (diag 1/2 weight applied here)
__global__ void __launch_bounds__(256, 4) greduce_kernel()
{
    const int o = (blockIdx.x * 256 + threadIdx.x) * 2;
    const int bh = o / (NE * NF);
    const int r = o - bh * (NE * NF);
    const int f = r % NF;
    const float* p = g_G2 + (size_t)bh * JSPLIT * NE * NF + r;
    float s0 = 0.f, s1 = 0.f;
#pragma unroll
    for (int js = 0; js < JSPLIT; ++js) {
        s0 += p[(size_t)js * NE * NF];
        s1 += p[(size_t)js * NE * NF + 1];
    }
    s0 *= fweight(f);
    s1 *= fweight(f + 1);
    *(uint32_t*)(g_Gb + o) = packbf(s0, s1);
}

// ===================== Stage C: Odev = Psi(q) G + epilogue (proven) ==========
__global__ void __launch_bounds__(256, 2)
stageC_kernel(const float* __restrict__ Wv, const float* __restrict__ bv)
{
    extern __shared__ unsigned char sm[];
    unsigned char* Qt  = sm;
    unsigned char* Psi = Qt + 34 * TS;
    unsigned char* Gs  = Psi + 128 * TS;
    uint32_t* lut      = (uint32_t*)(Gs + NE * GSS);
    float* svs         = (float*)(lut + NF);
    float* rd          = svs + 32;

    const int tid = threadIdx.x, w = tid >> 5, lane = tid & 31;
    const int i0 = blockIdx.x * 128;
    const int bh = blockIdx.y;
    const int b = bh >> 2, hh = bh & 3;
    const int cbase = b * CC + hh * DH;
    const __nv_bfloat16* qg = g_qb + (size_t)cbase * NT;

    const uint32_t ONE2 = packbf(1.f, 1.f);
    build_lut(lut, tid);
    for (int c = tid; c < 64; c += 256) {
        *(uint32_t*)(Qt + 32 * TS + c * 4) = ONE2;
        *(uint32_t*)(Qt + 33 * TS + c * 4) = 0u;
    }

    const uint32_t uQt = smem_u32(Qt), uPsi = smem_u32(Psi), uGs = smem_u32(Gs);

    {
#pragma unroll
        for (int r = 0; r < 2; ++r) {
            const int idx = tid + r * 256;
            const int d = idx >> 4, ch = idx & 15;
            cp16(uQt + d * TS + ch * 16, qg + (size_t)d * NT + i0 + ch * 8);
        }
        const __nv_bfloat16* Gp = g_Gb + (size_t)bh * NE * NF;
        for (int idx = tid; idx < NE * (NF / 8); idx += 256) {
            const int e = idx / (NF / 8), c = idx % (NF / 8);
            cp16(uGs + e * GSS + c * 16, Gp + (size_t)e * NF + c * 8);
        }
        asm volatile("cp.async.commit_group;" ::: "memory");
        asm volatile("cp.async.wait_group 0;" ::: "memory");
    }
    __syncthreads();

    float acc[5][4];
#pragma unroll
    for (int nt = 0; nt < 5; ++nt)
        acc[nt][0] = acc[nt][1] = acc[nt][2] = acc[nt][3] = 0.f;

    const int lq = lane >> 3, lr = lane & 7;

    for (int fbi = 0; fbi < NFB; ++fbi) {
        if (fbi > 0) __syncthreads();
        {
#pragma unroll
            for (int r = 0; r < 16; ++r) {
                const int row = w * 16 + r;
                const uint32_t e = lut[fbi * 128 + row];
                const int a = e & 0xff, b2 = (e >> 8) & 0xff;
                uint2 qa = *(const uint2*)(Qt + a * TS + lane * 8);
                uint2 qb = *(const uint2*)(Qt + b2 * TS + lane * 8);
                uint2 ps;
                ps.x = bffma2(qa.x, qb.x, 0u);
                ps.y = bffma2(qa.y, qb.y, 0u);
                *(uint2*)(Psi + row * TS + lane * 8) = ps;
            }
        }
        __syncthreads();

#pragma unroll
        for (int ug = 0; ug < 4; ++ug) {
            uint32_t A0[4], A1[4];
            ldsm4t(A0[0], A0[1], A0[2], A0[3],
                   uPsi + ((2 * ug) * 16 + ((lane >> 4) << 3) + (lane & 7)) * TS
                        + (w * 16 + ((lane >> 3) & 1) * 8) * 2);
            ldsm4t(A1[0], A1[1], A1[2], A1[3],
                   uPsi + ((2 * ug + 1) * 16 + ((lane >> 4) << 3) + (lane & 7)) * TS
                        + (w * 16 + ((lane >> 3) & 1) * 8) * 2);
#pragma unroll
            for (int nt = 0; nt < 5; ++nt) {
                uint32_t b0, b1, b2, b3;
                ldsm4(b0, b1, b2, b3,
                      uGs + (nt * 8 + lr) * GSS + fbi * 256 + (ug * 4 + lq) * 16);
                mma16816(acc[nt], A0[0], A0[1], A0[2], A0[3], b0, b1);
                mma16816(acc[nt], A1[0], A1[1], A1[2], A1[3], b2, b3);
            }
        }
    }

    {
#pragma unroll
        for (int mi = 0; mi < 4; ++mi) {
            const int d = w * 4 + mi;
            const int m = hh * DH + d;
            float s = 0.f;
#pragma unroll
            for (int c4 = 0; c4 < 4; ++c4)
                s += Wv[m * 128 + c4 * 32 + lane] * g_colsum[b * CC + c4 * 32 + lane];
#pragma unroll
            for (int o = 16; o > 0; o >>= 1) s += __shfl_xor_sync(0xffffffffu, s, o);
            if (lane == 0) svs[d] = s + (float)NT * bv[m];
        }
    }
    const int g = lane >> 2, tq = lane & 3;
    if (tq == 0) {
        rd[w * 16 + g]     = acc[4][0];
        rd[w * 16 + g + 8] = acc[4][2];
    }
    __syncthreads();

    const int r0 = w * 16 + g, r1 = r0 + 8;
    const float inv0 = 1.0f / (4096.0f + rd[r0]);
    const float inv1 = 1.0f / (4096.0f + rd[r1]);
    float* att = g_att + (size_t)cbase * NT;
#pragma unroll
    for (int nt = 0; nt < 4; ++nt) {
        const int e0 = nt * 8 + 2 * tq;
        const float s0 = svs[e0], s1 = svs[e0 + 1];
        att[(size_t)e0 * NT + i0 + r0]       = (acc[nt][0] + s0) * inv0;
        att[(size_t)(e0 + 1) * NT + i0 + r0] = (acc[nt][1] + s1) * inv0;
        att[(size_t)e0 * NT + i0 + r1]       = (acc[nt][2] + s0) * inv1;
        att[(size_t)(e0 + 1) * NT + i0 + r1] = (acc[nt][3] + s1) * inv1;
    }
}

// ================================== launch ===================================
extern "C" void kernel_launch(void* const* d_in, const int* in_sizes, int n_in,
                              void* d_out, int out_size)
{
    (void)in_sizes; (void)n_in; (void)out_size;
    const float* x  = (const float*)d_in[0];
    const float* cx = (const float*)d_in[1];
    const float* Wq = (const float*)d_in[2];
    const float* bq = (const float*)d_in[3];
    const float* Wk = (const float*)d_in[4];
    const float* bk = (const float*)d_in[5];
    const float* Wv = (const float*)d_in[6];
    const float* bv = (const float*)d_in[7];
    const float* Wo = (const float*)d_in[8];
    const float* bo = (const float*)d_in[9];
    float* out = (float*)d_out;

    const int QKV_SMEM = 2 * 128 * PW_STRIDE;
    const int OUT_SMEM = 2 * 128 * PW_STRIDE + 2 * 128 * PB64_STRIDE;
    const int SB_SMEM  = 2 * 34 * TS + 2 * 40 * TS;
    const int SC_SMEM  = 34 * TS + 128 * TS + NE * GSS + NF * 4 + 160 * 4;

    cudaFuncSetAttribute(proj_qkv_mma, cudaFuncAttributeMaxDynamicSharedMemorySize, QKV_SMEM);
    cudaFuncSetAttribute(proj_out_mma, cudaFuncAttributeMaxDynamicSharedMemorySize, OUT_SMEM);
    cudaFuncSetAttribute(stageB_kernel, cudaFuncAttributeMaxDynamicSharedMemorySize, SB_SMEM);
    cudaFuncSetAttribute(stageC_kernel, cudaFuncAttributeMaxDynamicSharedMemorySize, SC_SMEM);

    proj_qkv_mma<<<dim3(NT / 128, BB, 3), 256, QKV_SMEM>>>(x, cx, Wq, bq, Wk, bk, Wv, bv);
    normcol_kernel<<<dim3(BB * CC, 3), 256>>>(cx);
    stageB_kernel<<<dim3(NFB * JSPLIT, BB * NH), 256, SB_SMEM>>>();
    greduce_kernel<<<dim3(8 * NE * NF / 512), 256>>>();
    stageC_kernel<<<dim3(NT / 128, BB * NH), 256, SC_SMEM>>>(Wv, bv);
    proj_out_mma<<<dim3(NT / 64, BB), 256, OUT_SMEM>>>(Wo, bo, out);
}